// round 5
// baseline (speedup 1.0000x reference)
#include <cuda_runtime.h>
#include <cuda_bf16.h>
#include <cstdint>

#define BATCH 16
#define TSEQ 512
#define NH 16
#define DK 64
#define DM 1024
#define D3 3072
#define RR 1023  // 2T-1

// ---------------------------------------------------------------------------
// Scratch (allocation-free: device globals)
// ---------------------------------------------------------------------------
__device__ float g_Q[BATCH*NH*TSEQ*DK];
__device__ float g_K[BATCH*NH*TSEQ*DK];
__device__ float g_V[BATCH*NH*TSEQ*DK];
__device__ float g_P[NH*RR*DK];

// bf16 hi/lo split operands for projection GEMMs
__device__ __nv_bfloat16 g_Ah[BATCH*TSEQ*DM];
__device__ __nv_bfloat16 g_Al[BATCH*TSEQ*DM];
__device__ __nv_bfloat16 g_Wh[D3*DM];      // qvk_w transposed: [3072][1024]
__device__ __nv_bfloat16 g_Wl[D3*DM];
__device__ __nv_bfloat16 g_pAh[1024*DM];   // pos padded to 1024 rows
__device__ __nv_bfloat16 g_pAl[1024*DM];
__device__ __nv_bfloat16 g_pWh[DM*DM];     // pos_w transposed
__device__ __nv_bfloat16 g_pWl[DM*DM];

// ---------------------------------------------------------------------------
// helpers
// ---------------------------------------------------------------------------
__device__ __forceinline__ uint32_t smem_u32(const void* p) {
  uint32_t a;
  asm("{ .reg .u64 t; cvta.to.shared.u64 t, %1; cvt.u32.u64 %0, t; }" : "=r"(a) : "l"(p));
  return a;
}
__device__ __forceinline__ void cp16(uint32_t dst, const void* src) {
  asm volatile("cp.async.cg.shared.global [%0], [%1], 16;" :: "r"(dst), "l"(src));
}
__device__ __forceinline__ void cp_commit() {
  asm volatile("cp.async.commit_group;" ::: "memory");
}
__device__ __forceinline__ void ldm4(uint32_t& r0, uint32_t& r1, uint32_t& r2,
                                     uint32_t& r3, uint32_t a) {
  asm volatile("ldmatrix.sync.aligned.m8n8.x4.shared.b16 {%0,%1,%2,%3}, [%4];"
               : "=r"(r0), "=r"(r1), "=r"(r2), "=r"(r3) : "r"(a));
}
__device__ __forceinline__ void mma_bf16(float* c, const uint32_t* a,
                                         uint32_t b0, uint32_t b1) {
  asm volatile(
      "mma.sync.aligned.m16n8k16.row.col.f32.bf16.bf16.f32 "
      "{%0,%1,%2,%3}, {%4,%5,%6,%7}, {%8,%9}, {%0,%1,%2,%3};"
      : "+f"(c[0]), "+f"(c[1]), "+f"(c[2]), "+f"(c[3])
      : "r"(a[0]), "r"(a[1]), "r"(a[2]), "r"(a[3]), "r"(b0), "r"(b1));
}
__device__ __forceinline__ uint32_t pack_bf2(float a, float b) {
  __nv_bfloat16 ha = __float2bfloat16(a), hb = __float2bfloat16(b);
  uint16_t ua = *(uint16_t*)&ha, ub = *(uint16_t*)&hb;
  return (uint32_t)ua | ((uint32_t)ub << 16);
}
__device__ __forceinline__ float bf_res(float v) {
  return v - __bfloat162float(__float2bfloat16(v));
}

// ---------------------------------------------------------------------------
// Split conversion: f32 -> bf16 hi/lo.  DST 0: x, DST 1: pos (zero-padded)
// ---------------------------------------------------------------------------
template<int DST>
__global__ void __launch_bounds__(256) split_kernel(const float* __restrict__ in,
                                                    int n, int n_total) {
  __nv_bfloat16* hi = (DST == 0) ? g_Ah : g_pAh;
  __nv_bfloat16* lo = (DST == 0) ? g_Al : g_pAl;
  for (int i = blockIdx.x * 256 + threadIdx.x; i < n_total; i += gridDim.x * 256) {
    float v = (i < n) ? in[i] : 0.f;
    __nv_bfloat16 h = __float2bfloat16(v);
    hi[i] = h;
    lo[i] = __float2bfloat16(v - __bfloat162float(h));
  }
}

// Transpose + split: in[R][C] f32 -> out[C][R] bf16 hi/lo. DST 0: qvk_w, 1: pos_w
template<int DST>
__global__ void __launch_bounds__(256) tsplit_kernel(const float* __restrict__ in,
                                                     int R, int C) {
  __nv_bfloat16* hi = (DST == 0) ? g_Wh : g_pWh;
  __nv_bfloat16* lo = (DST == 0) ? g_Wl : g_pWl;
  __shared__ float t[32][33];
  const int c0 = blockIdx.x * 32, r0 = blockIdx.y * 32;
  const int tx = threadIdx.x & 31, ty = threadIdx.x >> 5;  // 32x8
#pragma unroll
  for (int i = 0; i < 4; i++)
    t[ty + i * 8][tx] = in[(size_t)(r0 + ty + i * 8) * C + c0 + tx];
  __syncthreads();
#pragma unroll
  for (int i = 0; i < 4; i++) {
    float v = t[tx][ty + i * 8];
    __nv_bfloat16 h = __float2bfloat16(v);
    size_t o = (size_t)(c0 + ty + i * 8) * R + r0 + tx;
    hi[o] = h;
    lo[o] = __float2bfloat16(v - __bfloat162float(h));
  }
}

// ---------------------------------------------------------------------------
// mma.sync bf16 GEMM:  C[M,N] = A[M,1024] @ B^T  (B stored [N][1024], K-major)
// 3-pass split: hi*hi + hi*lo + lo*hi, fp32 accum.
// CTA tile 128x128, K-chunk 64, cp.async double buffer, SW128 smem swizzle.
// MODE 0: QKV scatter (+bias) -> g_Q/g_K/g_V. MODE 1: pos -> g_P.
// ---------------------------------------------------------------------------
#define PBUF 65536
#define OFF_AH 0
#define OFF_AL 16384
#define OFF_BH 32768
#define OFF_BL 49152
#define GSMEM (2 * PBUF)  // 131072

template<int MODE>
__global__ void __launch_bounds__(256, 1) mma_gemm(const float* __restrict__ bias) {
  extern __shared__ char smem[];
  const uint32_t sb = smem_u32(smem);
  const int tid = threadIdx.x;
  const int wid = tid >> 5, lane = tid & 31;
  const int n0 = blockIdx.x * 128;
  const int m0 = blockIdx.y * 128;
  const int wm = wid & 3;   // m warp (0-3): 32 rows each
  const int wn = wid >> 2;  // n warp (0-1): 64 cols each

  const __nv_bfloat16* Ah = (MODE == 0) ? g_Ah : g_pAh;
  const __nv_bfloat16* Al = (MODE == 0) ? g_Al : g_pAl;
  const __nv_bfloat16* Bh = (MODE == 0) ? g_Wh : g_pWh;
  const __nv_bfloat16* Bl = (MODE == 0) ? g_Wl : g_pWl;

  const int gr = tid >> 3;         // row block
  const int gc = tid & 7;          // 16B column
  const uint32_t gsw = (uint32_t)((gc * 16) ^ ((gr & 7) << 4));

  const int l7 = lane & 7;
  const uint32_t xa = (uint32_t)(l7 << 4);
  const int rowA0 = wm * 32 + l7 + (((lane >> 3) & 1) << 3);
  const uint32_t kadd_a = (uint32_t)(((lane >> 4) & 1) << 4);
  const int rowB0 = wn * 64 + l7 + (((lane >> 4) & 1) << 3);
  const uint32_t kadd_b = (uint32_t)(((lane >> 3) & 1) << 4);

  float acc[2][8][4];
#pragma unroll
  for (int mt = 0; mt < 2; mt++)
#pragma unroll
    for (int nt = 0; nt < 8; nt++)
#pragma unroll
      for (int i = 0; i < 4; i++) acc[mt][nt][i] = 0.f;

  auto load_chunk = [&](int kc, int buf) {
    const int k0 = kc * 64;
    const uint32_t base = sb + buf * PBUF;
#pragma unroll
    for (int it = 0; it < 4; it++) {
      const int r = gr + it * 32;
      const uint32_t sw = (uint32_t)(r * 128) + gsw;
      const size_t asrc = (size_t)(m0 + r) * DM + k0 + gc * 8;
      const size_t bsrc = (size_t)(n0 + r) * DM + k0 + gc * 8;
      cp16(base + OFF_AH + sw, Ah + asrc);
      cp16(base + OFF_AL + sw, Al + asrc);
      cp16(base + OFF_BH + sw, Bh + bsrc);
      cp16(base + OFF_BL + sw, Bl + bsrc);
    }
    cp_commit();
  };

  load_chunk(0, 0);

  for (int kc = 0; kc < 16; kc++) {
    if (kc + 1 < 16) {
      load_chunk(kc + 1, (kc + 1) & 1);
      asm volatile("cp.async.wait_group 1;" ::: "memory");
    } else {
      asm volatile("cp.async.wait_group 0;" ::: "memory");
    }
    __syncthreads();

    const uint32_t bb = sb + (kc & 1) * PBUF;
#pragma unroll
    for (int ks = 0; ks < 4; ks++) {
      const uint32_t kba = (uint32_t)(ks * 32);
      uint32_t ah[2][4], al[2][4];
#pragma unroll
      for (int mt = 0; mt < 2; mt++) {
        const uint32_t aoff = (uint32_t)((rowA0 + mt * 16) * 128) + ((kba + kadd_a) ^ xa);
        ldm4(ah[mt][0], ah[mt][1], ah[mt][2], ah[mt][3], bb + OFF_AH + aoff);
        ldm4(al[mt][0], al[mt][1], al[mt][2], al[mt][3], bb + OFF_AL + aoff);
      }
#pragma unroll
      for (int np = 0; np < 4; np++) {
        const uint32_t boff = (uint32_t)((rowB0 + np * 16) * 128) + ((kba + kadd_b) ^ xa);
        uint32_t bh[4], bl[4];
        ldm4(bh[0], bh[1], bh[2], bh[3], bb + OFF_BH + boff);
        ldm4(bl[0], bl[1], bl[2], bl[3], bb + OFF_BL + boff);
#pragma unroll
        for (int mt = 0; mt < 2; mt++) {
          mma_bf16(acc[mt][2 * np + 0], ah[mt], bh[0], bh[1]);
          mma_bf16(acc[mt][2 * np + 1], ah[mt], bh[2], bh[3]);
          mma_bf16(acc[mt][2 * np + 0], ah[mt], bl[0], bl[1]);
          mma_bf16(acc[mt][2 * np + 1], ah[mt], bl[2], bl[3]);
          mma_bf16(acc[mt][2 * np + 0], al[mt], bh[0], bh[1]);
          mma_bf16(acc[mt][2 * np + 1], al[mt], bh[2], bh[3]);
        }
      }
    }
    __syncthreads();
  }

  const int mrow = m0 + wm * 32 + (lane >> 2);
#pragma unroll
  for (int mt = 0; mt < 2; mt++) {
#pragma unroll
    for (int half = 0; half < 2; half++) {
      const int m = mrow + mt * 16 + half * 8;
#pragma unroll
      for (int nt = 0; nt < 8; nt++) {
        const int n = n0 + wn * 64 + nt * 8 + (lane & 3) * 2;
        float2 o;
        o.x = acc[mt][nt][half * 2 + 0];
        o.y = acc[mt][nt][half * 2 + 1];
        if (MODE == 0) {
          o.x += bias[n];
          o.y += bias[n + 1];
          const int b = m >> 9, t = m & 511;
          const int sec = n >> 10;
          const int h = (n >> 6) & 15;
          const int d = n & 63;
          float* dst = (sec == 0 ? g_Q : sec == 1 ? g_K : g_V)
                       + (((size_t)(b * NH + h) * TSEQ + t) * DK + d);
          *(float2*)dst = o;
        } else {
          if (m < RR) {
            const int h = n >> 6;
            const int d = n & 63;
            *(float2*)(g_P + ((size_t)h * RR + m) * DK + d) = o;
          }
        }
      }
    }
  }
}

// ---------------------------------------------------------------------------
// Scores on tensor cores: per CTA (t-tile 64, s-tile 128, bh):
//   AC = QU @ K^T        (64 x 128)
//   BD = QV @ Pband^T    (64 x 192), Pband row jb -> P[s0-t0+448+jb]
//   out[t][s] = (AC[t][s] + BD[t][s-t+63]) / 8
// ---------------------------------------------------------------------------
#define S_QUH 0
#define S_QUL 8192
#define S_QVH 16384
#define S_QVL 24576
#define S_KH  32768
#define S_KL  49152
#define S_PH  65536
#define S_PL  90112
#define S_BD  114688            // 64 x 196 fp32
#define S_SMEM (114688 + 64*196*4)  // 164864

__global__ void __launch_bounds__(256, 1) scores_mma(
    const float* __restrict__ pu, const float* __restrict__ pv,
    float* __restrict__ wout) {
  extern __shared__ char smem[];
  const uint32_t sb = smem_u32(smem);
  float* BDs = (float*)(smem + S_BD);
  const int tid = threadIdx.x;
  const int wid = tid >> 5, lane = tid & 31;
  const int s0 = blockIdx.x * 128;
  const int t0 = blockIdx.y * 64;
  const int bh = blockIdx.z, h = bh & 15;

  const int frow = tid >> 4;
  const int c4 = (tid & 15) * 4;
  const uint32_t cb = (uint32_t)(c4 * 2);
  const float4 pu4 = *(const float4*)(pu + h * 64 + c4);
  const float4 pv4 = *(const float4*)(pv + h * 64 + c4);
  const float* qb = g_Q + ((size_t)bh * TSEQ + t0) * DK;
  const float* kb = g_K + ((size_t)bh * TSEQ + s0) * DK;
  const float* Pb = g_P + (size_t)h * RR * DK;
  const int relbase = s0 - t0 + 448;

#pragma unroll
  for (int it = 0; it < 4; it++) {
    const int row = frow + it * 16;
    const float4 q = *(const float4*)(qb + (size_t)row * DK + c4);
    const uint32_t sw = (uint32_t)(row * 128) + (cb ^ ((uint32_t)(row & 7) << 4));
    float ux = q.x + pu4.x, uy = q.y + pu4.y, uz = q.z + pu4.z, uw = q.w + pu4.w;
    float vx = q.x + pv4.x, vy = q.y + pv4.y, vz = q.z + pv4.z, vw = q.w + pv4.w;
    uint2 hh, ll;
    hh.x = pack_bf2(ux, uy); hh.y = pack_bf2(uz, uw);
    ll.x = pack_bf2(bf_res(ux), bf_res(uy));
    ll.y = pack_bf2(bf_res(uz), bf_res(uw));
    *(uint2*)(smem + S_QUH + sw) = hh;
    *(uint2*)(smem + S_QUL + sw) = ll;
    hh.x = pack_bf2(vx, vy); hh.y = pack_bf2(vz, vw);
    ll.x = pack_bf2(bf_res(vx), bf_res(vy));
    ll.y = pack_bf2(bf_res(vz), bf_res(vw));
    *(uint2*)(smem + S_QVH + sw) = hh;
    *(uint2*)(smem + S_QVL + sw) = ll;
  }
#pragma unroll
  for (int it = 0; it < 8; it++) {
    const int row = frow + it * 16;
    const float4 k = *(const float4*)(kb + (size_t)row * DK + c4);
    const uint32_t sw = (uint32_t)(row * 128) + (cb ^ ((uint32_t)(row & 7) << 4));
    uint2 hh, ll;
    hh.x = pack_bf2(k.x, k.y); hh.y = pack_bf2(k.z, k.w);
    ll.x = pack_bf2(bf_res(k.x), bf_res(k.y));
    ll.y = pack_bf2(bf_res(k.z), bf_res(k.w));
    *(uint2*)(smem + S_KH + sw) = hh;
    *(uint2*)(smem + S_KL + sw) = ll;
  }
#pragma unroll
  for (int it = 0; it < 12; it++) {
    const int row = frow + it * 16;
    const int r = relbase + row;
    float4 p = make_float4(0.f, 0.f, 0.f, 0.f);
    if (r >= 0 && r < RR) p = *(const float4*)(Pb + (size_t)r * DK + c4);
    const uint32_t sw = (uint32_t)(row * 128) + (cb ^ ((uint32_t)(row & 7) << 4));
    uint2 hh, ll;
    hh.x = pack_bf2(p.x, p.y); hh.y = pack_bf2(p.z, p.w);
    ll.x = pack_bf2(bf_res(p.x), bf_res(p.y));
    ll.y = pack_bf2(bf_res(p.z), bf_res(p.w));
    *(uint2*)(smem + S_PH + sw) = hh;
    *(uint2*)(smem + S_PL + sw) = ll;
  }
  __syncthreads();

  const int wm = wid & 3;
  const int wn = wid >> 2;
  const int l7 = lane & 7;
  const uint32_t xa = (uint32_t)(l7 << 4);
  const int rowA = wm * 16 + l7 + (((lane >> 3) & 1) << 3);
  const uint32_t kadd_a = (uint32_t)(((lane >> 4) & 1) << 4);
  const int rbB = l7 + (((lane >> 4) & 1) << 3);
  const uint32_t kadd_b = (uint32_t)(((lane >> 3) & 1) << 4);

  float ac[8][4], bd[12][4];
#pragma unroll
  for (int nt = 0; nt < 8; nt++)
#pragma unroll
    for (int i = 0; i < 4; i++) ac[nt][i] = 0.f;
#pragma unroll
  for (int nt = 0; nt < 12; nt++)
#pragma unroll
    for (int i = 0; i < 4; i++) bd[nt][i] = 0.f;

#pragma unroll
  for (int ks = 0; ks < 4; ks++) {
    const uint32_t kba = (uint32_t)(ks * 32);
    const uint32_t aoff = (uint32_t)(rowA * 128) + ((kba + kadd_a) ^ xa);
    uint32_t quh[4], qul[4], qvh[4], qvl[4];
    ldm4(quh[0], quh[1], quh[2], quh[3], sb + S_QUH + aoff);
    ldm4(qul[0], qul[1], qul[2], qul[3], sb + S_QUL + aoff);
    ldm4(qvh[0], qvh[1], qvh[2], qvh[3], sb + S_QVH + aoff);
    ldm4(qvl[0], qvl[1], qvl[2], qvl[3], sb + S_QVL + aoff);
#pragma unroll
    for (int np = 0; np < 4; np++) {
      const int rowB = wn * 64 + np * 16 + rbB;
      const uint32_t boff = (uint32_t)(rowB * 128) + ((kba + kadd_b) ^ xa);
      uint32_t kh[4], kl[4];
      ldm4(kh[0], kh[1], kh[2], kh[3], sb + S_KH + boff);
      ldm4(kl[0], kl[1], kl[2], kl[3], sb + S_KL + boff);
      mma_bf16(ac[2 * np + 0], quh, kh[0], kh[1]);
      mma_bf16(ac[2 * np + 1], quh, kh[2], kh[3]);
      mma_bf16(ac[2 * np + 0], quh, kl[0], kl[1]);
      mma_bf16(ac[2 * np + 1], quh, kl[2], kl[3]);
      mma_bf16(ac[2 * np + 0], qul, kh[0], kh[1]);
      mma_bf16(ac[2 * np + 1], qul, kh[2], kh[3]);
    }
#pragma unroll
    for (int np = 0; np < 6; np++) {
      const int rowB = wn * 96 + np * 16 + rbB;
      const uint32_t boff = (uint32_t)(rowB * 128) + ((kba + kadd_b) ^ xa);
      uint32_t ph[4], pl[4];
      ldm4(ph[0], ph[1], ph[2], ph[3], sb + S_PH + boff);
      ldm4(pl[0], pl[1], pl[2], pl[3], sb + S_PL + boff);
      mma_bf16(bd[2 * np + 0], qvh, ph[0], ph[1]);
      mma_bf16(bd[2 * np + 1], qvh, ph[2], ph[3]);
      mma_bf16(bd[2 * np + 0], qvh, pl[0], pl[1]);
      mma_bf16(bd[2 * np + 1], qvh, pl[2], pl[3]);
      mma_bf16(bd[2 * np + 0], qvl, ph[0], ph[1]);
      mma_bf16(bd[2 * np + 1], qvl, ph[2], ph[3]);
    }
  }

  const int r0w = wm * 16 + (lane >> 2);
#pragma unroll
  for (int nt = 0; nt < 12; nt++) {
    const int col = wn * 96 + nt * 8 + (lane & 3) * 2;
    *(float2*)&BDs[r0w * 196 + col] = make_float2(bd[nt][0], bd[nt][1]);
    *(float2*)&BDs[(r0w + 8) * 196 + col] = make_float2(bd[nt][2], bd[nt][3]);
  }
  __syncthreads();

  float* wbase = wout + ((size_t)bh * TSEQ + t0) * TSEQ + s0;
#pragma unroll
  for (int nt = 0; nt < 8; nt++) {
    const int col = wn * 64 + nt * 8 + (lane & 3) * 2;
#pragma unroll
    for (int half = 0; half < 2; half++) {
      const int row = r0w + half * 8;
      const int bdi = row * 196 + col - row + 63;
      float2 o;
      o.x = (ac[nt][half * 2 + 0] + BDs[bdi]) * 0.125f;
      o.y = (ac[nt][half * 2 + 1] + BDs[bdi + 1]) * 0.125f;
      *(float2*)(wbase + (size_t)row * TSEQ + col) = o;
    }
  }
}

// ---------------------------------------------------------------------------
// Fused softmax + context (tensor cores):
// per CTA (t-tile 64, bh): load raw scores 64x512 -> smem, softmax rows,
// write normalized weights (output) and compute ctx = W @ V via bf16x3 mma.
// ---------------------------------------------------------------------------
#define CX_RAW 0
#define CX_WH  131072
#define CX_WL  139264
#define CX_VH  147456
#define CX_VL  155648
#define CX_SMEM 163840

__global__ void __launch_bounds__(256, 1) smctx_kernel(
    float* __restrict__ wts, float* __restrict__ ctx) {
  extern __shared__ char smem[];
  float* RAW = (float*)smem;
  const uint32_t sb = smem_u32(smem);
  const int tid = threadIdx.x;
  const int wid = tid >> 5, lane = tid & 31;
  const int t0 = blockIdx.x * 64;
  const int bh = blockIdx.y;
  const int b = bh >> 4, h = bh & 15;
  float* wbase = wts + ((size_t)bh * TSEQ + t0) * TSEQ;
  const float* vbase = g_V + (size_t)bh * TSEQ * DK;

  // Phase A: load raw scores 64x512 into smem
  for (int i = tid; i < 64 * 128; i += 256) {
    const int r = i >> 7, c4 = (i & 127) * 4;
    *(float4*)&RAW[r * 512 + c4] = *(const float4*)(wbase + (size_t)r * TSEQ + c4);
  }
  __syncthreads();

  // Phase B: softmax per row in smem
  for (int r = wid; r < 64; r += 8) {
    float* row = &RAW[r * 512];
    float vals[16];
    float m = -1e30f;
#pragma unroll
    for (int k = 0; k < 16; k++) {
      vals[k] = row[lane + 32 * k];
      m = fmaxf(m, vals[k]);
    }
#pragma unroll
    for (int off = 16; off > 0; off >>= 1)
      m = fmaxf(m, __shfl_xor_sync(0xffffffffu, m, off));
    float s = 0.f;
#pragma unroll
    for (int k = 0; k < 16; k++) { vals[k] = __expf(vals[k] - m); s += vals[k]; }
#pragma unroll
    for (int off = 16; off > 0; off >>= 1)
      s += __shfl_xor_sync(0xffffffffu, s, off);
    const float inv = 1.0f / s;
#pragma unroll
    for (int k = 0; k < 16; k++) row[lane + 32 * k] = vals[k] * inv;
  }
  __syncthreads();

  // write normalized weights to global (output)
  for (int i = tid; i < 64 * 128; i += 256) {
    const int r = i >> 7, c4 = (i & 127) * 4;
    *(float4*)(wbase + (size_t)r * TSEQ + c4) = *(float4*)&RAW[r * 512 + c4];
  }

  // Phase C: ctx = W @ V, s chunks of 64, bf16 hi/lo 3-pass
  const int l7 = lane & 7;
  const uint32_t xa = (uint32_t)(l7 << 4);
  const int wm = wid & 3, wn = wid >> 2;
  const int rowA0 = wm * 16 + l7 + (((lane >> 3) & 1) << 3);
  const uint32_t kadd_a = (uint32_t)(((lane >> 4) & 1) << 4);
  const int rowB0 = wn * 32 + l7 + (((lane >> 4) & 1) << 3);
  const uint32_t kadd_b = (uint32_t)(((lane >> 3) & 1) << 4);

  float acc[4][4];
#pragma unroll
  for (int nt = 0; nt < 4; nt++)
#pragma unroll
    for (int i = 0; i < 4; i++) acc[nt][i] = 0.f;

  for (int sc = 0; sc < 8; sc++) {
    const int s0 = sc * 64;
    __syncthreads();
    // convert weights tile (64 t x 64 s)
    for (int i = tid; i < 1024; i += 256) {
      const int r = i >> 4, q = i & 15;
      const float4 wv = *(float4*)&RAW[r * 512 + s0 + q * 4];
      const uint32_t sw = (uint32_t)(r * 128) + ((uint32_t)(q * 8) ^ ((uint32_t)(r & 7) << 4));
      uint2 hh, ll;
      hh.x = pack_bf2(wv.x, wv.y); hh.y = pack_bf2(wv.z, wv.w);
      ll.x = pack_bf2(bf_res(wv.x), bf_res(wv.y));
      ll.y = pack_bf2(bf_res(wv.z), bf_res(wv.w));
      *(uint2*)(smem + CX_WH + sw) = hh;
      *(uint2*)(smem + CX_WL + sw) = ll;
    }
    // load + convert V^T tile (64 d x 64 s); coalesced global reads over d
    for (int i = tid; i < 1024; i += 256) {
      const int d = i & 63, q = i >> 6;  // q: s-quad 0..15
      const int ss = s0 + q * 4;
      const float v0 = vbase[(size_t)(ss + 0) * DK + d];
      const float v1 = vbase[(size_t)(ss + 1) * DK + d];
      const float v2 = vbase[(size_t)(ss + 2) * DK + d];
      const float v3 = vbase[(size_t)(ss + 3) * DK + d];
      const uint32_t sw = (uint32_t)(d * 128) + ((uint32_t)(q * 8) ^ ((uint32_t)(d & 7) << 4));
      uint2 hh, ll;
      hh.x = pack_bf2(v0, v1); hh.y = pack_bf2(v2, v3);
      ll.x = pack_bf2(bf_res(v0), bf_res(v1));
      ll.y = pack_bf2(bf_res(v2), bf_res(v3));
      *(uint2*)(smem + CX_VH + sw) = hh;
      *(uint2*)(smem + CX_VL + sw) = ll;
    }
    __syncthreads();
#pragma unroll
    for (int ks = 0; ks < 4; ks++) {
      const uint32_t kba = (uint32_t)(ks * 32);
      const uint32_t aoff = (uint32_t)(rowA0 * 128) + ((kba + kadd_a) ^ xa);
      uint32_t ah[4], al[4];
      ldm4(ah[0], ah[1], ah[2], ah[3], sb + CX_WH + aoff);
      ldm4(al[0], al[1], al[2], al[3], sb + CX_WL + aoff);
#pragma unroll
      for (int np = 0; np < 2; np++) {
        const uint32_t boff = (uint32_t)((rowB0 + np * 16) * 128) + ((kba + kadd_b) ^ xa);
        uint32_t vh[4], vl[4];
        ldm4(vh[0], vh[1], vh[2], vh[3], sb + CX_VH + boff);
        ldm4(vl[0], vl[1], vl[2], vl[3], sb + CX_VL + boff);
        mma_bf16(acc[2 * np + 0], ah, vh[0], vh[1]);
        mma_bf16(acc[2 * np + 1], ah, vh[2], vh[3]);
        mma_bf16(acc[2 * np + 0], ah, vl[0], vl[1]);
        mma_bf16(acc[2 * np + 1], ah, vl[2], vl[3]);
        mma_bf16(acc[2 * np + 0], al, vh[0], vh[1]);
        mma_bf16(acc[2 * np + 1], al, vh[2], vh[3]);
      }
    }
  }

  // epilogue
  const int r0w = wm * 16 + (lane >> 2);
#pragma unroll
  for (int nt = 0; nt < 4; nt++) {
    const int col = wn * 32 + nt * 8 + (lane & 3) * 2;
#pragma unroll
    for (int half = 0; half < 2; half++) {
      const int t = t0 + r0w + half * 8;
      float2 o;
      o.x = acc[nt][half * 2 + 0];
      o.y = acc[nt][half * 2 + 1];
      *(float2*)(ctx + ((size_t)b * TSEQ + t) * DM + h * DK + col) = o;
    }
  }
}

// ---------------------------------------------------------------------------
// Launch
// inputs: 0=x 1=mask 2=pos 3=qvk_w 4=qvk_b 5=pos_w 6=posu 7=posv
// output: [context (16*512*1024) | weights (16*16*512*512)] float32
// ---------------------------------------------------------------------------
extern "C" void kernel_launch(void* const* d_in, const int* in_sizes, int n_in,
                              void* d_out, int out_size) {
  const float* x     = (const float*)d_in[0];
  const float* pos   = (const float*)d_in[2];
  const float* qvk_w = (const float*)d_in[3];
  const float* qvk_b = (const float*)d_in[4];
  const float* pos_w = (const float*)d_in[5];
  const float* posu  = (const float*)d_in[6];
  const float* posv  = (const float*)d_in[7];

  float* ctx = (float*)d_out;
  float* wts = (float*)d_out + (size_t)BATCH * TSEQ * DM;

  // 0) bf16 hi/lo splits (+ transposed weights)
  split_kernel<0><<<1024, 256>>>(x, BATCH * TSEQ * DM, BATCH * TSEQ * DM);
  tsplit_kernel<0><<<dim3(D3 / 32, DM / 32), 256>>>(qvk_w, DM, D3);
  split_kernel<1><<<512, 256>>>(pos, RR * DM, 1024 * DM);
  tsplit_kernel<1><<<dim3(DM / 32, DM / 32), 256>>>(pos_w, DM, DM);

  // 1) QKV projection (8192 x 1024) @ (1024 x 3072) on mma.sync bf16x3
  cudaFuncSetAttribute(mma_gemm<0>, cudaFuncAttributeMaxDynamicSharedMemorySize,
                       GSMEM);
  cudaFuncSetAttribute(mma_gemm<1>, cudaFuncAttributeMaxDynamicSharedMemorySize,
                       GSMEM);
  mma_gemm<0><<<dim3(D3 / 128, (BATCH * TSEQ) / 128), 256, GSMEM>>>(qvk_b);

  // 2) pos projection: (1024(pad) x 1024) @ (1024 x 1024)
  mma_gemm<1><<<dim3(DM / 128, 1024 / 128), 256, GSMEM>>>(nullptr);

  // 3) scores on tensor cores (AC + shifted BD, scaled) -> weights region
  cudaFuncSetAttribute(scores_mma, cudaFuncAttributeMaxDynamicSharedMemorySize,
                       S_SMEM);
  scores_mma<<<dim3(TSEQ / 128, TSEQ / 64, BATCH * NH), 256, S_SMEM>>>(
      posu, posv, wts);

  // 4+5) fused softmax + context on tensor cores
  cudaFuncSetAttribute(smctx_kernel, cudaFuncAttributeMaxDynamicSharedMemorySize,
                       CX_SMEM);
  smctx_kernel<<<dim3(TSEQ / 64, BATCH * NH), 256, CX_SMEM>>>(wts, ctx);
}

// round 6
// speedup vs baseline: 1.3127x; 1.3127x over previous
#include <cuda_runtime.h>
#include <cuda_bf16.h>
#include <cstdint>

#define BATCH 16
#define TSEQ 512
#define NH 16
#define DK 64
#define DM 1024
#define D3 3072
#define RR 1023  // 2T-1

// ---------------------------------------------------------------------------
// Scratch (allocation-free: device globals)
// ---------------------------------------------------------------------------
__device__ float g_Q[BATCH*NH*TSEQ*DK];
__device__ float g_K[BATCH*NH*TSEQ*DK];
__device__ float g_V[BATCH*NH*TSEQ*DK];
__device__ float g_P[NH*RR*DK];

// bf16 hi/lo split operands for projection GEMMs
__device__ __nv_bfloat16 g_Ah[BATCH*TSEQ*DM];
__device__ __nv_bfloat16 g_Al[BATCH*TSEQ*DM];
__device__ __nv_bfloat16 g_Wh[D3*DM];      // qvk_w transposed: [3072][1024]
__device__ __nv_bfloat16 g_Wl[D3*DM];
__device__ __nv_bfloat16 g_pAh[1024*DM];   // pos padded to 1024 rows
__device__ __nv_bfloat16 g_pAl[1024*DM];
__device__ __nv_bfloat16 g_pWh[DM*DM];     // pos_w transposed
__device__ __nv_bfloat16 g_pWl[DM*DM];

// bf16 hi/lo normalized weights [bh][t][s] and V^T [bh][d][s]
__device__ __nv_bfloat16 g_Wsh[(size_t)BATCH*NH*TSEQ*TSEQ];
__device__ __nv_bfloat16 g_Wsl[(size_t)BATCH*NH*TSEQ*TSEQ];
__device__ __nv_bfloat16 g_Vth[(size_t)BATCH*NH*DK*TSEQ];
__device__ __nv_bfloat16 g_Vtl[(size_t)BATCH*NH*DK*TSEQ];

// ---------------------------------------------------------------------------
// helpers
// ---------------------------------------------------------------------------
__device__ __forceinline__ uint32_t smem_u32(const void* p) {
  uint32_t a;
  asm("{ .reg .u64 t; cvta.to.shared.u64 t, %1; cvt.u32.u64 %0, t; }" : "=r"(a) : "l"(p));
  return a;
}
__device__ __forceinline__ void cp16(uint32_t dst, const void* src) {
  asm volatile("cp.async.cg.shared.global [%0], [%1], 16;" :: "r"(dst), "l"(src));
}
__device__ __forceinline__ void cp_commit() {
  asm volatile("cp.async.commit_group;" ::: "memory");
}
__device__ __forceinline__ void ldm4(uint32_t& r0, uint32_t& r1, uint32_t& r2,
                                     uint32_t& r3, uint32_t a) {
  asm volatile("ldmatrix.sync.aligned.m8n8.x4.shared.b16 {%0,%1,%2,%3}, [%4];"
               : "=r"(r0), "=r"(r1), "=r"(r2), "=r"(r3) : "r"(a));
}
__device__ __forceinline__ void mma_bf16(float* c, const uint32_t* a,
                                         uint32_t b0, uint32_t b1) {
  asm volatile(
      "mma.sync.aligned.m16n8k16.row.col.f32.bf16.bf16.f32 "
      "{%0,%1,%2,%3}, {%4,%5,%6,%7}, {%8,%9}, {%0,%1,%2,%3};"
      : "+f"(c[0]), "+f"(c[1]), "+f"(c[2]), "+f"(c[3])
      : "r"(a[0]), "r"(a[1]), "r"(a[2]), "r"(a[3]), "r"(b0), "r"(b1));
}
__device__ __forceinline__ uint32_t pack_bf2(float a, float b) {
  __nv_bfloat16 ha = __float2bfloat16(a), hb = __float2bfloat16(b);
  uint16_t ua = *(uint16_t*)&ha, ub = *(uint16_t*)&hb;
  return (uint32_t)ua | ((uint32_t)ub << 16);
}
__device__ __forceinline__ float bf_res(float v) {
  return v - __bfloat162float(__float2bfloat16(v));
}

// ---------------------------------------------------------------------------
// Split conversion: f32 -> bf16 hi/lo.  DST 0: x, DST 1: pos (zero-padded)
// ---------------------------------------------------------------------------
template<int DST>
__global__ void __launch_bounds__(256) split_kernel(const float* __restrict__ in,
                                                    int n, int n_total) {
  __nv_bfloat16* hi = (DST == 0) ? g_Ah : g_pAh;
  __nv_bfloat16* lo = (DST == 0) ? g_Al : g_pAl;
  for (int i = blockIdx.x * 256 + threadIdx.x; i < n_total; i += gridDim.x * 256) {
    float v = (i < n) ? in[i] : 0.f;
    __nv_bfloat16 h = __float2bfloat16(v);
    hi[i] = h;
    lo[i] = __float2bfloat16(v - __bfloat162float(h));
  }
}

// Transpose + split: in[R][C] f32 -> out[C][R] bf16 hi/lo. DST 0: qvk_w, 1: pos_w
template<int DST>
__global__ void __launch_bounds__(256) tsplit_kernel(const float* __restrict__ in,
                                                     int R, int C) {
  __nv_bfloat16* hi = (DST == 0) ? g_Wh : g_pWh;
  __nv_bfloat16* lo = (DST == 0) ? g_Wl : g_pWl;
  __shared__ float t[32][33];
  const int c0 = blockIdx.x * 32, r0 = blockIdx.y * 32;
  const int tx = threadIdx.x & 31, ty = threadIdx.x >> 5;  // 32x8
#pragma unroll
  for (int i = 0; i < 4; i++)
    t[ty + i * 8][tx] = in[(size_t)(r0 + ty + i * 8) * C + c0 + tx];
  __syncthreads();
#pragma unroll
  for (int i = 0; i < 4; i++) {
    float v = t[tx][ty + i * 8];
    __nv_bfloat16 h = __float2bfloat16(v);
    size_t o = (size_t)(c0 + ty + i * 8) * R + r0 + tx;
    hi[o] = h;
    lo[o] = __float2bfloat16(v - __bfloat162float(h));
  }
}

// V transpose + split: g_V [bh][s][d] f32 -> g_Vth/g_Vtl [bh][d][s] bf16
__global__ void __launch_bounds__(256) vtsplit_kernel() {
  __shared__ float t[64][65];
  const int s0 = blockIdx.x * 64;
  const int bh = blockIdx.y;
  const int tid = threadIdx.x;
  const float* vbase = g_V + (size_t)bh * TSEQ * DK;
  for (int i = tid; i < 4096; i += 256) {
    const int sl = i >> 6, d = i & 63;
    t[sl][d] = vbase[(size_t)(s0 + sl) * DK + d];
  }
  __syncthreads();
  // write [d][s]: 2 consecutive s per thread -> 4B stores
  for (int i = tid; i < 2048; i += 256) {
    const int d = i >> 5, sl = (i & 31) * 2;
    const float v0 = t[sl][d], v1 = t[sl + 1][d];
    const size_t o = ((size_t)bh * DK + d) * TSEQ + s0 + sl;
    *(uint32_t*)&g_Vth[o] = pack_bf2(v0, v1);
    *(uint32_t*)&g_Vtl[o] = pack_bf2(bf_res(v0), bf_res(v1));
  }
}

// ---------------------------------------------------------------------------
// mma.sync bf16 GEMM:  C[M,N] = A[M,1024] @ B^T  (B stored [N][1024], K-major)
// 3-pass split: hi*hi + hi*lo + lo*hi, fp32 accum.
// CTA tile 128x128, K-chunk 64, cp.async double buffer, SW128 smem swizzle.
// MODE 0: QKV scatter (+bias) -> g_Q/g_K/g_V. MODE 1: pos -> g_P.
// ---------------------------------------------------------------------------
#define PBUF 65536
#define OFF_AH 0
#define OFF_AL 16384
#define OFF_BH 32768
#define OFF_BL 49152
#define GSMEM (2 * PBUF)  // 131072

template<int MODE>
__global__ void __launch_bounds__(256, 1) mma_gemm(const float* __restrict__ bias) {
  extern __shared__ char smem[];
  const uint32_t sb = smem_u32(smem);
  const int tid = threadIdx.x;
  const int wid = tid >> 5, lane = tid & 31;
  const int n0 = blockIdx.x * 128;
  const int m0 = blockIdx.y * 128;
  const int wm = wid & 3;
  const int wn = wid >> 2;

  const __nv_bfloat16* Ah = (MODE == 0) ? g_Ah : g_pAh;
  const __nv_bfloat16* Al = (MODE == 0) ? g_Al : g_pAl;
  const __nv_bfloat16* Bh = (MODE == 0) ? g_Wh : g_pWh;
  const __nv_bfloat16* Bl = (MODE == 0) ? g_Wl : g_pWl;

  const int gr = tid >> 3;
  const int gc = tid & 7;
  const uint32_t gsw = (uint32_t)((gc * 16) ^ ((gr & 7) << 4));

  const int l7 = lane & 7;
  const uint32_t xa = (uint32_t)(l7 << 4);
  const int rowA0 = wm * 32 + l7 + (((lane >> 3) & 1) << 3);
  const uint32_t kadd_a = (uint32_t)(((lane >> 4) & 1) << 4);
  const int rowB0 = wn * 64 + l7 + (((lane >> 4) & 1) << 3);
  const uint32_t kadd_b = (uint32_t)(((lane >> 3) & 1) << 4);

  float acc[2][8][4];
#pragma unroll
  for (int mt = 0; mt < 2; mt++)
#pragma unroll
    for (int nt = 0; nt < 8; nt++)
#pragma unroll
      for (int i = 0; i < 4; i++) acc[mt][nt][i] = 0.f;

  auto load_chunk = [&](int kc, int buf) {
    const int k0 = kc * 64;
    const uint32_t base = sb + buf * PBUF;
#pragma unroll
    for (int it = 0; it < 4; it++) {
      const int r = gr + it * 32;
      const uint32_t sw = (uint32_t)(r * 128) + gsw;
      const size_t asrc = (size_t)(m0 + r) * DM + k0 + gc * 8;
      const size_t bsrc = (size_t)(n0 + r) * DM + k0 + gc * 8;
      cp16(base + OFF_AH + sw, Ah + asrc);
      cp16(base + OFF_AL + sw, Al + asrc);
      cp16(base + OFF_BH + sw, Bh + bsrc);
      cp16(base + OFF_BL + sw, Bl + bsrc);
    }
    cp_commit();
  };

  load_chunk(0, 0);

  for (int kc = 0; kc < 16; kc++) {
    if (kc + 1 < 16) {
      load_chunk(kc + 1, (kc + 1) & 1);
      asm volatile("cp.async.wait_group 1;" ::: "memory");
    } else {
      asm volatile("cp.async.wait_group 0;" ::: "memory");
    }
    __syncthreads();

    const uint32_t bb = sb + (kc & 1) * PBUF;
#pragma unroll
    for (int ks = 0; ks < 4; ks++) {
      const uint32_t kba = (uint32_t)(ks * 32);
      uint32_t ah[2][4], al[2][4];
#pragma unroll
      for (int mt = 0; mt < 2; mt++) {
        const uint32_t aoff = (uint32_t)((rowA0 + mt * 16) * 128) + ((kba + kadd_a) ^ xa);
        ldm4(ah[mt][0], ah[mt][1], ah[mt][2], ah[mt][3], bb + OFF_AH + aoff);
        ldm4(al[mt][0], al[mt][1], al[mt][2], al[mt][3], bb + OFF_AL + aoff);
      }
#pragma unroll
      for (int np = 0; np < 4; np++) {
        const uint32_t boff = (uint32_t)((rowB0 + np * 16) * 128) + ((kba + kadd_b) ^ xa);
        uint32_t bh[4], bl[4];
        ldm4(bh[0], bh[1], bh[2], bh[3], bb + OFF_BH + boff);
        ldm4(bl[0], bl[1], bl[2], bl[3], bb + OFF_BL + boff);
#pragma unroll
        for (int mt = 0; mt < 2; mt++) {
          mma_bf16(acc[mt][2 * np + 0], ah[mt], bh[0], bh[1]);
          mma_bf16(acc[mt][2 * np + 1], ah[mt], bh[2], bh[3]);
          mma_bf16(acc[mt][2 * np + 0], ah[mt], bl[0], bl[1]);
          mma_bf16(acc[mt][2 * np + 1], ah[mt], bl[2], bl[3]);
          mma_bf16(acc[mt][2 * np + 0], al[mt], bh[0], bh[1]);
          mma_bf16(acc[mt][2 * np + 1], al[mt], bh[2], bh[3]);
        }
      }
    }
    __syncthreads();
  }

  const int mrow = m0 + wm * 32 + (lane >> 2);
#pragma unroll
  for (int mt = 0; mt < 2; mt++) {
#pragma unroll
    for (int half = 0; half < 2; half++) {
      const int m = mrow + mt * 16 + half * 8;
#pragma unroll
      for (int nt = 0; nt < 8; nt++) {
        const int n = n0 + wn * 64 + nt * 8 + (lane & 3) * 2;
        float2 o;
        o.x = acc[mt][nt][half * 2 + 0];
        o.y = acc[mt][nt][half * 2 + 1];
        if (MODE == 0) {
          o.x += bias[n];
          o.y += bias[n + 1];
          const int b = m >> 9, t = m & 511;
          const int sec = n >> 10;
          const int h = (n >> 6) & 15;
          const int d = n & 63;
          float* dst = (sec == 0 ? g_Q : sec == 1 ? g_K : g_V)
                       + (((size_t)(b * NH + h) * TSEQ + t) * DK + d);
          *(float2*)dst = o;
        } else {
          if (m < RR) {
            const int h = n >> 6;
            const int d = n & 63;
            *(float2*)(g_P + ((size_t)h * RR + m) * DK + d) = o;
          }
        }
      }
    }
  }
}

// ---------------------------------------------------------------------------
// Scores on tensor cores: per CTA (t-tile 64, s-tile 128, bh):
//   AC = QU @ K^T, BD = QV @ Pband^T; out[t][s] = (AC + BD[t][s-t+63]) / 8
// ---------------------------------------------------------------------------
#define S_QUH 0
#define S_QUL 8192
#define S_QVH 16384
#define S_QVL 24576
#define S_KH  32768
#define S_KL  49152
#define S_PH  65536
#define S_PL  90112
#define S_BD  114688            // 64 x 196 fp32
#define S_SMEM (114688 + 64*196*4)  // 164864

__global__ void __launch_bounds__(256, 1) scores_mma(
    const float* __restrict__ pu, const float* __restrict__ pv,
    float* __restrict__ wout) {
  extern __shared__ char smem[];
  const uint32_t sb = smem_u32(smem);
  float* BDs = (float*)(smem + S_BD);
  const int tid = threadIdx.x;
  const int wid = tid >> 5, lane = tid & 31;
  const int s0 = blockIdx.x * 128;
  const int t0 = blockIdx.y * 64;
  const int bh = blockIdx.z, h = bh & 15;

  const int frow = tid >> 4;
  const int c4 = (tid & 15) * 4;
  const uint32_t cb = (uint32_t)(c4 * 2);
  const float4 pu4 = *(const float4*)(pu + h * 64 + c4);
  const float4 pv4 = *(const float4*)(pv + h * 64 + c4);
  const float* qb = g_Q + ((size_t)bh * TSEQ + t0) * DK;
  const float* kb = g_K + ((size_t)bh * TSEQ + s0) * DK;
  const float* Pb = g_P + (size_t)h * RR * DK;
  const int relbase = s0 - t0 + 448;

#pragma unroll
  for (int it = 0; it < 4; it++) {
    const int row = frow + it * 16;
    const float4 q = *(const float4*)(qb + (size_t)row * DK + c4);
    const uint32_t sw = (uint32_t)(row * 128) + (cb ^ ((uint32_t)(row & 7) << 4));
    float ux = q.x + pu4.x, uy = q.y + pu4.y, uz = q.z + pu4.z, uw = q.w + pu4.w;
    float vx = q.x + pv4.x, vy = q.y + pv4.y, vz = q.z + pv4.z, vw = q.w + pv4.w;
    uint2 hh, ll;
    hh.x = pack_bf2(ux, uy); hh.y = pack_bf2(uz, uw);
    ll.x = pack_bf2(bf_res(ux), bf_res(uy));
    ll.y = pack_bf2(bf_res(uz), bf_res(uw));
    *(uint2*)(smem + S_QUH + sw) = hh;
    *(uint2*)(smem + S_QUL + sw) = ll;
    hh.x = pack_bf2(vx, vy); hh.y = pack_bf2(vz, vw);
    ll.x = pack_bf2(bf_res(vx), bf_res(vy));
    ll.y = pack_bf2(bf_res(vz), bf_res(vw));
    *(uint2*)(smem + S_QVH + sw) = hh;
    *(uint2*)(smem + S_QVL + sw) = ll;
  }
#pragma unroll
  for (int it = 0; it < 8; it++) {
    const int row = frow + it * 16;
    const float4 k = *(const float4*)(kb + (size_t)row * DK + c4);
    const uint32_t sw = (uint32_t)(row * 128) + (cb ^ ((uint32_t)(row & 7) << 4));
    uint2 hh, ll;
    hh.x = pack_bf2(k.x, k.y); hh.y = pack_bf2(k.z, k.w);
    ll.x = pack_bf2(bf_res(k.x), bf_res(k.y));
    ll.y = pack_bf2(bf_res(k.z), bf_res(k.w));
    *(uint2*)(smem + S_KH + sw) = hh;
    *(uint2*)(smem + S_KL + sw) = ll;
  }
#pragma unroll
  for (int it = 0; it < 12; it++) {
    const int row = frow + it * 16;
    const int r = relbase + row;
    float4 p = make_float4(0.f, 0.f, 0.f, 0.f);
    if (r >= 0 && r < RR) p = *(const float4*)(Pb + (size_t)r * DK + c4);
    const uint32_t sw = (uint32_t)(row * 128) + (cb ^ ((uint32_t)(row & 7) << 4));
    uint2 hh, ll;
    hh.x = pack_bf2(p.x, p.y); hh.y = pack_bf2(p.z, p.w);
    ll.x = pack_bf2(bf_res(p.x), bf_res(p.y));
    ll.y = pack_bf2(bf_res(p.z), bf_res(p.w));
    *(uint2*)(smem + S_PH + sw) = hh;
    *(uint2*)(smem + S_PL + sw) = ll;
  }
  __syncthreads();

  const int wm = wid & 3;
  const int wn = wid >> 2;
  const int l7 = lane & 7;
  const uint32_t xa = (uint32_t)(l7 << 4);
  const int rowA = wm * 16 + l7 + (((lane >> 3) & 1) << 3);
  const uint32_t kadd_a = (uint32_t)(((lane >> 4) & 1) << 4);
  const int rbB = l7 + (((lane >> 4) & 1) << 3);
  const uint32_t kadd_b = (uint32_t)(((lane >> 3) & 1) << 4);

  float ac[8][4], bd[12][4];
#pragma unroll
  for (int nt = 0; nt < 8; nt++)
#pragma unroll
    for (int i = 0; i < 4; i++) ac[nt][i] = 0.f;
#pragma unroll
  for (int nt = 0; nt < 12; nt++)
#pragma unroll
    for (int i = 0; i < 4; i++) bd[nt][i] = 0.f;

#pragma unroll
  for (int ks = 0; ks < 4; ks++) {
    const uint32_t kba = (uint32_t)(ks * 32);
    const uint32_t aoff = (uint32_t)(rowA * 128) + ((kba + kadd_a) ^ xa);
    uint32_t quh[4], qul[4], qvh[4], qvl[4];
    ldm4(quh[0], quh[1], quh[2], quh[3], sb + S_QUH + aoff);
    ldm4(qul[0], qul[1], qul[2], qul[3], sb + S_QUL + aoff);
    ldm4(qvh[0], qvh[1], qvh[2], qvh[3], sb + S_QVH + aoff);
    ldm4(qvl[0], qvl[1], qvl[2], qvl[3], sb + S_QVL + aoff);
#pragma unroll
    for (int np = 0; np < 4; np++) {
      const int rowB = wn * 64 + np * 16 + rbB;
      const uint32_t boff = (uint32_t)(rowB * 128) + ((kba + kadd_b) ^ xa);
      uint32_t kh[4], kl[4];
      ldm4(kh[0], kh[1], kh[2], kh[3], sb + S_KH + boff);
      ldm4(kl[0], kl[1], kl[2], kl[3], sb + S_KL + boff);
      mma_bf16(ac[2 * np + 0], quh, kh[0], kh[1]);
      mma_bf16(ac[2 * np + 1], quh, kh[2], kh[3]);
      mma_bf16(ac[2 * np + 0], quh, kl[0], kl[1]);
      mma_bf16(ac[2 * np + 1], quh, kl[2], kl[3]);
      mma_bf16(ac[2 * np + 0], qul, kh[0], kh[1]);
      mma_bf16(ac[2 * np + 1], qul, kh[2], kh[3]);
    }
#pragma unroll
    for (int np = 0; np < 6; np++) {
      const int rowB = wn * 96 + np * 16 + rbB;
      const uint32_t boff = (uint32_t)(rowB * 128) + ((kba + kadd_b) ^ xa);
      uint32_t ph[4], pl[4];
      ldm4(ph[0], ph[1], ph[2], ph[3], sb + S_PH + boff);
      ldm4(pl[0], pl[1], pl[2], pl[3], sb + S_PL + boff);
      mma_bf16(bd[2 * np + 0], qvh, ph[0], ph[1]);
      mma_bf16(bd[2 * np + 1], qvh, ph[2], ph[3]);
      mma_bf16(bd[2 * np + 0], qvh, pl[0], pl[1]);
      mma_bf16(bd[2 * np + 1], qvh, pl[2], pl[3]);
      mma_bf16(bd[2 * np + 0], qvl, ph[0], ph[1]);
      mma_bf16(bd[2 * np + 1], qvl, ph[2], ph[3]);
    }
  }

  const int r0w = wm * 16 + (lane >> 2);
#pragma unroll
  for (int nt = 0; nt < 12; nt++) {
    const int col = wn * 96 + nt * 8 + (lane & 3) * 2;
    *(float2*)&BDs[r0w * 196 + col] = make_float2(bd[nt][0], bd[nt][1]);
    *(float2*)&BDs[(r0w + 8) * 196 + col] = make_float2(bd[nt][2], bd[nt][3]);
  }
  __syncthreads();

  float* wbase = wout + ((size_t)bh * TSEQ + t0) * TSEQ + s0;
#pragma unroll
  for (int nt = 0; nt < 8; nt++) {
    const int col = wn * 64 + nt * 8 + (lane & 3) * 2;
#pragma unroll
    for (int half = 0; half < 2; half++) {
      const int row = r0w + half * 8;
      const int bdi = row * 196 + col - row + 63;
      float2 o;
      o.x = (ac[nt][half * 2 + 0] + BDs[bdi]) * 0.125f;
      o.y = (ac[nt][half * 2 + 1] + BDs[bdi + 1]) * 0.125f;
      *(float2*)(wbase + (size_t)row * TSEQ + col) = o;
    }
  }
}

// ---------------------------------------------------------------------------
// Softmax over rows of 512, in place; also emits bf16 hi/lo weights.
// One warp per row.
// ---------------------------------------------------------------------------
__global__ void __launch_bounds__(256) softmax_kernel(float* __restrict__ w) {
  const int gwarp = (blockIdx.x * 256 + threadIdx.x) >> 5;
  const int lane = threadIdx.x & 31;
  const size_t rbase = (size_t)gwarp * TSEQ;
  float* row = w + rbase;
  float4 v[4];
#pragma unroll
  for (int k = 0; k < 4; k++) v[k] = *(float4*)(row + k * 128 + lane * 4);
  float m = v[0].x;
#pragma unroll
  for (int k = 0; k < 4; k++)
    m = fmaxf(m, fmaxf(fmaxf(v[k].x, v[k].y), fmaxf(v[k].z, v[k].w)));
#pragma unroll
  for (int off = 16; off > 0; off >>= 1)
    m = fmaxf(m, __shfl_xor_sync(0xffffffffu, m, off));
  float s = 0.f;
#pragma unroll
  for (int k = 0; k < 4; k++) {
    v[k].x = __expf(v[k].x - m); s += v[k].x;
    v[k].y = __expf(v[k].y - m); s += v[k].y;
    v[k].z = __expf(v[k].z - m); s += v[k].z;
    v[k].w = __expf(v[k].w - m); s += v[k].w;
  }
#pragma unroll
  for (int off = 16; off > 0; off >>= 1)
    s += __shfl_xor_sync(0xffffffffu, s, off);
  const float inv = 1.0f / s;
#pragma unroll
  for (int k = 0; k < 4; k++) {
    v[k].x *= inv; v[k].y *= inv; v[k].z *= inv; v[k].w *= inv;
    *(float4*)(row + k * 128 + lane * 4) = v[k];
    const size_t o = rbase + k * 128 + lane * 4;
    uint2 hh, ll;
    hh.x = pack_bf2(v[k].x, v[k].y); hh.y = pack_bf2(v[k].z, v[k].w);
    ll.x = pack_bf2(bf_res(v[k].x), bf_res(v[k].y));
    ll.y = pack_bf2(bf_res(v[k].z), bf_res(v[k].w));
    *(uint2*)&g_Wsh[o] = hh;
    *(uint2*)&g_Wsl[o] = ll;
  }
}

// ---------------------------------------------------------------------------
// Context GEMM (tensor cores): ctx[b,t,h*64+d] = sum_s W[bh,t,s] * Vt[bh,d,s]
// CTA tile 128t x 64d per bh, K=512 in 8 chunks of 64, cp.async double buffer.
// ---------------------------------------------------------------------------
#define CBUF 49152
#define C_WH 0
#define C_WL 16384
#define C_VH 32768
#define C_VL 40960
#define CSMEM (2 * CBUF)  // 98304

__global__ void __launch_bounds__(256, 2) ctx_mma(float* __restrict__ ctx) {
  extern __shared__ char smem[];
  const uint32_t sb = smem_u32(smem);
  const int tid = threadIdx.x;
  const int wid = tid >> 5, lane = tid & 31;
  const int t0 = blockIdx.x * 128;
  const int bh = blockIdx.y;
  const int b = bh >> 4, h = bh & 15;

  const __nv_bfloat16* Wh = g_Wsh + (size_t)bh * TSEQ * TSEQ;
  const __nv_bfloat16* Wl = g_Wsl + (size_t)bh * TSEQ * TSEQ;
  const __nv_bfloat16* Vh = g_Vth + (size_t)bh * DK * TSEQ;
  const __nv_bfloat16* Vl = g_Vtl + (size_t)bh * DK * TSEQ;

  const int gr = tid >> 3;
  const int gc = tid & 7;
  const uint32_t gsw = (uint32_t)((gc * 16) ^ ((gr & 7) << 4));

  const int wm = wid & 3;   // 32 t-rows each
  const int wn = wid >> 2;  // 32 d-cols each
  const int l7 = lane & 7;
  const uint32_t xa = (uint32_t)(l7 << 4);
  const int rowA0 = wm * 32 + l7 + (((lane >> 3) & 1) << 3);
  const uint32_t kadd_a = (uint32_t)(((lane >> 4) & 1) << 4);
  const int rowB0 = wn * 32 + l7 + (((lane >> 4) & 1) << 3);
  const uint32_t kadd_b = (uint32_t)(((lane >> 3) & 1) << 4);

  float acc[2][4][4];
#pragma unroll
  for (int mt = 0; mt < 2; mt++)
#pragma unroll
    for (int nt = 0; nt < 4; nt++)
#pragma unroll
      for (int i = 0; i < 4; i++) acc[mt][nt][i] = 0.f;

  auto load_chunk = [&](int kc, int buf) {
    const int k0 = kc * 64;
    const uint32_t base = sb + buf * CBUF;
#pragma unroll
    for (int it = 0; it < 4; it++) {
      const int r = gr + it * 32;
      const uint32_t sw = (uint32_t)(r * 128) + gsw;
      const size_t src = (size_t)(t0 + r) * TSEQ + k0 + gc * 8;
      cp16(base + C_WH + sw, Wh + src);
      cp16(base + C_WL + sw, Wl + src);
    }
#pragma unroll
    for (int it = 0; it < 2; it++) {
      const int r = gr + it * 32;
      const uint32_t sw = (uint32_t)(r * 128) + gsw;
      const size_t src = (size_t)r * TSEQ + k0 + gc * 8;
      cp16(base + C_VH + sw, Vh + src);
      cp16(base + C_VL + sw, Vl + src);
    }
    cp_commit();
  };

  load_chunk(0, 0);

  for (int kc = 0; kc < 8; kc++) {
    if (kc + 1 < 8) {
      load_chunk(kc + 1, (kc + 1) & 1);
      asm volatile("cp.async.wait_group 1;" ::: "memory");
    } else {
      asm volatile("cp.async.wait_group 0;" ::: "memory");
    }
    __syncthreads();

    const uint32_t bb = sb + (kc & 1) * CBUF;
#pragma unroll
    for (int ks = 0; ks < 4; ks++) {
      const uint32_t kba = (uint32_t)(ks * 32);
      uint32_t ah[2][4], al[2][4];
#pragma unroll
      for (int mt = 0; mt < 2; mt++) {
        const uint32_t aoff = (uint32_t)((rowA0 + mt * 16) * 128) + ((kba + kadd_a) ^ xa);
        ldm4(ah[mt][0], ah[mt][1], ah[mt][2], ah[mt][3], bb + C_WH + aoff);
        ldm4(al[mt][0], al[mt][1], al[mt][2], al[mt][3], bb + C_WL + aoff);
      }
#pragma unroll
      for (int np = 0; np < 2; np++) {
        const uint32_t boff = (uint32_t)((rowB0 + np * 16) * 128) + ((kba + kadd_b) ^ xa);
        uint32_t vh[4], vl[4];
        ldm4(vh[0], vh[1], vh[2], vh[3], bb + C_VH + boff);
        ldm4(vl[0], vl[1], vl[2], vl[3], bb + C_VL + boff);
#pragma unroll
        for (int mt = 0; mt < 2; mt++) {
          mma_bf16(acc[mt][2 * np + 0], ah[mt], vh[0], vh[1]);
          mma_bf16(acc[mt][2 * np + 1], ah[mt], vh[2], vh[3]);
          mma_bf16(acc[mt][2 * np + 0], ah[mt], vl[0], vl[1]);
          mma_bf16(acc[mt][2 * np + 1], ah[mt], vl[2], vl[3]);
          mma_bf16(acc[mt][2 * np + 0], al[mt], vh[0], vh[1]);
          mma_bf16(acc[mt][2 * np + 1], al[mt], vh[2], vh[3]);
        }
      }
    }
    __syncthreads();
  }

  const int mrow = t0 + wm * 32 + (lane >> 2);
#pragma unroll
  for (int mt = 0; mt < 2; mt++) {
#pragma unroll
    for (int half = 0; half < 2; half++) {
      const int t = mrow + mt * 16 + half * 8;
#pragma unroll
      for (int nt = 0; nt < 4; nt++) {
        const int d = wn * 32 + nt * 8 + (lane & 3) * 2;
        float2 o;
        o.x = acc[mt][nt][half * 2 + 0];
        o.y = acc[mt][nt][half * 2 + 1];
        *(float2*)(ctx + ((size_t)b * TSEQ + t) * DM + h * DK + d) = o;
      }
    }
  }
}

// ---------------------------------------------------------------------------
// Launch
// inputs: 0=x 1=mask 2=pos 3=qvk_w 4=qvk_b 5=pos_w 6=posu 7=posv
// output: [context (16*512*1024) | weights (16*16*512*512)] float32
// ---------------------------------------------------------------------------
extern "C" void kernel_launch(void* const* d_in, const int* in_sizes, int n_in,
                              void* d_out, int out_size) {
  const float* x     = (const float*)d_in[0];
  const float* pos   = (const float*)d_in[2];
  const float* qvk_w = (const float*)d_in[3];
  const float* qvk_b = (const float*)d_in[4];
  const float* pos_w = (const float*)d_in[5];
  const float* posu  = (const float*)d_in[6];
  const float* posv  = (const float*)d_in[7];

  float* ctx = (float*)d_out;
  float* wts = (float*)d_out + (size_t)BATCH * TSEQ * DM;

  // 0) bf16 hi/lo splits (+ transposed weights)
  split_kernel<0><<<1024, 256>>>(x, BATCH * TSEQ * DM, BATCH * TSEQ * DM);
  tsplit_kernel<0><<<dim3(D3 / 32, DM / 32), 256>>>(qvk_w, DM, D3);
  split_kernel<1><<<512, 256>>>(pos, RR * DM, 1024 * DM);
  tsplit_kernel<1><<<dim3(DM / 32, DM / 32), 256>>>(pos_w, DM, DM);

  // 1) QKV projection (8192 x 1024) @ (1024 x 3072) on mma.sync bf16x3
  cudaFuncSetAttribute(mma_gemm<0>, cudaFuncAttributeMaxDynamicSharedMemorySize,
                       GSMEM);
  cudaFuncSetAttribute(mma_gemm<1>, cudaFuncAttributeMaxDynamicSharedMemorySize,
                       GSMEM);
  mma_gemm<0><<<dim3(D3 / 128, (BATCH * TSEQ) / 128), 256, GSMEM>>>(qvk_b);

  // 2) pos projection: (1024(pad) x 1024) @ (1024 x 1024)
  mma_gemm<1><<<dim3(DM / 128, 1024 / 128), 256, GSMEM>>>(nullptr);

  // 2b) V -> V^T bf16 hi/lo
  vtsplit_kernel<<<dim3(TSEQ / 64, BATCH * NH), 256>>>();

  // 3) scores on tensor cores (AC + shifted BD, scaled) -> weights region
  cudaFuncSetAttribute(scores_mma, cudaFuncAttributeMaxDynamicSharedMemorySize,
                       S_SMEM);
  scores_mma<<<dim3(TSEQ / 128, TSEQ / 64, BATCH * NH), 256, S_SMEM>>>(
      posu, posv, wts);

  // 4) softmax in place (+ bf16 hi/lo weight emission)
  softmax_kernel<<<(BATCH * NH * TSEQ) / 8, 256>>>(wts);

  // 5) context = W @ V on tensor cores
  cudaFuncSetAttribute(ctx_mma, cudaFuncAttributeMaxDynamicSharedMemorySize,
                       CSMEM);
  ctx_mma<<<dim3(TSEQ / 128, BATCH * NH), 256, CSMEM>>>(ctx);
}

// round 7
// speedup vs baseline: 1.4180x; 1.0802x over previous
#include <cuda_runtime.h>
#include <cuda_bf16.h>
#include <cstdint>

#define BATCH 16
#define TSEQ 512
#define NH 16
#define DK 64
#define DM 1024
#define D3 3072
#define RR 1023  // 2T-1

// ---------------------------------------------------------------------------
// Scratch (allocation-free: device globals)
// ---------------------------------------------------------------------------
__device__ float g_Q[BATCH*NH*TSEQ*DK];
__device__ float g_V[BATCH*NH*TSEQ*DK];

// K and P stored directly as bf16 hi/lo (written by projection epilogues)
__device__ __nv_bfloat16 g_Kh[BATCH*NH*TSEQ*DK];
__device__ __nv_bfloat16 g_Kl[BATCH*NH*TSEQ*DK];
__device__ __nv_bfloat16 g_Ph[NH*RR*DK];
__device__ __nv_bfloat16 g_Pl[NH*RR*DK];

// bf16 hi/lo split operands for projection GEMMs
__device__ __nv_bfloat16 g_Ah[BATCH*TSEQ*DM];
__device__ __nv_bfloat16 g_Al[BATCH*TSEQ*DM];
__device__ __nv_bfloat16 g_Wh[D3*DM];      // qvk_w transposed: [3072][1024]
__device__ __nv_bfloat16 g_Wl[D3*DM];
__device__ __nv_bfloat16 g_pAh[1024*DM];   // pos padded to 1024 rows
__device__ __nv_bfloat16 g_pAl[1024*DM];
__device__ __nv_bfloat16 g_pWh[DM*DM];     // pos_w transposed
__device__ __nv_bfloat16 g_pWl[DM*DM];

// bf16 hi/lo normalized weights [bh][t][s] and V^T [bh][d][s]
__device__ __nv_bfloat16 g_Wsh[(size_t)BATCH*NH*TSEQ*TSEQ];
__device__ __nv_bfloat16 g_Wsl[(size_t)BATCH*NH*TSEQ*TSEQ];
__device__ __nv_bfloat16 g_Vth[(size_t)BATCH*NH*DK*TSEQ];
__device__ __nv_bfloat16 g_Vtl[(size_t)BATCH*NH*DK*TSEQ];

// ---------------------------------------------------------------------------
// helpers
// ---------------------------------------------------------------------------
__device__ __forceinline__ uint32_t smem_u32(const void* p) {
  uint32_t a;
  asm("{ .reg .u64 t; cvta.to.shared.u64 t, %1; cvt.u32.u64 %0, t; }" : "=r"(a) : "l"(p));
  return a;
}
__device__ __forceinline__ void cp16(uint32_t dst, const void* src) {
  asm volatile("cp.async.cg.shared.global [%0], [%1], 16;" :: "r"(dst), "l"(src));
}
__device__ __forceinline__ void cp16z(uint32_t dst, const void* src, int nbytes) {
  asm volatile("cp.async.cg.shared.global [%0], [%1], 16, %2;"
               :: "r"(dst), "l"(src), "r"(nbytes));
}
__device__ __forceinline__ void cp_commit() {
  asm volatile("cp.async.commit_group;" ::: "memory");
}
__device__ __forceinline__ void ldm4(uint32_t& r0, uint32_t& r1, uint32_t& r2,
                                     uint32_t& r3, uint32_t a) {
  asm volatile("ldmatrix.sync.aligned.m8n8.x4.shared.b16 {%0,%1,%2,%3}, [%4];"
               : "=r"(r0), "=r"(r1), "=r"(r2), "=r"(r3) : "r"(a));
}
__device__ __forceinline__ void mma_bf16(float* c, const uint32_t* a,
                                         uint32_t b0, uint32_t b1) {
  asm volatile(
      "mma.sync.aligned.m16n8k16.row.col.f32.bf16.bf16.f32 "
      "{%0,%1,%2,%3}, {%4,%5,%6,%7}, {%8,%9}, {%0,%1,%2,%3};"
      : "+f"(c[0]), "+f"(c[1]), "+f"(c[2]), "+f"(c[3])
      : "r"(a[0]), "r"(a[1]), "r"(a[2]), "r"(a[3]), "r"(b0), "r"(b1));
}
__device__ __forceinline__ uint32_t pack_bf2(float a, float b) {
  __nv_bfloat16 ha = __float2bfloat16(a), hb = __float2bfloat16(b);
  uint16_t ua = *(uint16_t*)&ha, ub = *(uint16_t*)&hb;
  return (uint32_t)ua | ((uint32_t)ub << 16);
}
__device__ __forceinline__ float bf_res(float v) {
  return v - __bfloat162float(__float2bfloat16(v));
}

// ---------------------------------------------------------------------------
// Split conversion: f32 -> bf16 hi/lo.  DST 0: x, DST 1: pos (zero-padded)
// ---------------------------------------------------------------------------
template<int DST>
__global__ void __launch_bounds__(256) split_kernel(const float* __restrict__ in,
                                                    int n, int n_total) {
  __nv_bfloat16* hi = (DST == 0) ? g_Ah : g_pAh;
  __nv_bfloat16* lo = (DST == 0) ? g_Al : g_pAl;
  for (int i = blockIdx.x * 256 + threadIdx.x; i < n_total; i += gridDim.x * 256) {
    float v = (i < n) ? in[i] : 0.f;
    __nv_bfloat16 h = __float2bfloat16(v);
    hi[i] = h;
    lo[i] = __float2bfloat16(v - __bfloat162float(h));
  }
}

// Transpose + split: in[R][C] f32 -> out[C][R] bf16 hi/lo. DST 0: qvk_w, 1: pos_w
template<int DST>
__global__ void __launch_bounds__(256) tsplit_kernel(const float* __restrict__ in,
                                                     int R, int C) {
  __nv_bfloat16* hi = (DST == 0) ? g_Wh : g_pWh;
  __nv_bfloat16* lo = (DST == 0) ? g_Wl : g_pWl;
  __shared__ float t[32][33];
  const int c0 = blockIdx.x * 32, r0 = blockIdx.y * 32;
  const int tx = threadIdx.x & 31, ty = threadIdx.x >> 5;  // 32x8
#pragma unroll
  for (int i = 0; i < 4; i++)
    t[ty + i * 8][tx] = in[(size_t)(r0 + ty + i * 8) * C + c0 + tx];
  __syncthreads();
#pragma unroll
  for (int i = 0; i < 4; i++) {
    float v = t[tx][ty + i * 8];
    __nv_bfloat16 h = __float2bfloat16(v);
    size_t o = (size_t)(c0 + ty + i * 8) * R + r0 + tx;
    hi[o] = h;
    lo[o] = __float2bfloat16(v - __bfloat162float(h));
  }
}

// V transpose + split: g_V [bh][s][d] f32 -> g_Vth/g_Vtl [bh][d][s] bf16
__global__ void __launch_bounds__(256) vtsplit_kernel() {
  __shared__ float t[64][65];
  const int s0 = blockIdx.x * 64;
  const int bh = blockIdx.y;
  const int tid = threadIdx.x;
  const float* vbase = g_V + (size_t)bh * TSEQ * DK;
  for (int i = tid; i < 4096; i += 256) {
    const int sl = i >> 6, d = i & 63;
    t[sl][d] = vbase[(size_t)(s0 + sl) * DK + d];
  }
  __syncthreads();
  for (int i = tid; i < 2048; i += 256) {
    const int d = i >> 5, sl = (i & 31) * 2;
    const float v0 = t[sl][d], v1 = t[sl + 1][d];
    const size_t o = ((size_t)bh * DK + d) * TSEQ + s0 + sl;
    *(uint32_t*)&g_Vth[o] = pack_bf2(v0, v1);
    *(uint32_t*)&g_Vtl[o] = pack_bf2(bf_res(v0), bf_res(v1));
  }
}

// ---------------------------------------------------------------------------
// mma.sync bf16 GEMM:  C[M,N] = A[M,1024] @ B^T  (B stored [N][1024], K-major)
// 3-pass split: hi*hi + hi*lo + lo*hi, fp32 accum.
// MODE 0: QKV scatter (+bias) -> g_Q (f32), g_Kh/g_Kl (bf16), g_V (f32).
// MODE 1: pos -> g_Ph/g_Pl (bf16).
// ---------------------------------------------------------------------------
#define PBUF 65536
#define OFF_AH 0
#define OFF_AL 16384
#define OFF_BH 32768
#define OFF_BL 49152
#define GSMEM (2 * PBUF)  // 131072

template<int MODE>
__global__ void __launch_bounds__(256, 1) mma_gemm(const float* __restrict__ bias) {
  extern __shared__ char smem[];
  const uint32_t sb = smem_u32(smem);
  const int tid = threadIdx.x;
  const int wid = tid >> 5, lane = tid & 31;
  const int n0 = blockIdx.x * 128;
  const int m0 = blockIdx.y * 128;
  const int wm = wid & 3;
  const int wn = wid >> 2;

  const __nv_bfloat16* Ah = (MODE == 0) ? g_Ah : g_pAh;
  const __nv_bfloat16* Al = (MODE == 0) ? g_Al : g_pAl;
  const __nv_bfloat16* Bh = (MODE == 0) ? g_Wh : g_pWh;
  const __nv_bfloat16* Bl = (MODE == 0) ? g_Wl : g_pWl;

  const int gr = tid >> 3;
  const int gc = tid & 7;
  const uint32_t gsw = (uint32_t)((gc * 16) ^ ((gr & 7) << 4));

  const int l7 = lane & 7;
  const uint32_t xa = (uint32_t)(l7 << 4);
  const int rowA0 = wm * 32 + l7 + (((lane >> 3) & 1) << 3);
  const uint32_t kadd_a = (uint32_t)(((lane >> 4) & 1) << 4);
  const int rowB0 = wn * 64 + l7 + (((lane >> 4) & 1) << 3);
  const uint32_t kadd_b = (uint32_t)(((lane >> 3) & 1) << 4);

  float acc[2][8][4];
#pragma unroll
  for (int mt = 0; mt < 2; mt++)
#pragma unroll
    for (int nt = 0; nt < 8; nt++)
#pragma unroll
      for (int i = 0; i < 4; i++) acc[mt][nt][i] = 0.f;

  auto load_chunk = [&](int kc, int buf) {
    const int k0 = kc * 64;
    const uint32_t base = sb + buf * PBUF;
#pragma unroll
    for (int it = 0; it < 4; it++) {
      const int r = gr + it * 32;
      const uint32_t sw = (uint32_t)(r * 128) + gsw;
      const size_t asrc = (size_t)(m0 + r) * DM + k0 + gc * 8;
      const size_t bsrc = (size_t)(n0 + r) * DM + k0 + gc * 8;
      cp16(base + OFF_AH + sw, Ah + asrc);
      cp16(base + OFF_AL + sw, Al + asrc);
      cp16(base + OFF_BH + sw, Bh + bsrc);
      cp16(base + OFF_BL + sw, Bl + bsrc);
    }
    cp_commit();
  };

  load_chunk(0, 0);

  for (int kc = 0; kc < 16; kc++) {
    if (kc + 1 < 16) {
      load_chunk(kc + 1, (kc + 1) & 1);
      asm volatile("cp.async.wait_group 1;" ::: "memory");
    } else {
      asm volatile("cp.async.wait_group 0;" ::: "memory");
    }
    __syncthreads();

    const uint32_t bb = sb + (kc & 1) * PBUF;
#pragma unroll
    for (int ks = 0; ks < 4; ks++) {
      const uint32_t kba = (uint32_t)(ks * 32);
      uint32_t ah[2][4], al[2][4];
#pragma unroll
      for (int mt = 0; mt < 2; mt++) {
        const uint32_t aoff = (uint32_t)((rowA0 + mt * 16) * 128) + ((kba + kadd_a) ^ xa);
        ldm4(ah[mt][0], ah[mt][1], ah[mt][2], ah[mt][3], bb + OFF_AH + aoff);
        ldm4(al[mt][0], al[mt][1], al[mt][2], al[mt][3], bb + OFF_AL + aoff);
      }
#pragma unroll
      for (int np = 0; np < 4; np++) {
        const uint32_t boff = (uint32_t)((rowB0 + np * 16) * 128) + ((kba + kadd_b) ^ xa);
        uint32_t bh[4], bl[4];
        ldm4(bh[0], bh[1], bh[2], bh[3], bb + OFF_BH + boff);
        ldm4(bl[0], bl[1], bl[2], bl[3], bb + OFF_BL + boff);
#pragma unroll
        for (int mt = 0; mt < 2; mt++) {
          mma_bf16(acc[mt][2 * np + 0], ah[mt], bh[0], bh[1]);
          mma_bf16(acc[mt][2 * np + 1], ah[mt], bh[2], bh[3]);
          mma_bf16(acc[mt][2 * np + 0], ah[mt], bl[0], bl[1]);
          mma_bf16(acc[mt][2 * np + 1], ah[mt], bl[2], bl[3]);
          mma_bf16(acc[mt][2 * np + 0], al[mt], bh[0], bh[1]);
          mma_bf16(acc[mt][2 * np + 1], al[mt], bh[2], bh[3]);
        }
      }
    }
    __syncthreads();
  }

  const int mrow = m0 + wm * 32 + (lane >> 2);
#pragma unroll
  for (int mt = 0; mt < 2; mt++) {
#pragma unroll
    for (int half = 0; half < 2; half++) {
      const int m = mrow + mt * 16 + half * 8;
#pragma unroll
      for (int nt = 0; nt < 8; nt++) {
        const int n = n0 + wn * 64 + nt * 8 + (lane & 3) * 2;
        float2 o;
        o.x = acc[mt][nt][half * 2 + 0];
        o.y = acc[mt][nt][half * 2 + 1];
        if (MODE == 0) {
          o.x += bias[n];
          o.y += bias[n + 1];
          const int b = m >> 9, t = m & 511;
          const int sec = n >> 10;
          const int h = (n >> 6) & 15;
          const int d = n & 63;
          const size_t idx = ((size_t)(b * NH + h) * TSEQ + t) * DK + d;
          if (sec == 0) {
            *(float2*)(g_Q + idx) = o;
          } else if (sec == 1) {
            *(uint32_t*)&g_Kh[idx] = pack_bf2(o.x, o.y);
            *(uint32_t*)&g_Kl[idx] = pack_bf2(bf_res(o.x), bf_res(o.y));
          } else {
            *(float2*)(g_V + idx) = o;
          }
        } else {
          if (m < RR) {
            const int h = n >> 6;
            const int d = n & 63;
            const size_t idx = ((size_t)h * RR + m) * DK + d;
            *(uint32_t*)&g_Ph[idx] = pack_bf2(o.x, o.y);
            *(uint32_t*)&g_Pl[idx] = pack_bf2(bf_res(o.x), bf_res(o.y));
          }
        }
      }
    }
  }
}

// ---------------------------------------------------------------------------
// Scores on tensor cores: per CTA (t-tile 64, s-tile 64, bh):
//   AC = QU @ K^T (64x64), BD = QV @ Pband^T (64x128), band row jb -> rel
//   relbase+jb, relbase = s0-t0+448.  out[t][s] = (AC + BD[t][s-t+63]) / 8
// K/P loaded via cp.async from pre-split bf16; Q converted in-kernel.
// BD exchange buffer aliased over operand smem (dead after mma).
// ---------------------------------------------------------------------------
#define SC_QUH 0
#define SC_QUL 8192
#define SC_QVH 16384
#define SC_QVL 24576
#define SC_KH  32768
#define SC_KL  40960
#define SC_PH  49152
#define SC_PL  65536
#define SC_SMEM 81920
#define SC_BDW 132

__global__ void __launch_bounds__(256, 2) scores_mma(
    const float* __restrict__ pu, const float* __restrict__ pv,
    float* __restrict__ wout) {
  extern __shared__ char smem[];
  const uint32_t sb = smem_u32(smem);
  float* BDs = (float*)smem;  // aliased after mma phase
  const int tid = threadIdx.x;
  const int wid = tid >> 5, lane = tid & 31;
  const int s0 = blockIdx.x * 64;
  const int t0 = blockIdx.y * 64;
  const int bh = blockIdx.z, h = bh & 15;
  const int relbase = s0 - t0 + 448;

  // ---- cp.async K tiles (64 rows x 128B, hi+lo)
  {
    const __nv_bfloat16* Kh = g_Kh + ((size_t)bh * TSEQ + s0) * DK;
    const __nv_bfloat16* Kl = g_Kl + ((size_t)bh * TSEQ + s0) * DK;
#pragma unroll
    for (int it = 0; it < 2; it++) {
      const int idx = tid + it * 256;
      const int row = idx >> 3, ch = idx & 7;
      const uint32_t sw = (uint32_t)(row * 128) + ((uint32_t)(ch * 16) ^ ((uint32_t)(row & 7) << 4));
      cp16(sb + SC_KH + sw, Kh + row * DK + ch * 8);
      cp16(sb + SC_KL + sw, Kl + row * DK + ch * 8);
    }
  }
  // ---- cp.async P band (128 rows x 128B, hi+lo), zero-fill out of range
  {
    const __nv_bfloat16* Ph = g_Ph + (size_t)h * RR * DK;
    const __nv_bfloat16* Pl = g_Pl + (size_t)h * RR * DK;
#pragma unroll
    for (int it = 0; it < 4; it++) {
      const int idx = tid + it * 256;
      const int row = idx >> 3, ch = idx & 7;
      const int r = relbase + row;
      const int rc = r < 0 ? 0 : (r >= RR ? RR - 1 : r);
      const int ok = (r >= 0 && r < RR) ? 16 : 0;
      const uint32_t sw = (uint32_t)(row * 128) + ((uint32_t)(ch * 16) ^ ((uint32_t)(row & 7) << 4));
      cp16z(sb + SC_PH + sw, Ph + (size_t)rc * DK + ch * 8, ok);
      cp16z(sb + SC_PL + sw, Pl + (size_t)rc * DK + ch * 8, ok);
    }
  }
  cp_commit();

  // ---- Q fill: fp32 + posu/posv, convert to bf16 hi/lo (overlaps cp.async)
  {
    const int frow = tid >> 4;
    const int c4 = (tid & 15) * 4;
    const uint32_t cb = (uint32_t)(c4 * 2);
    const float4 pu4 = *(const float4*)(pu + h * 64 + c4);
    const float4 pv4 = *(const float4*)(pv + h * 64 + c4);
    const float* qb = g_Q + ((size_t)bh * TSEQ + t0) * DK;
#pragma unroll
    for (int it = 0; it < 4; it++) {
      const int row = frow + it * 16;
      const float4 q = *(const float4*)(qb + (size_t)row * DK + c4);
      const uint32_t sw = (uint32_t)(row * 128) + (cb ^ ((uint32_t)(row & 7) << 4));
      float ux = q.x + pu4.x, uy = q.y + pu4.y, uz = q.z + pu4.z, uw = q.w + pu4.w;
      float vx = q.x + pv4.x, vy = q.y + pv4.y, vz = q.z + pv4.z, vw = q.w + pv4.w;
      uint2 hh, ll;
      hh.x = pack_bf2(ux, uy); hh.y = pack_bf2(uz, uw);
      ll.x = pack_bf2(bf_res(ux), bf_res(uy));
      ll.y = pack_bf2(bf_res(uz), bf_res(uw));
      *(uint2*)(smem + SC_QUH + sw) = hh;
      *(uint2*)(smem + SC_QUL + sw) = ll;
      hh.x = pack_bf2(vx, vy); hh.y = pack_bf2(vz, vw);
      ll.x = pack_bf2(bf_res(vx), bf_res(vy));
      ll.y = pack_bf2(bf_res(vz), bf_res(vw));
      *(uint2*)(smem + SC_QVH + sw) = hh;
      *(uint2*)(smem + SC_QVL + sw) = ll;
    }
  }
  asm volatile("cp.async.wait_group 0;" ::: "memory");
  __syncthreads();

  // ---- mma: 8 warps = 4 (t) x 2 (s/band)
  const int wm = wid & 3;   // 16 t-rows
  const int wn = wid >> 2;  // AC: 32 s-cols, BD: 64 band-cols
  const int l7 = lane & 7;
  const uint32_t xa = (uint32_t)(l7 << 4);
  const int rowA = wm * 16 + l7 + (((lane >> 3) & 1) << 3);
  const uint32_t kadd_a = (uint32_t)(((lane >> 4) & 1) << 4);
  const int rbB = l7 + (((lane >> 4) & 1) << 3);
  const uint32_t kadd_b = (uint32_t)(((lane >> 3) & 1) << 4);

  float ac[4][4], bd[8][4];
#pragma unroll
  for (int nt = 0; nt < 4; nt++)
#pragma unroll
    for (int i = 0; i < 4; i++) ac[nt][i] = 0.f;
#pragma unroll
  for (int nt = 0; nt < 8; nt++)
#pragma unroll
    for (int i = 0; i < 4; i++) bd[nt][i] = 0.f;

#pragma unroll
  for (int ks = 0; ks < 4; ks++) {
    const uint32_t kba = (uint32_t)(ks * 32);
    const uint32_t aoff = (uint32_t)(rowA * 128) + ((kba + kadd_a) ^ xa);
    uint32_t quh[4], qul[4], qvh[4], qvl[4];
    ldm4(quh[0], quh[1], quh[2], quh[3], sb + SC_QUH + aoff);
    ldm4(qul[0], qul[1], qul[2], qul[3], sb + SC_QUL + aoff);
    ldm4(qvh[0], qvh[1], qvh[2], qvh[3], sb + SC_QVH + aoff);
    ldm4(qvl[0], qvl[1], qvl[2], qvl[3], sb + SC_QVL + aoff);
#pragma unroll
    for (int np = 0; np < 2; np++) {
      const int rowB = wn * 32 + np * 16 + rbB;
      const uint32_t boff = (uint32_t)(rowB * 128) + ((kba + kadd_b) ^ xa);
      uint32_t kh[4], kl[4];
      ldm4(kh[0], kh[1], kh[2], kh[3], sb + SC_KH + boff);
      ldm4(kl[0], kl[1], kl[2], kl[3], sb + SC_KL + boff);
      mma_bf16(ac[2 * np + 0], quh, kh[0], kh[1]);
      mma_bf16(ac[2 * np + 1], quh, kh[2], kh[3]);
      mma_bf16(ac[2 * np + 0], quh, kl[0], kl[1]);
      mma_bf16(ac[2 * np + 1], quh, kl[2], kl[3]);
      mma_bf16(ac[2 * np + 0], qul, kh[0], kh[1]);
      mma_bf16(ac[2 * np + 1], qul, kh[2], kh[3]);
    }
#pragma unroll
    for (int np = 0; np < 4; np++) {
      const int rowB = wn * 64 + np * 16 + rbB;
      const uint32_t boff = (uint32_t)(rowB * 128) + ((kba + kadd_b) ^ xa);
      uint32_t ph[4], pl[4];
      ldm4(ph[0], ph[1], ph[2], ph[3], sb + SC_PH + boff);
      ldm4(pl[0], pl[1], pl[2], pl[3], sb + SC_PL + boff);
      mma_bf16(bd[2 * np + 0], qvh, ph[0], ph[1]);
      mma_bf16(bd[2 * np + 1], qvh, ph[2], ph[3]);
      mma_bf16(bd[2 * np + 0], qvh, pl[0], pl[1]);
      mma_bf16(bd[2 * np + 1], qvh, pl[2], pl[3]);
      mma_bf16(bd[2 * np + 0], qvl, ph[0], ph[1]);
      mma_bf16(bd[2 * np + 1], qvl, ph[2], ph[3]);
    }
  }
  __syncthreads();  // operand smem dead; safe to alias with BDs

  // ---- BD -> smem (stride 132 floats)
  const int r0w = wm * 16 + (lane >> 2);
#pragma unroll
  for (int nt = 0; nt < 8; nt++) {
    const int col = wn * 64 + nt * 8 + (lane & 3) * 2;
    *(float2*)&BDs[r0w * SC_BDW + col] = make_float2(bd[nt][0], bd[nt][1]);
    *(float2*)&BDs[(r0w + 8) * SC_BDW + col] = make_float2(bd[nt][2], bd[nt][3]);
  }
  __syncthreads();

  // ---- epilogue: out = (AC + shifted BD) / 8  (scalar BD reads: alignment)
  float* wbase = wout + ((size_t)bh * TSEQ + t0) * TSEQ + s0;
#pragma unroll
  for (int nt = 0; nt < 4; nt++) {
    const int col = wn * 32 + nt * 8 + (lane & 3) * 2;
#pragma unroll
    for (int half = 0; half < 2; half++) {
      const int row = r0w + half * 8;
      const int bdi = row * SC_BDW + col - row + 63;
      float2 o;
      o.x = (ac[nt][half * 2 + 0] + BDs[bdi]) * 0.125f;
      o.y = (ac[nt][half * 2 + 1] + BDs[bdi + 1]) * 0.125f;
      *(float2*)(wbase + (size_t)row * TSEQ + col) = o;
    }
  }
}

// ---------------------------------------------------------------------------
// Softmax over rows of 512, in place; also emits bf16 hi/lo weights.
// ---------------------------------------------------------------------------
__global__ void __launch_bounds__(256) softmax_kernel(float* __restrict__ w) {
  const int gwarp = (blockIdx.x * 256 + threadIdx.x) >> 5;
  const int lane = threadIdx.x & 31;
  const size_t rbase = (size_t)gwarp * TSEQ;
  float* row = w + rbase;
  float4 v[4];
#pragma unroll
  for (int k = 0; k < 4; k++) v[k] = *(float4*)(row + k * 128 + lane * 4);
  float m = v[0].x;
#pragma unroll
  for (int k = 0; k < 4; k++)
    m = fmaxf(m, fmaxf(fmaxf(v[k].x, v[k].y), fmaxf(v[k].z, v[k].w)));
#pragma unroll
  for (int off = 16; off > 0; off >>= 1)
    m = fmaxf(m, __shfl_xor_sync(0xffffffffu, m, off));
  float s = 0.f;
#pragma unroll
  for (int k = 0; k < 4; k++) {
    v[k].x = __expf(v[k].x - m); s += v[k].x;
    v[k].y = __expf(v[k].y - m); s += v[k].y;
    v[k].z = __expf(v[k].z - m); s += v[k].z;
    v[k].w = __expf(v[k].w - m); s += v[k].w;
  }
#pragma unroll
  for (int off = 16; off > 0; off >>= 1)
    s += __shfl_xor_sync(0xffffffffu, s, off);
  const float inv = 1.0f / s;
#pragma unroll
  for (int k = 0; k < 4; k++) {
    v[k].x *= inv; v[k].y *= inv; v[k].z *= inv; v[k].w *= inv;
    *(float4*)(row + k * 128 + lane * 4) = v[k];
    const size_t o = rbase + k * 128 + lane * 4;
    uint2 hh, ll;
    hh.x = pack_bf2(v[k].x, v[k].y); hh.y = pack_bf2(v[k].z, v[k].w);
    ll.x = pack_bf2(bf_res(v[k].x), bf_res(v[k].y));
    ll.y = pack_bf2(bf_res(v[k].z), bf_res(v[k].w));
    *(uint2*)&g_Wsh[o] = hh;
    *(uint2*)&g_Wsl[o] = ll;
  }
}

// ---------------------------------------------------------------------------
// Context GEMM: ctx[b,t,h*64+d] = sum_s W[bh,t,s] * Vt[bh,d,s]
// ---------------------------------------------------------------------------
#define CBUF 49152
#define C_WH 0
#define C_WL 16384
#define C_VH 32768
#define C_VL 40960
#define CSMEM (2 * CBUF)  // 98304

__global__ void __launch_bounds__(256, 2) ctx_mma(float* __restrict__ ctx) {
  extern __shared__ char smem[];
  const uint32_t sb = smem_u32(smem);
  const int tid = threadIdx.x;
  const int wid = tid >> 5, lane = tid & 31;
  const int t0 = blockIdx.x * 128;
  const int bh = blockIdx.y;
  const int b = bh >> 4, h = bh & 15;

  const __nv_bfloat16* Wh = g_Wsh + (size_t)bh * TSEQ * TSEQ;
  const __nv_bfloat16* Wl = g_Wsl + (size_t)bh * TSEQ * TSEQ;
  const __nv_bfloat16* Vh = g_Vth + (size_t)bh * DK * TSEQ;
  const __nv_bfloat16* Vl = g_Vtl + (size_t)bh * DK * TSEQ;

  const int gr = tid >> 3;
  const int gc = tid & 7;
  const uint32_t gsw = (uint32_t)((gc * 16) ^ ((gr & 7) << 4));

  const int wm = wid & 3;
  const int wn = wid >> 2;
  const int l7 = lane & 7;
  const uint32_t xa = (uint32_t)(l7 << 4);
  const int rowA0 = wm * 32 + l7 + (((lane >> 3) & 1) << 3);
  const uint32_t kadd_a = (uint32_t)(((lane >> 4) & 1) << 4);
  const int rowB0 = wn * 32 + l7 + (((lane >> 4) & 1) << 3);
  const uint32_t kadd_b = (uint32_t)(((lane >> 3) & 1) << 4);

  float acc[2][4][4];
#pragma unroll
  for (int mt = 0; mt < 2; mt++)
#pragma unroll
    for (int nt = 0; nt < 4; nt++)
#pragma unroll
      for (int i = 0; i < 4; i++) acc[mt][nt][i] = 0.f;

  auto load_chunk = [&](int kc, int buf) {
    const int k0 = kc * 64;
    const uint32_t base = sb + buf * CBUF;
#pragma unroll
    for (int it = 0; it < 4; it++) {
      const int r = gr + it * 32;
      const uint32_t sw = (uint32_t)(r * 128) + gsw;
      const size_t src = (size_t)(t0 + r) * TSEQ + k0 + gc * 8;
      cp16(base + C_WH + sw, Wh + src);
      cp16(base + C_WL + sw, Wl + src);
    }
#pragma unroll
    for (int it = 0; it < 2; it++) {
      const int r = gr + it * 32;
      const uint32_t sw = (uint32_t)(r * 128) + gsw;
      const size_t src = (size_t)r * TSEQ + k0 + gc * 8;
      cp16(base + C_VH + sw, Vh + src);
      cp16(base + C_VL + sw, Vl + src);
    }
    cp_commit();
  };

  load_chunk(0, 0);

  for (int kc = 0; kc < 8; kc++) {
    if (kc + 1 < 8) {
      load_chunk(kc + 1, (kc + 1) & 1);
      asm volatile("cp.async.wait_group 1;" ::: "memory");
    } else {
      asm volatile("cp.async.wait_group 0;" ::: "memory");
    }
    __syncthreads();

    const uint32_t bb = sb + (kc & 1) * CBUF;
#pragma unroll
    for (int ks = 0; ks < 4; ks++) {
      const uint32_t kba = (uint32_t)(ks * 32);
      uint32_t ah[2][4], al[2][4];
#pragma unroll
      for (int mt = 0; mt < 2; mt++) {
        const uint32_t aoff = (uint32_t)((rowA0 + mt * 16) * 128) + ((kba + kadd_a) ^ xa);
        ldm4(ah[mt][0], ah[mt][1], ah[mt][2], ah[mt][3], bb + C_WH + aoff);
        ldm4(al[mt][0], al[mt][1], al[mt][2], al[mt][3], bb + C_WL + aoff);
      }
#pragma unroll
      for (int np = 0; np < 2; np++) {
        const uint32_t boff = (uint32_t)((rowB0 + np * 16) * 128) + ((kba + kadd_b) ^ xa);
        uint32_t vh[4], vl[4];
        ldm4(vh[0], vh[1], vh[2], vh[3], bb + C_VH + boff);
        ldm4(vl[0], vl[1], vl[2], vl[3], bb + C_VL + boff);
#pragma unroll
        for (int mt = 0; mt < 2; mt++) {
          mma_bf16(acc[mt][2 * np + 0], ah[mt], vh[0], vh[1]);
          mma_bf16(acc[mt][2 * np + 1], ah[mt], vh[2], vh[3]);
          mma_bf16(acc[mt][2 * np + 0], ah[mt], vl[0], vl[1]);
          mma_bf16(acc[mt][2 * np + 1], ah[mt], vl[2], vl[3]);
          mma_bf16(acc[mt][2 * np + 0], al[mt], vh[0], vh[1]);
          mma_bf16(acc[mt][2 * np + 1], al[mt], vh[2], vh[3]);
        }
      }
    }
    __syncthreads();
  }

  const int mrow = t0 + wm * 32 + (lane >> 2);
#pragma unroll
  for (int mt = 0; mt < 2; mt++) {
#pragma unroll
    for (int half = 0; half < 2; half++) {
      const int t = mrow + mt * 16 + half * 8;
#pragma unroll
      for (int nt = 0; nt < 4; nt++) {
        const int d = wn * 32 + nt * 8 + (lane & 3) * 2;
        float2 o;
        o.x = acc[mt][nt][half * 2 + 0];
        o.y = acc[mt][nt][half * 2 + 1];
        *(float2*)(ctx + ((size_t)b * TSEQ + t) * DM + h * DK + d) = o;
      }
    }
  }
}

// ---------------------------------------------------------------------------
// Launch
// ---------------------------------------------------------------------------
extern "C" void kernel_launch(void* const* d_in, const int* in_sizes, int n_in,
                              void* d_out, int out_size) {
  const float* x     = (const float*)d_in[0];
  const float* pos   = (const float*)d_in[2];
  const float* qvk_w = (const float*)d_in[3];
  const float* qvk_b = (const float*)d_in[4];
  const float* pos_w = (const float*)d_in[5];
  const float* posu  = (const float*)d_in[6];
  const float* posv  = (const float*)d_in[7];

  float* ctx = (float*)d_out;
  float* wts = (float*)d_out + (size_t)BATCH * TSEQ * DM;

  // 0) bf16 hi/lo splits (+ transposed weights)
  split_kernel<0><<<1024, 256>>>(x, BATCH * TSEQ * DM, BATCH * TSEQ * DM);
  tsplit_kernel<0><<<dim3(D3 / 32, DM / 32), 256>>>(qvk_w, DM, D3);
  split_kernel<1><<<512, 256>>>(pos, RR * DM, 1024 * DM);
  tsplit_kernel<1><<<dim3(DM / 32, DM / 32), 256>>>(pos_w, DM, DM);

  // 1) QKV projection (Q,V f32; K bf16 hi/lo)
  cudaFuncSetAttribute(mma_gemm<0>, cudaFuncAttributeMaxDynamicSharedMemorySize,
                       GSMEM);
  cudaFuncSetAttribute(mma_gemm<1>, cudaFuncAttributeMaxDynamicSharedMemorySize,
                       GSMEM);
  mma_gemm<0><<<dim3(D3 / 128, (BATCH * TSEQ) / 128), 256, GSMEM>>>(qvk_b);

  // 2) pos projection -> P bf16 hi/lo
  mma_gemm<1><<<dim3(DM / 128, 1024 / 128), 256, GSMEM>>>(nullptr);

  // 2b) V -> V^T bf16 hi/lo
  vtsplit_kernel<<<dim3(TSEQ / 64, BATCH * NH), 256>>>();

  // 3) scores (AC + shifted BD, scaled) -> weights region
  cudaFuncSetAttribute(scores_mma, cudaFuncAttributeMaxDynamicSharedMemorySize,
                       SC_SMEM);
  scores_mma<<<dim3(TSEQ / 64, TSEQ / 64, BATCH * NH), 256, SC_SMEM>>>(
      posu, posv, wts);

  // 4) softmax in place (+ bf16 hi/lo weight emission)
  softmax_kernel<<<(BATCH * NH * TSEQ) / 8, 256>>>(wts);

  // 5) context = W @ V on tensor cores
  cudaFuncSetAttribute(ctx_mma, cudaFuncAttributeMaxDynamicSharedMemorySize,
                       CSMEM);
  ctx_mma<<<dim3(TSEQ / 128, BATCH * NH), 256, CSMEM>>>(ctx);
}

// round 8
// speedup vs baseline: 1.4528x; 1.0245x over previous
#include <cuda_runtime.h>
#include <cuda_bf16.h>
#include <cstdint>

#define BATCH 16
#define TSEQ 512
#define NH 16
#define DK 64
#define DM 1024
#define D3 3072
#define RR 1023  // 2T-1

// ---------------------------------------------------------------------------
// Scratch (allocation-free: device globals)
// ---------------------------------------------------------------------------
__device__ float g_Q[BATCH*NH*TSEQ*DK];
__device__ float g_V[BATCH*NH*TSEQ*DK];

// K and P stored directly as bf16 hi/lo (written by projection epilogues)
__device__ __nv_bfloat16 g_Kh[BATCH*NH*TSEQ*DK];
__device__ __nv_bfloat16 g_Kl[BATCH*NH*TSEQ*DK];
__device__ __nv_bfloat16 g_Ph[NH*RR*DK];
__device__ __nv_bfloat16 g_Pl[NH*RR*DK];

// bf16 hi/lo split operands for projection GEMMs
__device__ __nv_bfloat16 g_Ah[BATCH*TSEQ*DM];
__device__ __nv_bfloat16 g_Al[BATCH*TSEQ*DM];
__device__ __nv_bfloat16 g_Wh[D3*DM];      // qvk_w transposed: [3072][1024]
__device__ __nv_bfloat16 g_Wl[D3*DM];
__device__ __nv_bfloat16 g_pAh[1024*DM];   // pos padded to 1024 rows
__device__ __nv_bfloat16 g_pAl[1024*DM];
__device__ __nv_bfloat16 g_pWh[DM*DM];     // pos_w transposed
__device__ __nv_bfloat16 g_pWl[DM*DM];

// V^T bf16 hi/lo [bh][d][s]
__device__ __nv_bfloat16 g_Vth[(size_t)BATCH*NH*DK*TSEQ];
__device__ __nv_bfloat16 g_Vtl[(size_t)BATCH*NH*DK*TSEQ];

// ---------------------------------------------------------------------------
// helpers
// ---------------------------------------------------------------------------
__device__ __forceinline__ uint32_t smem_u32(const void* p) {
  uint32_t a;
  asm("{ .reg .u64 t; cvta.to.shared.u64 t, %1; cvt.u32.u64 %0, t; }" : "=r"(a) : "l"(p));
  return a;
}
__device__ __forceinline__ void cp16(uint32_t dst, const void* src) {
  asm volatile("cp.async.cg.shared.global [%0], [%1], 16;" :: "r"(dst), "l"(src));
}
__device__ __forceinline__ void cp16z(uint32_t dst, const void* src, int nbytes) {
  asm volatile("cp.async.cg.shared.global [%0], [%1], 16, %2;"
               :: "r"(dst), "l"(src), "r"(nbytes));
}
__device__ __forceinline__ void cp_commit() {
  asm volatile("cp.async.commit_group;" ::: "memory");
}
__device__ __forceinline__ void ldm4(uint32_t& r0, uint32_t& r1, uint32_t& r2,
                                     uint32_t& r3, uint32_t a) {
  asm volatile("ldmatrix.sync.aligned.m8n8.x4.shared.b16 {%0,%1,%2,%3}, [%4];"
               : "=r"(r0), "=r"(r1), "=r"(r2), "=r"(r3) : "r"(a));
}
__device__ __forceinline__ void mma_bf16(float* c, const uint32_t* a,
                                         uint32_t b0, uint32_t b1) {
  asm volatile(
      "mma.sync.aligned.m16n8k16.row.col.f32.bf16.bf16.f32 "
      "{%0,%1,%2,%3}, {%4,%5,%6,%7}, {%8,%9}, {%0,%1,%2,%3};"
      : "+f"(c[0]), "+f"(c[1]), "+f"(c[2]), "+f"(c[3])
      : "r"(a[0]), "r"(a[1]), "r"(a[2]), "r"(a[3]), "r"(b0), "r"(b1));
}
__device__ __forceinline__ uint32_t pack_bf2(float a, float b) {
  __nv_bfloat16 ha = __float2bfloat16(a), hb = __float2bfloat16(b);
  uint16_t ua = *(uint16_t*)&ha, ub = *(uint16_t*)&hb;
  return (uint32_t)ua | ((uint32_t)ub << 16);
}
__device__ __forceinline__ float bf_res(float v) {
  return v - __bfloat162float(__float2bfloat16(v));
}

// ---------------------------------------------------------------------------
// Merged prep: all 4 split/tsplit jobs in ONE launch.
//  bid [0,2048): split x   [2048,5120): tsplit qvk_w
//  [5120,5376): split pos  [5376,6400): tsplit pos_w
// ---------------------------------------------------------------------------
__global__ void __launch_bounds__(256) prep_kernel(
    const float* __restrict__ x, const float* __restrict__ qvk_w,
    const float* __restrict__ pos, const float* __restrict__ pos_w) {
  __shared__ float t[32][33];
  const int bid = blockIdx.x;
  const int tid = threadIdx.x;
  if (bid < 2048) {  // split x
    const int n = BATCH * TSEQ * DM;
    for (int i = bid * 256 + tid; i < n; i += 2048 * 256) {
      float v = x[i];
      __nv_bfloat16 h = __float2bfloat16(v);
      g_Ah[i] = h;
      g_Al[i] = __float2bfloat16(v - __bfloat162float(h));
    }
  } else if (bid < 5120) {  // tsplit qvk_w: R=1024 C=3072
    const int r = bid - 2048;
    const int c0 = (r % 96) * 32, r0 = (r / 96) * 32;
    const int tx = tid & 31, ty = tid >> 5;
#pragma unroll
    for (int i = 0; i < 4; i++)
      t[ty + i * 8][tx] = qvk_w[(size_t)(r0 + ty + i * 8) * D3 + c0 + tx];
    __syncthreads();
#pragma unroll
    for (int i = 0; i < 4; i++) {
      float v = t[tx][ty + i * 8];
      __nv_bfloat16 h = __float2bfloat16(v);
      size_t o = (size_t)(c0 + ty + i * 8) * DM + r0 + tx;
      g_Wh[o] = h;
      g_Wl[o] = __float2bfloat16(v - __bfloat162float(h));
    }
  } else if (bid < 5376) {  // split pos (pad to 1024 rows)
    const int r = bid - 5120;
    const int n = RR * DM, ntot = 1024 * DM;
    for (int i = r * 256 + tid; i < ntot; i += 256 * 256) {
      float v = (i < n) ? pos[i] : 0.f;
      __nv_bfloat16 h = __float2bfloat16(v);
      g_pAh[i] = h;
      g_pAl[i] = __float2bfloat16(v - __bfloat162float(h));
    }
  } else {  // tsplit pos_w: R=1024 C=1024
    const int r = bid - 5376;
    const int c0 = (r % 32) * 32, r0 = (r / 32) * 32;
    const int tx = tid & 31, ty = tid >> 5;
#pragma unroll
    for (int i = 0; i < 4; i++)
      t[ty + i * 8][tx] = pos_w[(size_t)(r0 + ty + i * 8) * DM + c0 + tx];
    __syncthreads();
#pragma unroll
    for (int i = 0; i < 4; i++) {
      float v = t[tx][ty + i * 8];
      __nv_bfloat16 h = __float2bfloat16(v);
      size_t o = (size_t)(c0 + ty + i * 8) * DM + r0 + tx;
      g_pWh[o] = h;
      g_pWl[o] = __float2bfloat16(v - __bfloat162float(h));
    }
  }
}

// ---------------------------------------------------------------------------
// Merged projection GEMMs (QKV + pos) in one launch.
//  bid < 1536: QKV tile;  bid >= 1536: pos tile.
// C = A[M,1024] @ B^T, 3-pass bf16 split, tile 128x128, K-chunk 64.
// ---------------------------------------------------------------------------
#define PBUF 65536
#define OFF_AH 0
#define OFF_AL 16384
#define OFF_BH 32768
#define OFF_BL 49152
#define GSMEM (2 * PBUF)  // 131072

__global__ void __launch_bounds__(256, 1) mma_gemm_all(const float* __restrict__ bias) {
  extern __shared__ char smem[];
  const uint32_t sb = smem_u32(smem);
  const int tid = threadIdx.x;
  const int wid = tid >> 5, lane = tid & 31;
  const int bid = blockIdx.x;
  const bool qkv = bid < 1536;
  int n0, m0;
  const __nv_bfloat16 *Ah, *Al, *Bh, *Bl;
  if (qkv) {
    n0 = (bid % 24) * 128; m0 = (bid / 24) * 128;
    Ah = g_Ah; Al = g_Al; Bh = g_Wh; Bl = g_Wl;
  } else {
    const int r = bid - 1536;
    n0 = (r % 8) * 128; m0 = (r / 8) * 128;
    Ah = g_pAh; Al = g_pAl; Bh = g_pWh; Bl = g_pWl;
  }
  const int wm = wid & 3;
  const int wn = wid >> 2;

  const int gr = tid >> 3;
  const int gc = tid & 7;
  const uint32_t gsw = (uint32_t)((gc * 16) ^ ((gr & 7) << 4));

  const int l7 = lane & 7;
  const uint32_t xa = (uint32_t)(l7 << 4);
  const int rowA0 = wm * 32 + l7 + (((lane >> 3) & 1) << 3);
  const uint32_t kadd_a = (uint32_t)(((lane >> 4) & 1) << 4);
  const int rowB0 = wn * 64 + l7 + (((lane >> 4) & 1) << 3);
  const uint32_t kadd_b = (uint32_t)(((lane >> 3) & 1) << 4);

  float acc[2][8][4];
#pragma unroll
  for (int mt = 0; mt < 2; mt++)
#pragma unroll
    for (int nt = 0; nt < 8; nt++)
#pragma unroll
      for (int i = 0; i < 4; i++) acc[mt][nt][i] = 0.f;

  auto load_chunk = [&](int kc, int buf) {
    const int k0 = kc * 64;
    const uint32_t base = sb + buf * PBUF;
#pragma unroll
    for (int it = 0; it < 4; it++) {
      const int r = gr + it * 32;
      const uint32_t sw = (uint32_t)(r * 128) + gsw;
      const size_t asrc = (size_t)(m0 + r) * DM + k0 + gc * 8;
      const size_t bsrc = (size_t)(n0 + r) * DM + k0 + gc * 8;
      cp16(base + OFF_AH + sw, Ah + asrc);
      cp16(base + OFF_AL + sw, Al + asrc);
      cp16(base + OFF_BH + sw, Bh + bsrc);
      cp16(base + OFF_BL + sw, Bl + bsrc);
    }
    cp_commit();
  };

  load_chunk(0, 0);

  for (int kc = 0; kc < 16; kc++) {
    if (kc + 1 < 16) {
      load_chunk(kc + 1, (kc + 1) & 1);
      asm volatile("cp.async.wait_group 1;" ::: "memory");
    } else {
      asm volatile("cp.async.wait_group 0;" ::: "memory");
    }
    __syncthreads();

    const uint32_t bb = sb + (kc & 1) * PBUF;
#pragma unroll
    for (int ks = 0; ks < 4; ks++) {
      const uint32_t kba = (uint32_t)(ks * 32);
      uint32_t ah[2][4], al[2][4];
#pragma unroll
      for (int mt = 0; mt < 2; mt++) {
        const uint32_t aoff = (uint32_t)((rowA0 + mt * 16) * 128) + ((kba + kadd_a) ^ xa);
        ldm4(ah[mt][0], ah[mt][1], ah[mt][2], ah[mt][3], bb + OFF_AH + aoff);
        ldm4(al[mt][0], al[mt][1], al[mt][2], al[mt][3], bb + OFF_AL + aoff);
      }
#pragma unroll
      for (int np = 0; np < 4; np++) {
        const uint32_t boff = (uint32_t)((rowB0 + np * 16) * 128) + ((kba + kadd_b) ^ xa);
        uint32_t bh[4], bl[4];
        ldm4(bh[0], bh[1], bh[2], bh[3], bb + OFF_BH + boff);
        ldm4(bl[0], bl[1], bl[2], bl[3], bb + OFF_BL + boff);
#pragma unroll
        for (int mt = 0; mt < 2; mt++) {
          mma_bf16(acc[mt][2 * np + 0], ah[mt], bh[0], bh[1]);
          mma_bf16(acc[mt][2 * np + 1], ah[mt], bh[2], bh[3]);
          mma_bf16(acc[mt][2 * np + 0], ah[mt], bl[0], bl[1]);
          mma_bf16(acc[mt][2 * np + 1], ah[mt], bl[2], bl[3]);
          mma_bf16(acc[mt][2 * np + 0], al[mt], bh[0], bh[1]);
          mma_bf16(acc[mt][2 * np + 1], al[mt], bh[2], bh[3]);
        }
      }
    }
    __syncthreads();
  }

  const int mrow = m0 + wm * 32 + (lane >> 2);
#pragma unroll
  for (int mt = 0; mt < 2; mt++) {
#pragma unroll
    for (int half = 0; half < 2; half++) {
      const int m = mrow + mt * 16 + half * 8;
#pragma unroll
      for (int nt = 0; nt < 8; nt++) {
        const int n = n0 + wn * 64 + nt * 8 + (lane & 3) * 2;
        float2 o;
        o.x = acc[mt][nt][half * 2 + 0];
        o.y = acc[mt][nt][half * 2 + 1];
        if (qkv) {
          o.x += bias[n];
          o.y += bias[n + 1];
          const int b = m >> 9, t = m & 511;
          const int sec = n >> 10;
          const int h = (n >> 6) & 15;
          const int d = n & 63;
          const size_t idx = ((size_t)(b * NH + h) * TSEQ + t) * DK + d;
          if (sec == 0) {
            *(float2*)(g_Q + idx) = o;
          } else if (sec == 1) {
            *(uint32_t*)&g_Kh[idx] = pack_bf2(o.x, o.y);
            *(uint32_t*)&g_Kl[idx] = pack_bf2(bf_res(o.x), bf_res(o.y));
          } else {
            *(float2*)(g_V + idx) = o;
          }
        } else {
          if (m < RR) {
            const int h = n >> 6;
            const int d = n & 63;
            const size_t idx = ((size_t)h * RR + m) * DK + d;
            *(uint32_t*)&g_Ph[idx] = pack_bf2(o.x, o.y);
            *(uint32_t*)&g_Pl[idx] = pack_bf2(bf_res(o.x), bf_res(o.y));
          }
        }
      }
    }
  }
}

// ---------------------------------------------------------------------------
// Scores (+ merged vtsplit tail): grid (8, 8, 288).
//  z < 256: scores tile (t 64, s 64, bh=z)
//  z >= 256: vtsplit job (V f32 -> V^T bf16 hi/lo)
// ---------------------------------------------------------------------------
#define SC_QUH 0
#define SC_QUL 8192
#define SC_QVH 16384
#define SC_QVL 24576
#define SC_KH  32768
#define SC_KL  40960
#define SC_PH  49152
#define SC_PL  65536
#define SC_SMEM 81920
#define SC_BDW 132

__global__ void __launch_bounds__(256, 2) scores_mma(
    const float* __restrict__ pu, const float* __restrict__ pv,
    float* __restrict__ wout) {
  extern __shared__ char smem[];
  const uint32_t sb = smem_u32(smem);
  const int tid = threadIdx.x;

  if (blockIdx.z >= 256) {
    // ---- vtsplit job
    float (*t)[65] = (float(*)[65])smem;
    const int job = (blockIdx.z - 256) * 64 + blockIdx.y * 8 + blockIdx.x;
    const int vbh = job >> 3;
    const int vs0 = (job & 7) * 64;
    const float* vbase = g_V + (size_t)vbh * TSEQ * DK;
    for (int i = tid; i < 4096; i += 256) {
      const int sl = i >> 6, d = i & 63;
      t[sl][d] = vbase[(size_t)(vs0 + sl) * DK + d];
    }
    __syncthreads();
    for (int i = tid; i < 2048; i += 256) {
      const int d = i >> 5, sl = (i & 31) * 2;
      const float v0 = t[sl][d], v1 = t[sl + 1][d];
      const size_t o = ((size_t)vbh * DK + d) * TSEQ + vs0 + sl;
      *(uint32_t*)&g_Vth[o] = pack_bf2(v0, v1);
      *(uint32_t*)&g_Vtl[o] = pack_bf2(bf_res(v0), bf_res(v1));
    }
    return;
  }

  float* BDs = (float*)smem;  // aliased after mma phase
  const int wid = tid >> 5, lane = tid & 31;
  const int s0 = blockIdx.x * 64;
  const int t0 = blockIdx.y * 64;
  const int bh = blockIdx.z, h = bh & 15;
  const int relbase = s0 - t0 + 448;

  // ---- cp.async K tiles (64 rows x 128B, hi+lo)
  {
    const __nv_bfloat16* Kh = g_Kh + ((size_t)bh * TSEQ + s0) * DK;
    const __nv_bfloat16* Kl = g_Kl + ((size_t)bh * TSEQ + s0) * DK;
#pragma unroll
    for (int it = 0; it < 2; it++) {
      const int idx = tid + it * 256;
      const int row = idx >> 3, ch = idx & 7;
      const uint32_t sw = (uint32_t)(row * 128) + ((uint32_t)(ch * 16) ^ ((uint32_t)(row & 7) << 4));
      cp16(sb + SC_KH + sw, Kh + row * DK + ch * 8);
      cp16(sb + SC_KL + sw, Kl + row * DK + ch * 8);
    }
  }
  // ---- cp.async P band (128 rows x 128B, hi+lo), zero-fill out of range
  {
    const __nv_bfloat16* Ph = g_Ph + (size_t)h * RR * DK;
    const __nv_bfloat16* Pl = g_Pl + (size_t)h * RR * DK;
#pragma unroll
    for (int it = 0; it < 4; it++) {
      const int idx = tid + it * 256;
      const int row = idx >> 3, ch = idx & 7;
      const int r = relbase + row;
      const int rc = r < 0 ? 0 : (r >= RR ? RR - 1 : r);
      const int ok = (r >= 0 && r < RR) ? 16 : 0;
      const uint32_t sw = (uint32_t)(row * 128) + ((uint32_t)(ch * 16) ^ ((uint32_t)(row & 7) << 4));
      cp16z(sb + SC_PH + sw, Ph + (size_t)rc * DK + ch * 8, ok);
      cp16z(sb + SC_PL + sw, Pl + (size_t)rc * DK + ch * 8, ok);
    }
  }
  cp_commit();

  // ---- Q fill: fp32 + posu/posv, convert to bf16 hi/lo (overlaps cp.async)
  {
    const int frow = tid >> 4;
    const int c4 = (tid & 15) * 4;
    const uint32_t cb = (uint32_t)(c4 * 2);
    const float4 pu4 = *(const float4*)(pu + h * 64 + c4);
    const float4 pv4 = *(const float4*)(pv + h * 64 + c4);
    const float* qb = g_Q + ((size_t)bh * TSEQ + t0) * DK;
#pragma unroll
    for (int it = 0; it < 4; it++) {
      const int row = frow + it * 16;
      const float4 q = *(const float4*)(qb + (size_t)row * DK + c4);
      const uint32_t sw = (uint32_t)(row * 128) + (cb ^ ((uint32_t)(row & 7) << 4));
      float ux = q.x + pu4.x, uy = q.y + pu4.y, uz = q.z + pu4.z, uw = q.w + pu4.w;
      float vx = q.x + pv4.x, vy = q.y + pv4.y, vz = q.z + pv4.z, vw = q.w + pv4.w;
      uint2 hh, ll;
      hh.x = pack_bf2(ux, uy); hh.y = pack_bf2(uz, uw);
      ll.x = pack_bf2(bf_res(ux), bf_res(uy));
      ll.y = pack_bf2(bf_res(uz), bf_res(uw));
      *(uint2*)(smem + SC_QUH + sw) = hh;
      *(uint2*)(smem + SC_QUL + sw) = ll;
      hh.x = pack_bf2(vx, vy); hh.y = pack_bf2(vz, vw);
      ll.x = pack_bf2(bf_res(vx), bf_res(vy));
      ll.y = pack_bf2(bf_res(vz), bf_res(vw));
      *(uint2*)(smem + SC_QVH + sw) = hh;
      *(uint2*)(smem + SC_QVL + sw) = ll;
    }
  }
  asm volatile("cp.async.wait_group 0;" ::: "memory");
  __syncthreads();

  // ---- mma: 8 warps = 4 (t) x 2 (s/band)
  const int wm = wid & 3;
  const int wn = wid >> 2;
  const int l7 = lane & 7;
  const uint32_t xa = (uint32_t)(l7 << 4);
  const int rowA = wm * 16 + l7 + (((lane >> 3) & 1) << 3);
  const uint32_t kadd_a = (uint32_t)(((lane >> 4) & 1) << 4);
  const int rbB = l7 + (((lane >> 4) & 1) << 3);
  const uint32_t kadd_b = (uint32_t)(((lane >> 3) & 1) << 4);

  float ac[4][4], bd[8][4];
#pragma unroll
  for (int nt = 0; nt < 4; nt++)
#pragma unroll
    for (int i = 0; i < 4; i++) ac[nt][i] = 0.f;
#pragma unroll
  for (int nt = 0; nt < 8; nt++)
#pragma unroll
    for (int i = 0; i < 4; i++) bd[nt][i] = 0.f;

#pragma unroll
  for (int ks = 0; ks < 4; ks++) {
    const uint32_t kba = (uint32_t)(ks * 32);
    const uint32_t aoff = (uint32_t)(rowA * 128) + ((kba + kadd_a) ^ xa);
    uint32_t quh[4], qul[4], qvh[4], qvl[4];
    ldm4(quh[0], quh[1], quh[2], quh[3], sb + SC_QUH + aoff);
    ldm4(qul[0], qul[1], qul[2], qul[3], sb + SC_QUL + aoff);
    ldm4(qvh[0], qvh[1], qvh[2], qvh[3], sb + SC_QVH + aoff);
    ldm4(qvl[0], qvl[1], qvl[2], qvl[3], sb + SC_QVL + aoff);
#pragma unroll
    for (int np = 0; np < 2; np++) {
      const int rowB = wn * 32 + np * 16 + rbB;
      const uint32_t boff = (uint32_t)(rowB * 128) + ((kba + kadd_b) ^ xa);
      uint32_t kh[4], kl[4];
      ldm4(kh[0], kh[1], kh[2], kh[3], sb + SC_KH + boff);
      ldm4(kl[0], kl[1], kl[2], kl[3], sb + SC_KL + boff);
      mma_bf16(ac[2 * np + 0], quh, kh[0], kh[1]);
      mma_bf16(ac[2 * np + 1], quh, kh[2], kh[3]);
      mma_bf16(ac[2 * np + 0], quh, kl[0], kl[1]);
      mma_bf16(ac[2 * np + 1], quh, kl[2], kl[3]);
      mma_bf16(ac[2 * np + 0], qul, kh[0], kh[1]);
      mma_bf16(ac[2 * np + 1], qul, kh[2], kh[3]);
    }
#pragma unroll
    for (int np = 0; np < 4; np++) {
      const int rowB = wn * 64 + np * 16 + rbB;
      const uint32_t boff = (uint32_t)(rowB * 128) + ((kba + kadd_b) ^ xa);
      uint32_t ph[4], pl[4];
      ldm4(ph[0], ph[1], ph[2], ph[3], sb + SC_PH + boff);
      ldm4(pl[0], pl[1], pl[2], pl[3], sb + SC_PL + boff);
      mma_bf16(bd[2 * np + 0], qvh, ph[0], ph[1]);
      mma_bf16(bd[2 * np + 1], qvh, ph[2], ph[3]);
      mma_bf16(bd[2 * np + 0], qvh, pl[0], pl[1]);
      mma_bf16(bd[2 * np + 1], qvh, pl[2], pl[3]);
      mma_bf16(bd[2 * np + 0], qvl, ph[0], ph[1]);
      mma_bf16(bd[2 * np + 1], qvl, ph[2], ph[3]);
    }
  }
  __syncthreads();  // operand smem dead; safe to alias with BDs

  // ---- BD -> smem (stride 132 floats)
  const int r0w = wm * 16 + (lane >> 2);
#pragma unroll
  for (int nt = 0; nt < 8; nt++) {
    const int col = wn * 64 + nt * 8 + (lane & 3) * 2;
    *(float2*)&BDs[r0w * SC_BDW + col] = make_float2(bd[nt][0], bd[nt][1]);
    *(float2*)&BDs[(r0w + 8) * SC_BDW + col] = make_float2(bd[nt][2], bd[nt][3]);
  }
  __syncthreads();

  // ---- epilogue: out = (AC + shifted BD) / 8
  float* wbase = wout + ((size_t)bh * TSEQ + t0) * TSEQ + s0;
#pragma unroll
  for (int nt = 0; nt < 4; nt++) {
    const int col = wn * 32 + nt * 8 + (lane & 3) * 2;
#pragma unroll
    for (int half = 0; half < 2; half++) {
      const int row = r0w + half * 8;
      const int bdi = row * SC_BDW + col - row + 63;
      float2 o;
      o.x = (ac[nt][half * 2 + 0] + BDs[bdi]) * 0.125f;
      o.y = (ac[nt][half * 2 + 1] + BDs[bdi + 1]) * 0.125f;
      *(float2*)(wbase + (size_t)row * TSEQ + col) = o;
    }
  }
}

// ---------------------------------------------------------------------------
// Softmax over rows of 512, in place (f32 only). One warp per row.
// ---------------------------------------------------------------------------
__global__ void __launch_bounds__(256) softmax_kernel(float* __restrict__ w) {
  const int gwarp = (blockIdx.x * 256 + threadIdx.x) >> 5;
  const int lane = threadIdx.x & 31;
  float* row = w + (size_t)gwarp * TSEQ;
  float4 v[4];
#pragma unroll
  for (int k = 0; k < 4; k++) v[k] = *(float4*)(row + k * 128 + lane * 4);
  float m = v[0].x;
#pragma unroll
  for (int k = 0; k < 4; k++)
    m = fmaxf(m, fmaxf(fmaxf(v[k].x, v[k].y), fmaxf(v[k].z, v[k].w)));
#pragma unroll
  for (int off = 16; off > 0; off >>= 1)
    m = fmaxf(m, __shfl_xor_sync(0xffffffffu, m, off));
  float s = 0.f;
#pragma unroll
  for (int k = 0; k < 4; k++) {
    v[k].x = __expf(v[k].x - m); s += v[k].x;
    v[k].y = __expf(v[k].y - m); s += v[k].y;
    v[k].z = __expf(v[k].z - m); s += v[k].z;
    v[k].w = __expf(v[k].w - m); s += v[k].w;
  }
#pragma unroll
  for (int off = 16; off > 0; off >>= 1)
    s += __shfl_xor_sync(0xffffffffu, s, off);
  const float inv = 1.0f / s;
#pragma unroll
  for (int k = 0; k < 4; k++) {
    v[k].x *= inv; v[k].y *= inv; v[k].z *= inv; v[k].w *= inv;
    *(float4*)(row + k * 128 + lane * 4) = v[k];
  }
}

// ---------------------------------------------------------------------------
// Context GEMM: ctx[b,t,h*64+d] = sum_s W[bh,t,s] * Vt[bh,d,s]
// W read as f32 from the weights output and converted in-kernel to bf16 hi/lo.
// Tile 128t x 64d per bh; s chunks of 64; V double-buffered; 96KB smem, 2/SM.
// ---------------------------------------------------------------------------
#define CT_WF 0        // 128 x 64 f32 staging (linear, 256B rows), 32KB
#define CT_WH 32768    // converted W hi (swizzled), 16KB
#define CT_WL 49152    // converted W lo, 16KB
#define CT_V  65536    // V buffers: +buf*16384; hi at +0 (8KB), lo at +8192
#define CT_SMEM 98304

__global__ void __launch_bounds__(256, 2) ctx_mma(
    const float* __restrict__ wts, float* __restrict__ ctx) {
  extern __shared__ char smem[];
  const uint32_t sb = smem_u32(smem);
  const int tid = threadIdx.x;
  const int wid = tid >> 5, lane = tid & 31;
  const int t0 = blockIdx.x * 128;
  const int bh = blockIdx.y;
  const int b = bh >> 4, h = bh & 15;

  const float* Wf = wts + ((size_t)bh * TSEQ + t0) * TSEQ;
  const __nv_bfloat16* Vh = g_Vth + (size_t)bh * DK * TSEQ;
  const __nv_bfloat16* Vl = g_Vtl + (size_t)bh * DK * TSEQ;

  const int wm = wid & 3;
  const int wn = wid >> 2;
  const int l7 = lane & 7;
  const uint32_t xa = (uint32_t)(l7 << 4);
  const int rowA0 = wm * 32 + l7 + (((lane >> 3) & 1) << 3);
  const uint32_t kadd_a = (uint32_t)(((lane >> 4) & 1) << 4);
  const int rowB0 = wn * 32 + l7 + (((lane >> 4) & 1) << 3);
  const uint32_t kadd_b = (uint32_t)(((lane >> 3) & 1) << 4);

  float acc[2][4][4];
#pragma unroll
  for (int mt = 0; mt < 2; mt++)
#pragma unroll
    for (int nt = 0; nt < 4; nt++)
#pragma unroll
      for (int i = 0; i < 4; i++) acc[mt][nt][i] = 0.f;

  // W f32 staging load: 128 rows x 256B = 2048 x 16B
  auto load_wf = [&](int kc) {
    const int k0 = kc * 64;
#pragma unroll
    for (int it = 0; it < 8; it++) {
      const int idx = tid + it * 256;
      const int row = idx >> 4, seg = idx & 15;
      cp16(sb + CT_WF + (uint32_t)(row * 256 + seg * 16),
           Wf + (size_t)row * TSEQ + k0 + seg * 4);
    }
  };
  // V bf16 load: 64 rows x 128B, hi+lo, swizzled
  auto load_v = [&](int kc, int buf) {
    const int k0 = kc * 64;
    const uint32_t vb = sb + CT_V + (uint32_t)(buf * 16384);
#pragma unroll
    for (int it = 0; it < 2; it++) {
      const int idx = tid + it * 256;
      const int row = idx >> 3, ch = idx & 7;
      const uint32_t sw = (uint32_t)(row * 128) + ((uint32_t)(ch * 16) ^ ((uint32_t)(row & 7) << 4));
      cp16(vb + sw, Vh + (size_t)row * TSEQ + k0 + ch * 8);
      cp16(vb + 8192 + sw, Vl + (size_t)row * TSEQ + k0 + ch * 8);
    }
  };

  load_wf(0);
  load_v(0, 0);
  cp_commit();

  for (int kc = 0; kc < 8; kc++) {
    asm volatile("cp.async.wait_group 0;" ::: "memory");
    __syncthreads();  // staging ready + previous mma done with WH/WL

    // convert W f32 -> bf16 hi/lo swizzled (2048 float4)
#pragma unroll
    for (int it = 0; it < 8; it++) {
      const int idx = tid + it * 256;
      const int r = idx >> 4, q = idx & 15;
      const float4 wv = *(const float4*)(smem + CT_WF + r * 256 + q * 16);
      const uint32_t sw = (uint32_t)(r * 128) + ((uint32_t)(q * 8) ^ ((uint32_t)(r & 7) << 4));
      uint2 hh, ll;
      hh.x = pack_bf2(wv.x, wv.y); hh.y = pack_bf2(wv.z, wv.w);
      ll.x = pack_bf2(bf_res(wv.x), bf_res(wv.y));
      ll.y = pack_bf2(bf_res(wv.z), bf_res(wv.w));
      *(uint2*)(smem + CT_WH + sw) = hh;
      *(uint2*)(smem + CT_WL + sw) = ll;
    }
    __syncthreads();

    // prefetch next chunk (overlaps mma below)
    if (kc + 1 < 8) {
      load_wf(kc + 1);
      load_v(kc + 1, (kc + 1) & 1);
      cp_commit();
    }

    const uint32_t vb = sb + CT_V + (uint32_t)((kc & 1) * 16384);
#pragma unroll
    for (int ks = 0; ks < 4; ks++) {
      const uint32_t kba = (uint32_t)(ks * 32);
      uint32_t ah[2][4], al[2][4];
#pragma unroll
      for (int mt = 0; mt < 2; mt++) {
        const uint32_t aoff = (uint32_t)((rowA0 + mt * 16) * 128) + ((kba + kadd_a) ^ xa);
        ldm4(ah[mt][0], ah[mt][1], ah[mt][2], ah[mt][3], sb + CT_WH + aoff);
        ldm4(al[mt][0], al[mt][1], al[mt][2], al[mt][3], sb + CT_WL + aoff);
      }
#pragma unroll
      for (int np = 0; np < 2; np++) {
        const uint32_t boff = (uint32_t)((rowB0 + np * 16) * 128) + ((kba + kadd_b) ^ xa);
        uint32_t vhh[4], vll[4];
        ldm4(vhh[0], vhh[1], vhh[2], vhh[3], vb + boff);
        ldm4(vll[0], vll[1], vll[2], vll[3], vb + 8192 + boff);
#pragma unroll
        for (int mt = 0; mt < 2; mt++) {
          mma_bf16(acc[mt][2 * np + 0], ah[mt], vhh[0], vhh[1]);
          mma_bf16(acc[mt][2 * np + 1], ah[mt], vhh[2], vhh[3]);
          mma_bf16(acc[mt][2 * np + 0], ah[mt], vll[0], vll[1]);
          mma_bf16(acc[mt][2 * np + 1], ah[mt], vll[2], vll[3]);
          mma_bf16(acc[mt][2 * np + 0], al[mt], vhh[0], vhh[1]);
          mma_bf16(acc[mt][2 * np + 1], al[mt], vhh[2], vhh[3]);
        }
      }
    }
  }

  const int mrow = t0 + wm * 32 + (lane >> 2);
#pragma unroll
  for (int mt = 0; mt < 2; mt++) {
#pragma unroll
    for (int half = 0; half < 2; half++) {
      const int t = mrow + mt * 16 + half * 8;
#pragma unroll
      for (int nt = 0; nt < 4; nt++) {
        const int d = wn * 32 + nt * 8 + (lane & 3) * 2;
        float2 o;
        o.x = acc[mt][nt][half * 2 + 0];
        o.y = acc[mt][nt][half * 2 + 1];
        *(float2*)(ctx + ((size_t)b * TSEQ + t) * DM + h * DK + d) = o;
      }
    }
  }
}

// ---------------------------------------------------------------------------
// Launch
// ---------------------------------------------------------------------------
extern "C" void kernel_launch(void* const* d_in, const int* in_sizes, int n_in,
                              void* d_out, int out_size) {
  const float* x     = (const float*)d_in[0];
  const float* pos   = (const float*)d_in[2];
  const float* qvk_w = (const float*)d_in[3];
  const float* qvk_b = (const float*)d_in[4];
  const float* pos_w = (const float*)d_in[5];
  const float* posu  = (const float*)d_in[6];
  const float* posv  = (const float*)d_in[7];

  float* ctx = (float*)d_out;
  float* wts = (float*)d_out + (size_t)BATCH * TSEQ * DM;

  // 0) merged prep (all bf16 hi/lo splits)
  prep_kernel<<<6400, 256>>>(x, qvk_w, pos, pos_w);

  // 1) merged projection GEMMs (QKV 1536 tiles + pos 64 tiles)
  cudaFuncSetAttribute(mma_gemm_all, cudaFuncAttributeMaxDynamicSharedMemorySize,
                       GSMEM);
  mma_gemm_all<<<1600, 256, GSMEM>>>(qvk_b);

  // 2) scores (+ merged vtsplit tail) -> weights region
  cudaFuncSetAttribute(scores_mma, cudaFuncAttributeMaxDynamicSharedMemorySize,
                       SC_SMEM);
  scores_mma<<<dim3(8, 8, 288), 256, SC_SMEM>>>(posu, posv, wts);

  // 3) softmax in place (f32 only)
  softmax_kernel<<<(BATCH * NH * TSEQ) / 8, 256>>>(wts);

  // 4) context = W @ V (W f32 converted in-kernel)
  cudaFuncSetAttribute(ctx_mma, cudaFuncAttributeMaxDynamicSharedMemorySize,
                       CT_SMEM);
  ctx_mma<<<dim3(TSEQ / 128, BATCH * NH), 256, CT_SMEM>>>(wts, ctx);
}

// round 9
// speedup vs baseline: 1.5299x; 1.0531x over previous
#include <cuda_runtime.h>
#include <cuda_bf16.h>
#include <cstdint>

#define BATCH 16
#define TSEQ 512
#define NH 16
#define DK 64
#define DM 1024
#define D3 3072
#define RR 1023  // 2T-1

// ---------------------------------------------------------------------------
// Scratch (allocation-free: device globals)
// ---------------------------------------------------------------------------
__device__ float g_Q[BATCH*NH*TSEQ*DK];
__device__ float g_V[BATCH*NH*TSEQ*DK];

// K and P stored directly as bf16 hi/lo (written by projection epilogues)
__device__ __nv_bfloat16 g_Kh[BATCH*NH*TSEQ*DK];
__device__ __nv_bfloat16 g_Kl[BATCH*NH*TSEQ*DK];
__device__ __nv_bfloat16 g_Ph[NH*RR*DK];
__device__ __nv_bfloat16 g_Pl[NH*RR*DK];

// bf16 hi/lo split operands for projection GEMMs
__device__ __nv_bfloat16 g_Ah[BATCH*TSEQ*DM];
__device__ __nv_bfloat16 g_Al[BATCH*TSEQ*DM];
__device__ __nv_bfloat16 g_Wh[D3*DM];      // qvk_w transposed: [3072][1024]
__device__ __nv_bfloat16 g_Wl[D3*DM];
__device__ __nv_bfloat16 g_pAh[1024*DM];   // pos padded to 1024 rows
__device__ __nv_bfloat16 g_pAl[1024*DM];
__device__ __nv_bfloat16 g_pWh[DM*DM];     // pos_w transposed
__device__ __nv_bfloat16 g_pWl[DM*DM];

// V^T bf16 hi/lo [bh][d][s]
__device__ __nv_bfloat16 g_Vth[(size_t)BATCH*NH*DK*TSEQ];
__device__ __nv_bfloat16 g_Vtl[(size_t)BATCH*NH*DK*TSEQ];

// ---------------------------------------------------------------------------
// helpers
// ---------------------------------------------------------------------------
__device__ __forceinline__ uint32_t smem_u32(const void* p) {
  uint32_t a;
  asm("{ .reg .u64 t; cvta.to.shared.u64 t, %1; cvt.u32.u64 %0, t; }" : "=r"(a) : "l"(p));
  return a;
}
__device__ __forceinline__ void cp16(uint32_t dst, const void* src) {
  asm volatile("cp.async.cg.shared.global [%0], [%1], 16;" :: "r"(dst), "l"(src));
}
__device__ __forceinline__ void cp16z(uint32_t dst, const void* src, int nbytes) {
  asm volatile("cp.async.cg.shared.global [%0], [%1], 16, %2;"
               :: "r"(dst), "l"(src), "r"(nbytes));
}
__device__ __forceinline__ void cp_commit() {
  asm volatile("cp.async.commit_group;" ::: "memory");
}
__device__ __forceinline__ void ldm4(uint32_t& r0, uint32_t& r1, uint32_t& r2,
                                     uint32_t& r3, uint32_t a) {
  asm volatile("ldmatrix.sync.aligned.m8n8.x4.shared.b16 {%0,%1,%2,%3}, [%4];"
               : "=r"(r0), "=r"(r1), "=r"(r2), "=r"(r3) : "r"(a));
}
__device__ __forceinline__ void mma_bf16(float* c, const uint32_t* a,
                                         uint32_t b0, uint32_t b1) {
  asm volatile(
      "mma.sync.aligned.m16n8k16.row.col.f32.bf16.bf16.f32 "
      "{%0,%1,%2,%3}, {%4,%5,%6,%7}, {%8,%9}, {%0,%1,%2,%3};"
      : "+f"(c[0]), "+f"(c[1]), "+f"(c[2]), "+f"(c[3])
      : "r"(a[0]), "r"(a[1]), "r"(a[2]), "r"(a[3]), "r"(b0), "r"(b1));
}
__device__ __forceinline__ uint32_t pack_bf2(float a, float b) {
  __nv_bfloat16 ha = __float2bfloat16(a), hb = __float2bfloat16(b);
  uint16_t ua = *(uint16_t*)&ha, ub = *(uint16_t*)&hb;
  return (uint32_t)ua | ((uint32_t)ub << 16);
}
__device__ __forceinline__ float bf_res(float v) {
  return v - __bfloat162float(__float2bfloat16(v));
}

// ---------------------------------------------------------------------------
// Merged prep: all 4 split/tsplit jobs in ONE launch.
// ---------------------------------------------------------------------------
__global__ void __launch_bounds__(256) prep_kernel(
    const float* __restrict__ x, const float* __restrict__ qvk_w,
    const float* __restrict__ pos, const float* __restrict__ pos_w) {
  __shared__ float t[32][33];
  const int bid = blockIdx.x;
  const int tid = threadIdx.x;
  if (bid < 2048) {  // split x
    const int n = BATCH * TSEQ * DM;
    for (int i = bid * 256 + tid; i < n; i += 2048 * 256) {
      float v = x[i];
      __nv_bfloat16 h = __float2bfloat16(v);
      g_Ah[i] = h;
      g_Al[i] = __float2bfloat16(v - __bfloat162float(h));
    }
  } else if (bid < 5120) {  // tsplit qvk_w: R=1024 C=3072
    const int r = bid - 2048;
    const int c0 = (r % 96) * 32, r0 = (r / 96) * 32;
    const int tx = tid & 31, ty = tid >> 5;
#pragma unroll
    for (int i = 0; i < 4; i++)
      t[ty + i * 8][tx] = qvk_w[(size_t)(r0 + ty + i * 8) * D3 + c0 + tx];
    __syncthreads();
#pragma unroll
    for (int i = 0; i < 4; i++) {
      float v = t[tx][ty + i * 8];
      __nv_bfloat16 h = __float2bfloat16(v);
      size_t o = (size_t)(c0 + ty + i * 8) * DM + r0 + tx;
      g_Wh[o] = h;
      g_Wl[o] = __float2bfloat16(v - __bfloat162float(h));
    }
  } else if (bid < 5376) {  // split pos (pad to 1024 rows)
    const int r = bid - 5120;
    const int n = RR * DM, ntot = 1024 * DM;
    for (int i = r * 256 + tid; i < ntot; i += 256 * 256) {
      float v = (i < n) ? pos[i] : 0.f;
      __nv_bfloat16 h = __float2bfloat16(v);
      g_pAh[i] = h;
      g_pAl[i] = __float2bfloat16(v - __bfloat162float(h));
    }
  } else {  // tsplit pos_w: R=1024 C=1024
    const int r = bid - 5376;
    const int c0 = (r % 32) * 32, r0 = (r / 32) * 32;
    const int tx = tid & 31, ty = tid >> 5;
#pragma unroll
    for (int i = 0; i < 4; i++)
      t[ty + i * 8][tx] = pos_w[(size_t)(r0 + ty + i * 8) * DM + c0 + tx];
    __syncthreads();
#pragma unroll
    for (int i = 0; i < 4; i++) {
      float v = t[tx][ty + i * 8];
      __nv_bfloat16 h = __float2bfloat16(v);
      size_t o = (size_t)(c0 + ty + i * 8) * DM + r0 + tx;
      g_pWh[o] = h;
      g_pWl[o] = __float2bfloat16(v - __bfloat162float(h));
    }
  }
}

// ---------------------------------------------------------------------------
// Merged projection GEMMs (QKV + pos) in one launch.
// ---------------------------------------------------------------------------
#define PBUF 65536
#define OFF_AH 0
#define OFF_AL 16384
#define OFF_BH 32768
#define OFF_BL 49152
#define GSMEM (2 * PBUF)  // 131072

__global__ void __launch_bounds__(256, 1) mma_gemm_all(const float* __restrict__ bias) {
  extern __shared__ char smem[];
  const uint32_t sb = smem_u32(smem);
  const int tid = threadIdx.x;
  const int wid = tid >> 5, lane = tid & 31;
  const int bid = blockIdx.x;
  const bool qkv = bid < 1536;
  int n0, m0;
  const __nv_bfloat16 *Ah, *Al, *Bh, *Bl;
  if (qkv) {
    n0 = (bid % 24) * 128; m0 = (bid / 24) * 128;
    Ah = g_Ah; Al = g_Al; Bh = g_Wh; Bl = g_Wl;
  } else {
    const int r = bid - 1536;
    n0 = (r % 8) * 128; m0 = (r / 8) * 128;
    Ah = g_pAh; Al = g_pAl; Bh = g_pWh; Bl = g_pWl;
  }
  const int wm = wid & 3;
  const int wn = wid >> 2;

  const int gr = tid >> 3;
  const int gc = tid & 7;
  const uint32_t gsw = (uint32_t)((gc * 16) ^ ((gr & 7) << 4));

  const int l7 = lane & 7;
  const uint32_t xa = (uint32_t)(l7 << 4);
  const int rowA0 = wm * 32 + l7 + (((lane >> 3) & 1) << 3);
  const uint32_t kadd_a = (uint32_t)(((lane >> 4) & 1) << 4);
  const int rowB0 = wn * 64 + l7 + (((lane >> 4) & 1) << 3);
  const uint32_t kadd_b = (uint32_t)(((lane >> 3) & 1) << 4);

  float acc[2][8][4];
#pragma unroll
  for (int mt = 0; mt < 2; mt++)
#pragma unroll
    for (int nt = 0; nt < 8; nt++)
#pragma unroll
      for (int i = 0; i < 4; i++) acc[mt][nt][i] = 0.f;

  auto load_chunk = [&](int kc, int buf) {
    const int k0 = kc * 64;
    const uint32_t base = sb + buf * PBUF;
#pragma unroll
    for (int it = 0; it < 4; it++) {
      const int r = gr + it * 32;
      const uint32_t sw = (uint32_t)(r * 128) + gsw;
      const size_t asrc = (size_t)(m0 + r) * DM + k0 + gc * 8;
      const size_t bsrc = (size_t)(n0 + r) * DM + k0 + gc * 8;
      cp16(base + OFF_AH + sw, Ah + asrc);
      cp16(base + OFF_AL + sw, Al + asrc);
      cp16(base + OFF_BH + sw, Bh + bsrc);
      cp16(base + OFF_BL + sw, Bl + bsrc);
    }
    cp_commit();
  };

  load_chunk(0, 0);

  for (int kc = 0; kc < 16; kc++) {
    if (kc + 1 < 16) {
      load_chunk(kc + 1, (kc + 1) & 1);
      asm volatile("cp.async.wait_group 1;" ::: "memory");
    } else {
      asm volatile("cp.async.wait_group 0;" ::: "memory");
    }
    __syncthreads();

    const uint32_t bb = sb + (kc & 1) * PBUF;
#pragma unroll
    for (int ks = 0; ks < 4; ks++) {
      const uint32_t kba = (uint32_t)(ks * 32);
      uint32_t ah[2][4], al[2][4];
#pragma unroll
      for (int mt = 0; mt < 2; mt++) {
        const uint32_t aoff = (uint32_t)((rowA0 + mt * 16) * 128) + ((kba + kadd_a) ^ xa);
        ldm4(ah[mt][0], ah[mt][1], ah[mt][2], ah[mt][3], bb + OFF_AH + aoff);
        ldm4(al[mt][0], al[mt][1], al[mt][2], al[mt][3], bb + OFF_AL + aoff);
      }
#pragma unroll
      for (int np = 0; np < 4; np++) {
        const uint32_t boff = (uint32_t)((rowB0 + np * 16) * 128) + ((kba + kadd_b) ^ xa);
        uint32_t bh[4], bl[4];
        ldm4(bh[0], bh[1], bh[2], bh[3], bb + OFF_BH + boff);
        ldm4(bl[0], bl[1], bl[2], bl[3], bb + OFF_BL + boff);
#pragma unroll
        for (int mt = 0; mt < 2; mt++) {
          mma_bf16(acc[mt][2 * np + 0], ah[mt], bh[0], bh[1]);
          mma_bf16(acc[mt][2 * np + 1], ah[mt], bh[2], bh[3]);
          mma_bf16(acc[mt][2 * np + 0], ah[mt], bl[0], bl[1]);
          mma_bf16(acc[mt][2 * np + 1], ah[mt], bl[2], bl[3]);
          mma_bf16(acc[mt][2 * np + 0], al[mt], bh[0], bh[1]);
          mma_bf16(acc[mt][2 * np + 1], al[mt], bh[2], bh[3]);
        }
      }
    }
    __syncthreads();
  }

  const int mrow = m0 + wm * 32 + (lane >> 2);
#pragma unroll
  for (int mt = 0; mt < 2; mt++) {
#pragma unroll
    for (int half = 0; half < 2; half++) {
      const int m = mrow + mt * 16 + half * 8;
#pragma unroll
      for (int nt = 0; nt < 8; nt++) {
        const int n = n0 + wn * 64 + nt * 8 + (lane & 3) * 2;
        float2 o;
        o.x = acc[mt][nt][half * 2 + 0];
        o.y = acc[mt][nt][half * 2 + 1];
        if (qkv) {
          o.x += bias[n];
          o.y += bias[n + 1];
          const int b = m >> 9, t = m & 511;
          const int sec = n >> 10;
          const int h = (n >> 6) & 15;
          const int d = n & 63;
          const size_t idx = ((size_t)(b * NH + h) * TSEQ + t) * DK + d;
          if (sec == 0) {
            *(float2*)(g_Q + idx) = o;
          } else if (sec == 1) {
            *(uint32_t*)&g_Kh[idx] = pack_bf2(o.x, o.y);
            *(uint32_t*)&g_Kl[idx] = pack_bf2(bf_res(o.x), bf_res(o.y));
          } else {
            *(float2*)(g_V + idx) = o;
          }
        } else {
          if (m < RR) {
            const int h = n >> 6;
            const int d = n & 63;
            const size_t idx = ((size_t)h * RR + m) * DK + d;
            *(uint32_t*)&g_Ph[idx] = pack_bf2(o.x, o.y);
            *(uint32_t*)&g_Pl[idx] = pack_bf2(bf_res(o.x), bf_res(o.y));
          }
        }
      }
    }
  }
}

// ---------------------------------------------------------------------------
// Scores (+ merged vtsplit tail): grid (4, 8, 320).
//  z < 256: scores tile (t 64, s 128, bh=z)
//  z >= 256: vtsplit job (V f32 -> V^T bf16 hi/lo); job = (z-256)*32 + y*4 + x
// AC = QU @ K^T (64x128), BD = QV @ Pband^T (64x192); band row jb -> rel
// relbase+jb, relbase = s0-t0+448.  out[t][s] = (AC + BD[t][s-t+63]) / 8
// 112KB smem -> 2 CTAs/SM.
// ---------------------------------------------------------------------------
#define SC_QUH 0
#define SC_QUL 8192
#define SC_QVH 16384
#define SC_QVL 24576
#define SC_KH  32768
#define SC_KL  49152
#define SC_PH  65536
#define SC_PL  90112
#define SC_SMEM 114688
#define SC_BDW 196

__global__ void __launch_bounds__(256, 2) scores_mma(
    const float* __restrict__ pu, const float* __restrict__ pv,
    float* __restrict__ wout) {
  extern __shared__ char smem[];
  const uint32_t sb = smem_u32(smem);
  const int tid = threadIdx.x;

  if (blockIdx.z >= 256) {
    // ---- vtsplit job
    float (*t)[65] = (float(*)[65])smem;
    const int job = (blockIdx.z - 256) * 32 + blockIdx.y * 4 + blockIdx.x;
    const int vbh = job >> 3;
    const int vs0 = (job & 7) * 64;
    const float* vbase = g_V + (size_t)vbh * TSEQ * DK;
    for (int i = tid; i < 4096; i += 256) {
      const int sl = i >> 6, d = i & 63;
      t[sl][d] = vbase[(size_t)(vs0 + sl) * DK + d];
    }
    __syncthreads();
    for (int i = tid; i < 2048; i += 256) {
      const int d = i >> 5, sl = (i & 31) * 2;
      const float v0 = t[sl][d], v1 = t[sl + 1][d];
      const size_t o = ((size_t)vbh * DK + d) * TSEQ + vs0 + sl;
      *(uint32_t*)&g_Vth[o] = pack_bf2(v0, v1);
      *(uint32_t*)&g_Vtl[o] = pack_bf2(bf_res(v0), bf_res(v1));
    }
    return;
  }

  float* BDs = (float*)smem;  // aliased after mma phase
  const int wid = tid >> 5, lane = tid & 31;
  const int s0 = blockIdx.x * 128;
  const int t0 = blockIdx.y * 64;
  const int bh = blockIdx.z, h = bh & 15;
  const int relbase = s0 - t0 + 448;

  // ---- cp.async K tiles (128 rows x 128B, hi+lo)
  {
    const __nv_bfloat16* Kh = g_Kh + ((size_t)bh * TSEQ + s0) * DK;
    const __nv_bfloat16* Kl = g_Kl + ((size_t)bh * TSEQ + s0) * DK;
#pragma unroll
    for (int it = 0; it < 4; it++) {
      const int idx = tid + it * 256;
      const int row = idx >> 3, ch = idx & 7;
      const uint32_t sw = (uint32_t)(row * 128) + ((uint32_t)(ch * 16) ^ ((uint32_t)(row & 7) << 4));
      cp16(sb + SC_KH + sw, Kh + row * DK + ch * 8);
      cp16(sb + SC_KL + sw, Kl + row * DK + ch * 8);
    }
  }
  // ---- cp.async P band (192 rows x 128B, hi+lo), zero-fill out of range
  {
    const __nv_bfloat16* Ph = g_Ph + (size_t)h * RR * DK;
    const __nv_bfloat16* Pl = g_Pl + (size_t)h * RR * DK;
#pragma unroll
    for (int it = 0; it < 6; it++) {
      const int idx = tid + it * 256;
      const int row = idx >> 3, ch = idx & 7;
      const int r = relbase + row;
      const int rc = r < 0 ? 0 : (r >= RR ? RR - 1 : r);
      const int ok = (r >= 0 && r < RR) ? 16 : 0;
      const uint32_t sw = (uint32_t)(row * 128) + ((uint32_t)(ch * 16) ^ ((uint32_t)(row & 7) << 4));
      cp16z(sb + SC_PH + sw, Ph + (size_t)rc * DK + ch * 8, ok);
      cp16z(sb + SC_PL + sw, Pl + (size_t)rc * DK + ch * 8, ok);
    }
  }
  cp_commit();

  // ---- Q fill: fp32 + posu/posv, convert to bf16 hi/lo (overlaps cp.async)
  {
    const int frow = tid >> 4;
    const int c4 = (tid & 15) * 4;
    const uint32_t cb = (uint32_t)(c4 * 2);
    const float4 pu4 = *(const float4*)(pu + h * 64 + c4);
    const float4 pv4 = *(const float4*)(pv + h * 64 + c4);
    const float* qb = g_Q + ((size_t)bh * TSEQ + t0) * DK;
#pragma unroll
    for (int it = 0; it < 4; it++) {
      const int row = frow + it * 16;
      const float4 q = *(const float4*)(qb + (size_t)row * DK + c4);
      const uint32_t sw = (uint32_t)(row * 128) + (cb ^ ((uint32_t)(row & 7) << 4));
      float ux = q.x + pu4.x, uy = q.y + pu4.y, uz = q.z + pu4.z, uw = q.w + pu4.w;
      float vx = q.x + pv4.x, vy = q.y + pv4.y, vz = q.z + pv4.z, vw = q.w + pv4.w;
      uint2 hh, ll;
      hh.x = pack_bf2(ux, uy); hh.y = pack_bf2(uz, uw);
      ll.x = pack_bf2(bf_res(ux), bf_res(uy));
      ll.y = pack_bf2(bf_res(uz), bf_res(uw));
      *(uint2*)(smem + SC_QUH + sw) = hh;
      *(uint2*)(smem + SC_QUL + sw) = ll;
      hh.x = pack_bf2(vx, vy); hh.y = pack_bf2(vz, vw);
      ll.x = pack_bf2(bf_res(vx), bf_res(vy));
      ll.y = pack_bf2(bf_res(vz), bf_res(vw));
      *(uint2*)(smem + SC_QVH + sw) = hh;
      *(uint2*)(smem + SC_QVL + sw) = ll;
    }
  }
  asm volatile("cp.async.wait_group 0;" ::: "memory");
  __syncthreads();

  // ---- mma: 8 warps = 4 (t) x 2 (s/band)
  const int wm = wid & 3;   // 16 t-rows
  const int wn = wid >> 2;  // AC: 64 s-cols, BD: 96 band-cols
  const int l7 = lane & 7;
  const uint32_t xa = (uint32_t)(l7 << 4);
  const int rowA = wm * 16 + l7 + (((lane >> 3) & 1) << 3);
  const uint32_t kadd_a = (uint32_t)(((lane >> 4) & 1) << 4);
  const int rbB = l7 + (((lane >> 4) & 1) << 3);
  const uint32_t kadd_b = (uint32_t)(((lane >> 3) & 1) << 4);

  float ac[8][4], bd[12][4];
#pragma unroll
  for (int nt = 0; nt < 8; nt++)
#pragma unroll
    for (int i = 0; i < 4; i++) ac[nt][i] = 0.f;
#pragma unroll
  for (int nt = 0; nt < 12; nt++)
#pragma unroll
    for (int i = 0; i < 4; i++) bd[nt][i] = 0.f;

#pragma unroll
  for (int ks = 0; ks < 4; ks++) {
    const uint32_t kba = (uint32_t)(ks * 32);
    const uint32_t aoff = (uint32_t)(rowA * 128) + ((kba + kadd_a) ^ xa);
    uint32_t quh[4], qul[4], qvh[4], qvl[4];
    ldm4(quh[0], quh[1], quh[2], quh[3], sb + SC_QUH + aoff);
    ldm4(qul[0], qul[1], qul[2], qul[3], sb + SC_QUL + aoff);
    ldm4(qvh[0], qvh[1], qvh[2], qvh[3], sb + SC_QVH + aoff);
    ldm4(qvl[0], qvl[1], qvl[2], qvl[3], sb + SC_QVL + aoff);
#pragma unroll
    for (int np = 0; np < 4; np++) {
      const int rowB = wn * 64 + np * 16 + rbB;
      const uint32_t boff = (uint32_t)(rowB * 128) + ((kba + kadd_b) ^ xa);
      uint32_t kh[4], kl[4];
      ldm4(kh[0], kh[1], kh[2], kh[3], sb + SC_KH + boff);
      ldm4(kl[0], kl[1], kl[2], kl[3], sb + SC_KL + boff);
      mma_bf16(ac[2 * np + 0], quh, kh[0], kh[1]);
      mma_bf16(ac[2 * np + 1], quh, kh[2], kh[3]);
      mma_bf16(ac[2 * np + 0], quh, kl[0], kl[1]);
      mma_bf16(ac[2 * np + 1], quh, kl[2], kl[3]);
      mma_bf16(ac[2 * np + 0], qul, kh[0], kh[1]);
      mma_bf16(ac[2 * np + 1], qul, kh[2], kh[3]);
    }
#pragma unroll
    for (int np = 0; np < 6; np++) {
      const int rowB = wn * 96 + np * 16 + rbB;
      const uint32_t boff = (uint32_t)(rowB * 128) + ((kba + kadd_b) ^ xa);
      uint32_t ph[4], pl[4];
      ldm4(ph[0], ph[1], ph[2], ph[3], sb + SC_PH + boff);
      ldm4(pl[0], pl[1], pl[2], pl[3], sb + SC_PL + boff);
      mma_bf16(bd[2 * np + 0], qvh, ph[0], ph[1]);
      mma_bf16(bd[2 * np + 1], qvh, ph[2], ph[3]);
      mma_bf16(bd[2 * np + 0], qvh, pl[0], pl[1]);
      mma_bf16(bd[2 * np + 1], qvh, pl[2], pl[3]);
      mma_bf16(bd[2 * np + 0], qvl, ph[0], ph[1]);
      mma_bf16(bd[2 * np + 1], qvl, ph[2], ph[3]);
    }
  }
  __syncthreads();  // operand smem dead; safe to alias with BDs

  // ---- BD -> smem (stride 196 floats)
  const int r0w = wm * 16 + (lane >> 2);
#pragma unroll
  for (int nt = 0; nt < 12; nt++) {
    const int col = wn * 96 + nt * 8 + (lane & 3) * 2;
    *(float2*)&BDs[r0w * SC_BDW + col] = make_float2(bd[nt][0], bd[nt][1]);
    *(float2*)&BDs[(r0w + 8) * SC_BDW + col] = make_float2(bd[nt][2], bd[nt][3]);
  }
  __syncthreads();

  // ---- epilogue: out = (AC + shifted BD) / 8
  float* wbase = wout + ((size_t)bh * TSEQ + t0) * TSEQ + s0;
#pragma unroll
  for (int nt = 0; nt < 8; nt++) {
    const int col = wn * 64 + nt * 8 + (lane & 3) * 2;
#pragma unroll
    for (int half = 0; half < 2; half++) {
      const int row = r0w + half * 8;
      const int bdi = row * SC_BDW + col - row + 63;
      float2 o;
      o.x = (ac[nt][half * 2 + 0] + BDs[bdi]) * 0.125f;
      o.y = (ac[nt][half * 2 + 1] + BDs[bdi + 1]) * 0.125f;
      *(float2*)(wbase + (size_t)row * TSEQ + col) = o;
    }
  }
}

// ---------------------------------------------------------------------------
// Softmax over rows of 512, in place (f32 only). One warp per row.
// ---------------------------------------------------------------------------
__global__ void __launch_bounds__(256) softmax_kernel(float* __restrict__ w) {
  const int gwarp = (blockIdx.x * 256 + threadIdx.x) >> 5;
  const int lane = threadIdx.x & 31;
  float* row = w + (size_t)gwarp * TSEQ;
  float4 v[4];
#pragma unroll
  for (int k = 0; k < 4; k++) v[k] = *(float4*)(row + k * 128 + lane * 4);
  float m = v[0].x;
#pragma unroll
  for (int k = 0; k < 4; k++)
    m = fmaxf(m, fmaxf(fmaxf(v[k].x, v[k].y), fmaxf(v[k].z, v[k].w)));
#pragma unroll
  for (int off = 16; off > 0; off >>= 1)
    m = fmaxf(m, __shfl_xor_sync(0xffffffffu, m, off));
  float s = 0.f;
#pragma unroll
  for (int k = 0; k < 4; k++) {
    v[k].x = __expf(v[k].x - m); s += v[k].x;
    v[k].y = __expf(v[k].y - m); s += v[k].y;
    v[k].z = __expf(v[k].z - m); s += v[k].z;
    v[k].w = __expf(v[k].w - m); s += v[k].w;
  }
#pragma unroll
  for (int off = 16; off > 0; off >>= 1)
    s += __shfl_xor_sync(0xffffffffu, s, off);
  const float inv = 1.0f / s;
#pragma unroll
  for (int k = 0; k < 4; k++) {
    v[k].x *= inv; v[k].y *= inv; v[k].z *= inv; v[k].w *= inv;
    *(float4*)(row + k * 128 + lane * 4) = v[k];
  }
}

// ---------------------------------------------------------------------------
// Context GEMM: ctx[b,t,h*64+d] = sum_s W[bh,t,s] * Vt[bh,d,s]
// W read as f32 and converted in-kernel to bf16 hi/lo.
// ---------------------------------------------------------------------------
#define CT_WF 0        // 128 x 64 f32 staging (linear, 256B rows), 32KB
#define CT_WH 32768    // converted W hi (swizzled), 16KB
#define CT_WL 49152    // converted W lo, 16KB
#define CT_V  65536    // V buffers: +buf*16384; hi at +0 (8KB), lo at +8192
#define CT_SMEM 98304

__global__ void __launch_bounds__(256, 2) ctx_mma(
    const float* __restrict__ wts, float* __restrict__ ctx) {
  extern __shared__ char smem[];
  const uint32_t sb = smem_u32(smem);
  const int tid = threadIdx.x;
  const int wid = tid >> 5, lane = tid & 31;
  const int t0 = blockIdx.x * 128;
  const int bh = blockIdx.y;
  const int b = bh >> 4, h = bh & 15;

  const float* Wf = wts + ((size_t)bh * TSEQ + t0) * TSEQ;
  const __nv_bfloat16* Vh = g_Vth + (size_t)bh * DK * TSEQ;
  const __nv_bfloat16* Vl = g_Vtl + (size_t)bh * DK * TSEQ;

  const int wm = wid & 3;
  const int wn = wid >> 2;
  const int l7 = lane & 7;
  const uint32_t xa = (uint32_t)(l7 << 4);
  const int rowA0 = wm * 32 + l7 + (((lane >> 3) & 1) << 3);
  const uint32_t kadd_a = (uint32_t)(((lane >> 4) & 1) << 4);
  const int rowB0 = wn * 32 + l7 + (((lane >> 4) & 1) << 3);
  const uint32_t kadd_b = (uint32_t)(((lane >> 3) & 1) << 4);

  float acc[2][4][4];
#pragma unroll
  for (int mt = 0; mt < 2; mt++)
#pragma unroll
    for (int nt = 0; nt < 4; nt++)
#pragma unroll
      for (int i = 0; i < 4; i++) acc[mt][nt][i] = 0.f;

  auto load_wf = [&](int kc) {
    const int k0 = kc * 64;
#pragma unroll
    for (int it = 0; it < 8; it++) {
      const int idx = tid + it * 256;
      const int row = idx >> 4, seg = idx & 15;
      cp16(sb + CT_WF + (uint32_t)(row * 256 + seg * 16),
           Wf + (size_t)row * TSEQ + k0 + seg * 4);
    }
  };
  auto load_v = [&](int kc, int buf) {
    const int k0 = kc * 64;
    const uint32_t vb = sb + CT_V + (uint32_t)(buf * 16384);
#pragma unroll
    for (int it = 0; it < 2; it++) {
      const int idx = tid + it * 256;
      const int row = idx >> 3, ch = idx & 7;
      const uint32_t sw = (uint32_t)(row * 128) + ((uint32_t)(ch * 16) ^ ((uint32_t)(row & 7) << 4));
      cp16(vb + sw, Vh + (size_t)row * TSEQ + k0 + ch * 8);
      cp16(vb + 8192 + sw, Vl + (size_t)row * TSEQ + k0 + ch * 8);
    }
  };

  load_wf(0);
  load_v(0, 0);
  cp_commit();

  for (int kc = 0; kc < 8; kc++) {
    asm volatile("cp.async.wait_group 0;" ::: "memory");
    __syncthreads();

#pragma unroll
    for (int it = 0; it < 8; it++) {
      const int idx = tid + it * 256;
      const int r = idx >> 4, q = idx & 15;
      const float4 wv = *(const float4*)(smem + CT_WF + r * 256 + q * 16);
      const uint32_t sw = (uint32_t)(r * 128) + ((uint32_t)(q * 8) ^ ((uint32_t)(r & 7) << 4));
      uint2 hh, ll;
      hh.x = pack_bf2(wv.x, wv.y); hh.y = pack_bf2(wv.z, wv.w);
      ll.x = pack_bf2(bf_res(wv.x), bf_res(wv.y));
      ll.y = pack_bf2(bf_res(wv.z), bf_res(wv.w));
      *(uint2*)(smem + CT_WH + sw) = hh;
      *(uint2*)(smem + CT_WL + sw) = ll;
    }
    __syncthreads();

    if (kc + 1 < 8) {
      load_wf(kc + 1);
      load_v(kc + 1, (kc + 1) & 1);
      cp_commit();
    }

    const uint32_t vb = sb + CT_V + (uint32_t)((kc & 1) * 16384);
#pragma unroll
    for (int ks = 0; ks < 4; ks++) {
      const uint32_t kba = (uint32_t)(ks * 32);
      uint32_t ah[2][4], al[2][4];
#pragma unroll
      for (int mt = 0; mt < 2; mt++) {
        const uint32_t aoff = (uint32_t)((rowA0 + mt * 16) * 128) + ((kba + kadd_a) ^ xa);
        ldm4(ah[mt][0], ah[mt][1], ah[mt][2], ah[mt][3], sb + CT_WH + aoff);
        ldm4(al[mt][0], al[mt][1], al[mt][2], al[mt][3], sb + CT_WL + aoff);
      }
#pragma unroll
      for (int np = 0; np < 2; np++) {
        const uint32_t boff = (uint32_t)((rowB0 + np * 16) * 128) + ((kba + kadd_b) ^ xa);
        uint32_t vhh[4], vll[4];
        ldm4(vhh[0], vhh[1], vhh[2], vhh[3], vb + boff);
        ldm4(vll[0], vll[1], vll[2], vll[3], vb + 8192 + boff);
#pragma unroll
        for (int mt = 0; mt < 2; mt++) {
          mma_bf16(acc[mt][2 * np + 0], ah[mt], vhh[0], vhh[1]);
          mma_bf16(acc[mt][2 * np + 1], ah[mt], vhh[2], vhh[3]);
          mma_bf16(acc[mt][2 * np + 0], ah[mt], vll[0], vll[1]);
          mma_bf16(acc[mt][2 * np + 1], ah[mt], vll[2], vll[3]);
          mma_bf16(acc[mt][2 * np + 0], al[mt], vhh[0], vhh[1]);
          mma_bf16(acc[mt][2 * np + 1], al[mt], vhh[2], vhh[3]);
        }
      }
    }
  }

  const int mrow = t0 + wm * 32 + (lane >> 2);
#pragma unroll
  for (int mt = 0; mt < 2; mt++) {
#pragma unroll
    for (int half = 0; half < 2; half++) {
      const int t = mrow + mt * 16 + half * 8;
#pragma unroll
      for (int nt = 0; nt < 4; nt++) {
        const int d = wn * 32 + nt * 8 + (lane & 3) * 2;
        float2 o;
        o.x = acc[mt][nt][half * 2 + 0];
        o.y = acc[mt][nt][half * 2 + 1];
        *(float2*)(ctx + ((size_t)b * TSEQ + t) * DM + h * DK + d) = o;
      }
    }
  }
}

// ---------------------------------------------------------------------------
// Launch
// ---------------------------------------------------------------------------
extern "C" void kernel_launch(void* const* d_in, const int* in_sizes, int n_in,
                              void* d_out, int out_size) {
  const float* x     = (const float*)d_in[0];
  const float* pos   = (const float*)d_in[2];
  const float* qvk_w = (const float*)d_in[3];
  const float* qvk_b = (const float*)d_in[4];
  const float* pos_w = (const float*)d_in[5];
  const float* posu  = (const float*)d_in[6];
  const float* posv  = (const float*)d_in[7];

  float* ctx = (float*)d_out;
  float* wts = (float*)d_out + (size_t)BATCH * TSEQ * DM;

  // 0) merged prep (all bf16 hi/lo splits)
  prep_kernel<<<6400, 256>>>(x, qvk_w, pos, pos_w);

  // 1) merged projection GEMMs (QKV 1536 tiles + pos 64 tiles)
  cudaFuncSetAttribute(mma_gemm_all, cudaFuncAttributeMaxDynamicSharedMemorySize,
                       GSMEM);
  mma_gemm_all<<<1600, 256, GSMEM>>>(qvk_b);

  // 2) scores (+ merged vtsplit tail) -> weights region
  cudaFuncSetAttribute(scores_mma, cudaFuncAttributeMaxDynamicSharedMemorySize,
                       SC_SMEM);
  scores_mma<<<dim3(4, 8, 320), 256, SC_SMEM>>>(posu, posv, wts);

  // 3) softmax in place (f32 only)
  softmax_kernel<<<(BATCH * NH * TSEQ) / 8, 256>>>(wts);

  // 4) context = W @ V (W f32 converted in-kernel)
  cudaFuncSetAttribute(ctx_mma, cudaFuncAttributeMaxDynamicSharedMemorySize,
                       CT_SMEM);
  ctx_mma<<<dim3(TSEQ / 128, BATCH * NH), 256, CT_SMEM>>>(wts, ctx);
}

// round 10
// speedup vs baseline: 1.5412x; 1.0074x over previous
#include <cuda_runtime.h>
#include <cuda_bf16.h>
#include <cstdint>

#define BATCH 16
#define TSEQ 512
#define NH 16
#define DK 64
#define DM 1024
#define D3 3072
#define RR 1023  // 2T-1

// ---------------------------------------------------------------------------
// Scratch (allocation-free: device globals)
// ---------------------------------------------------------------------------
__device__ float g_Q[BATCH*NH*TSEQ*DK];
__device__ float g_V[BATCH*NH*TSEQ*DK];

// K and P stored directly as bf16 hi/lo (written by projection epilogues)
__device__ __nv_bfloat16 g_Kh[BATCH*NH*TSEQ*DK];
__device__ __nv_bfloat16 g_Kl[BATCH*NH*TSEQ*DK];
__device__ __nv_bfloat16 g_Ph[NH*RR*DK];
__device__ __nv_bfloat16 g_Pl[NH*RR*DK];

// bf16 hi/lo split operands for projection GEMMs
__device__ __nv_bfloat16 g_Ah[BATCH*TSEQ*DM];
__device__ __nv_bfloat16 g_Al[BATCH*TSEQ*DM];
__device__ __nv_bfloat16 g_Wh[D3*DM];      // qvk_w transposed: [3072][1024]
__device__ __nv_bfloat16 g_Wl[D3*DM];
__device__ __nv_bfloat16 g_pAh[1024*DM];   // pos padded to 1024 rows
__device__ __nv_bfloat16 g_pAl[1024*DM];
__device__ __nv_bfloat16 g_pWh[DM*DM];     // pos_w transposed
__device__ __nv_bfloat16 g_pWl[DM*DM];

// V^T bf16 hi/lo [bh][d][s]
__device__ __nv_bfloat16 g_Vth[(size_t)BATCH*NH*DK*TSEQ];
__device__ __nv_bfloat16 g_Vtl[(size_t)BATCH*NH*DK*TSEQ];

// ---------------------------------------------------------------------------
// helpers
// ---------------------------------------------------------------------------
__device__ __forceinline__ uint32_t smem_u32(const void* p) {
  uint32_t a;
  asm("{ .reg .u64 t; cvta.to.shared.u64 t, %1; cvt.u32.u64 %0, t; }" : "=r"(a) : "l"(p));
  return a;
}
__device__ __forceinline__ void cp16(uint32_t dst, const void* src) {
  asm volatile("cp.async.cg.shared.global [%0], [%1], 16;" :: "r"(dst), "l"(src));
}
__device__ __forceinline__ void cp16z(uint32_t dst, const void* src, int nbytes) {
  asm volatile("cp.async.cg.shared.global [%0], [%1], 16, %2;"
               :: "r"(dst), "l"(src), "r"(nbytes));
}
__device__ __forceinline__ void cp_commit() {
  asm volatile("cp.async.commit_group;" ::: "memory");
}
__device__ __forceinline__ void ldm4(uint32_t& r0, uint32_t& r1, uint32_t& r2,
                                     uint32_t& r3, uint32_t a) {
  asm volatile("ldmatrix.sync.aligned.m8n8.x4.shared.b16 {%0,%1,%2,%3}, [%4];"
               : "=r"(r0), "=r"(r1), "=r"(r2), "=r"(r3) : "r"(a));
}
__device__ __forceinline__ void mma_bf16(float* c, const uint32_t* a,
                                         uint32_t b0, uint32_t b1) {
  asm volatile(
      "mma.sync.aligned.m16n8k16.row.col.f32.bf16.bf16.f32 "
      "{%0,%1,%2,%3}, {%4,%5,%6,%7}, {%8,%9}, {%0,%1,%2,%3};"
      : "+f"(c[0]), "+f"(c[1]), "+f"(c[2]), "+f"(c[3])
      : "r"(a[0]), "r"(a[1]), "r"(a[2]), "r"(a[3]), "r"(b0), "r"(b1));
}
__device__ __forceinline__ uint32_t pack_bf2(float a, float b) {
  __nv_bfloat16 ha = __float2bfloat16(a), hb = __float2bfloat16(b);
  uint16_t ua = *(uint16_t*)&ha, ub = *(uint16_t*)&hb;
  return (uint32_t)ua | ((uint32_t)ub << 16);
}
__device__ __forceinline__ float bf_res(float v) {
  return v - __bfloat162float(__float2bfloat16(v));
}

// ---------------------------------------------------------------------------
// Merged prep: all 4 split/tsplit jobs in ONE launch.
// ---------------------------------------------------------------------------
__global__ void __launch_bounds__(256) prep_kernel(
    const float* __restrict__ x, const float* __restrict__ qvk_w,
    const float* __restrict__ pos, const float* __restrict__ pos_w) {
  __shared__ float t[32][33];
  const int bid = blockIdx.x;
  const int tid = threadIdx.x;
  if (bid < 2048) {  // split x
    const int n = BATCH * TSEQ * DM;
    for (int i = bid * 256 + tid; i < n; i += 2048 * 256) {
      float v = x[i];
      __nv_bfloat16 h = __float2bfloat16(v);
      g_Ah[i] = h;
      g_Al[i] = __float2bfloat16(v - __bfloat162float(h));
    }
  } else if (bid < 5120) {  // tsplit qvk_w: R=1024 C=3072
    const int r = bid - 2048;
    const int c0 = (r % 96) * 32, r0 = (r / 96) * 32;
    const int tx = tid & 31, ty = tid >> 5;
#pragma unroll
    for (int i = 0; i < 4; i++)
      t[ty + i * 8][tx] = qvk_w[(size_t)(r0 + ty + i * 8) * D3 + c0 + tx];
    __syncthreads();
#pragma unroll
    for (int i = 0; i < 4; i++) {
      float v = t[tx][ty + i * 8];
      __nv_bfloat16 h = __float2bfloat16(v);
      size_t o = (size_t)(c0 + ty + i * 8) * DM + r0 + tx;
      g_Wh[o] = h;
      g_Wl[o] = __float2bfloat16(v - __bfloat162float(h));
    }
  } else if (bid < 5376) {  // split pos (pad to 1024 rows)
    const int r = bid - 5120;
    const int n = RR * DM, ntot = 1024 * DM;
    for (int i = r * 256 + tid; i < ntot; i += 256 * 256) {
      float v = (i < n) ? pos[i] : 0.f;
      __nv_bfloat16 h = __float2bfloat16(v);
      g_pAh[i] = h;
      g_pAl[i] = __float2bfloat16(v - __bfloat162float(h));
    }
  } else {  // tsplit pos_w: R=1024 C=1024
    const int r = bid - 5376;
    const int c0 = (r % 32) * 32, r0 = (r / 32) * 32;
    const int tx = tid & 31, ty = tid >> 5;
#pragma unroll
    for (int i = 0; i < 4; i++)
      t[ty + i * 8][tx] = pos_w[(size_t)(r0 + ty + i * 8) * DM + c0 + tx];
    __syncthreads();
#pragma unroll
    for (int i = 0; i < 4; i++) {
      float v = t[tx][ty + i * 8];
      __nv_bfloat16 h = __float2bfloat16(v);
      size_t o = (size_t)(c0 + ty + i * 8) * DM + r0 + tx;
      g_pWh[o] = h;
      g_pWl[o] = __float2bfloat16(v - __bfloat162float(h));
    }
  }
}

// ---------------------------------------------------------------------------
// Merged projection GEMMs (QKV + pos), tile 128x256, 512 threads (16 warps).
//  bid < 768: QKV tile;  bid >= 768: pos tile.
// 3-pass bf16 split: hi*hi + hi*lo + lo*hi, fp32 accum. K-chunk 64.
// smem: per buf A hi/lo 32KB + B hi/lo 64KB = 96KB; x2 = 192KB.
// ---------------------------------------------------------------------------
#define PBUF 98304
#define OFF_AH 0
#define OFF_AL 16384
#define OFF_BH 32768
#define OFF_BL 65536
#define GSMEM (2 * PBUF)  // 196608

__global__ void __launch_bounds__(512, 1) mma_gemm_all(const float* __restrict__ bias) {
  extern __shared__ char smem[];
  const uint32_t sb = smem_u32(smem);
  const int tid = threadIdx.x;
  const int wid = tid >> 5, lane = tid & 31;
  const int bid = blockIdx.x;
  const bool qkv = bid < 768;
  int n0, m0;
  const __nv_bfloat16 *Ah, *Al, *Bh, *Bl;
  if (qkv) {
    n0 = (bid % 12) * 256; m0 = (bid / 12) * 128;
    Ah = g_Ah; Al = g_Al; Bh = g_Wh; Bl = g_Wl;
  } else {
    const int r = bid - 768;
    n0 = (r % 4) * 256; m0 = (r / 4) * 128;
    Ah = g_pAh; Al = g_pAl; Bh = g_pWh; Bl = g_pWl;
  }
  const int wm = wid & 3;   // 32 m-rows each
  const int wn = wid >> 2;  // 64 n-cols each (0..3)

  const int gr = tid >> 3;  // 0..63
  const int gc = tid & 7;
  const uint32_t gsw = (uint32_t)((gc * 16) ^ ((gr & 7) << 4));

  const int l7 = lane & 7;
  const uint32_t xa = (uint32_t)(l7 << 4);
  const int rowA0 = wm * 32 + l7 + (((lane >> 3) & 1) << 3);
  const uint32_t kadd_a = (uint32_t)(((lane >> 4) & 1) << 4);
  const int rowB0 = wn * 64 + l7 + (((lane >> 4) & 1) << 3);
  const uint32_t kadd_b = (uint32_t)(((lane >> 3) & 1) << 4);

  float acc[2][8][4];
#pragma unroll
  for (int mt = 0; mt < 2; mt++)
#pragma unroll
    for (int nt = 0; nt < 8; nt++)
#pragma unroll
      for (int i = 0; i < 4; i++) acc[mt][nt][i] = 0.f;

  auto load_chunk = [&](int kc, int buf) {
    const int k0 = kc * 64;
    const uint32_t base = sb + buf * PBUF;
    // A: 128 rows, hi+lo
#pragma unroll
    for (int it = 0; it < 2; it++) {
      const int r = gr + it * 64;
      const uint32_t sw = (uint32_t)(r * 128) + gsw;
      const size_t asrc = (size_t)(m0 + r) * DM + k0 + gc * 8;
      cp16(base + OFF_AH + sw, Ah + asrc);
      cp16(base + OFF_AL + sw, Al + asrc);
    }
    // B: 256 rows, hi+lo
#pragma unroll
    for (int it = 0; it < 4; it++) {
      const int r = gr + it * 64;
      const uint32_t sw = (uint32_t)(r * 128) + gsw;
      const size_t bsrc = (size_t)(n0 + r) * DM + k0 + gc * 8;
      cp16(base + OFF_BH + sw, Bh + bsrc);
      cp16(base + OFF_BL + sw, Bl + bsrc);
    }
    cp_commit();
  };

  load_chunk(0, 0);

  for (int kc = 0; kc < 16; kc++) {
    if (kc + 1 < 16) {
      load_chunk(kc + 1, (kc + 1) & 1);
      asm volatile("cp.async.wait_group 1;" ::: "memory");
    } else {
      asm volatile("cp.async.wait_group 0;" ::: "memory");
    }
    __syncthreads();

    const uint32_t bb = sb + (kc & 1) * PBUF;
#pragma unroll
    for (int ks = 0; ks < 4; ks++) {
      const uint32_t kba = (uint32_t)(ks * 32);
      uint32_t ah[2][4], al[2][4];
#pragma unroll
      for (int mt = 0; mt < 2; mt++) {
        const uint32_t aoff = (uint32_t)((rowA0 + mt * 16) * 128) + ((kba + kadd_a) ^ xa);
        ldm4(ah[mt][0], ah[mt][1], ah[mt][2], ah[mt][3], bb + OFF_AH + aoff);
        ldm4(al[mt][0], al[mt][1], al[mt][2], al[mt][3], bb + OFF_AL + aoff);
      }
#pragma unroll
      for (int np = 0; np < 4; np++) {
        const uint32_t boff = (uint32_t)((rowB0 + np * 16) * 128) + ((kba + kadd_b) ^ xa);
        uint32_t bh[4], bl[4];
        ldm4(bh[0], bh[1], bh[2], bh[3], bb + OFF_BH + boff);
        ldm4(bl[0], bl[1], bl[2], bl[3], bb + OFF_BL + boff);
#pragma unroll
        for (int mt = 0; mt < 2; mt++) {
          mma_bf16(acc[mt][2 * np + 0], ah[mt], bh[0], bh[1]);
          mma_bf16(acc[mt][2 * np + 1], ah[mt], bh[2], bh[3]);
          mma_bf16(acc[mt][2 * np + 0], ah[mt], bl[0], bl[1]);
          mma_bf16(acc[mt][2 * np + 1], ah[mt], bl[2], bl[3]);
          mma_bf16(acc[mt][2 * np + 0], al[mt], bh[0], bh[1]);
          mma_bf16(acc[mt][2 * np + 1], al[mt], bh[2], bh[3]);
        }
      }
    }
    __syncthreads();
  }

  const int mrow = m0 + wm * 32 + (lane >> 2);
#pragma unroll
  for (int mt = 0; mt < 2; mt++) {
#pragma unroll
    for (int half = 0; half < 2; half++) {
      const int m = mrow + mt * 16 + half * 8;
#pragma unroll
      for (int nt = 0; nt < 8; nt++) {
        const int n = n0 + wn * 64 + nt * 8 + (lane & 3) * 2;
        float2 o;
        o.x = acc[mt][nt][half * 2 + 0];
        o.y = acc[mt][nt][half * 2 + 1];
        if (qkv) {
          o.x += bias[n];
          o.y += bias[n + 1];
          const int b = m >> 9, t = m & 511;
          const int sec = n >> 10;
          const int h = (n >> 6) & 15;
          const int d = n & 63;
          const size_t idx = ((size_t)(b * NH + h) * TSEQ + t) * DK + d;
          if (sec == 0) {
            *(float2*)(g_Q + idx) = o;
          } else if (sec == 1) {
            *(uint32_t*)&g_Kh[idx] = pack_bf2(o.x, o.y);
            *(uint32_t*)&g_Kl[idx] = pack_bf2(bf_res(o.x), bf_res(o.y));
          } else {
            *(float2*)(g_V + idx) = o;
          }
        } else {
          if (m < RR) {
            const int h = n >> 6;
            const int d = n & 63;
            const size_t idx = ((size_t)h * RR + m) * DK + d;
            *(uint32_t*)&g_Ph[idx] = pack_bf2(o.x, o.y);
            *(uint32_t*)&g_Pl[idx] = pack_bf2(bf_res(o.x), bf_res(o.y));
          }
        }
      }
    }
  }
}

// ---------------------------------------------------------------------------
// Scores (+ merged vtsplit tail): grid (4, 8, 320).
//  z < 256: scores tile (t 64, s 128, bh=z)
//  z >= 256: vtsplit job; job = (z-256)*32 + y*4 + x
// ---------------------------------------------------------------------------
#define SC_QUH 0
#define SC_QUL 8192
#define SC_QVH 16384
#define SC_QVL 24576
#define SC_KH  32768
#define SC_KL  49152
#define SC_PH  65536
#define SC_PL  90112
#define SC_SMEM 114688
#define SC_BDW 196

__global__ void __launch_bounds__(256, 2) scores_mma(
    const float* __restrict__ pu, const float* __restrict__ pv,
    float* __restrict__ wout) {
  extern __shared__ char smem[];
  const uint32_t sb = smem_u32(smem);
  const int tid = threadIdx.x;

  if (blockIdx.z >= 256) {
    // ---- vtsplit job
    float (*t)[65] = (float(*)[65])smem;
    const int job = (blockIdx.z - 256) * 32 + blockIdx.y * 4 + blockIdx.x;
    const int vbh = job >> 3;
    const int vs0 = (job & 7) * 64;
    const float* vbase = g_V + (size_t)vbh * TSEQ * DK;
    for (int i = tid; i < 4096; i += 256) {
      const int sl = i >> 6, d = i & 63;
      t[sl][d] = vbase[(size_t)(vs0 + sl) * DK + d];
    }
    __syncthreads();
    for (int i = tid; i < 2048; i += 256) {
      const int d = i >> 5, sl = (i & 31) * 2;
      const float v0 = t[sl][d], v1 = t[sl + 1][d];
      const size_t o = ((size_t)vbh * DK + d) * TSEQ + vs0 + sl;
      *(uint32_t*)&g_Vth[o] = pack_bf2(v0, v1);
      *(uint32_t*)&g_Vtl[o] = pack_bf2(bf_res(v0), bf_res(v1));
    }
    return;
  }

  float* BDs = (float*)smem;  // aliased after mma phase
  const int wid = tid >> 5, lane = tid & 31;
  const int s0 = blockIdx.x * 128;
  const int t0 = blockIdx.y * 64;
  const int bh = blockIdx.z, h = bh & 15;
  const int relbase = s0 - t0 + 448;

  // ---- cp.async K tiles (128 rows x 128B, hi+lo)
  {
    const __nv_bfloat16* Kh = g_Kh + ((size_t)bh * TSEQ + s0) * DK;
    const __nv_bfloat16* Kl = g_Kl + ((size_t)bh * TSEQ + s0) * DK;
#pragma unroll
    for (int it = 0; it < 4; it++) {
      const int idx = tid + it * 256;
      const int row = idx >> 3, ch = idx & 7;
      const uint32_t sw = (uint32_t)(row * 128) + ((uint32_t)(ch * 16) ^ ((uint32_t)(row & 7) << 4));
      cp16(sb + SC_KH + sw, Kh + row * DK + ch * 8);
      cp16(sb + SC_KL + sw, Kl + row * DK + ch * 8);
    }
  }
  // ---- cp.async P band (192 rows x 128B, hi+lo), zero-fill out of range
  {
    const __nv_bfloat16* Ph = g_Ph + (size_t)h * RR * DK;
    const __nv_bfloat16* Pl = g_Pl + (size_t)h * RR * DK;
#pragma unroll
    for (int it = 0; it < 6; it++) {
      const int idx = tid + it * 256;
      const int row = idx >> 3, ch = idx & 7;
      const int r = relbase + row;
      const int rc = r < 0 ? 0 : (r >= RR ? RR - 1 : r);
      const int ok = (r >= 0 && r < RR) ? 16 : 0;
      const uint32_t sw = (uint32_t)(row * 128) + ((uint32_t)(ch * 16) ^ ((uint32_t)(row & 7) << 4));
      cp16z(sb + SC_PH + sw, Ph + (size_t)rc * DK + ch * 8, ok);
      cp16z(sb + SC_PL + sw, Pl + (size_t)rc * DK + ch * 8, ok);
    }
  }
  cp_commit();

  // ---- Q fill: fp32 + posu/posv, convert to bf16 hi/lo (overlaps cp.async)
  {
    const int frow = tid >> 4;
    const int c4 = (tid & 15) * 4;
    const uint32_t cb = (uint32_t)(c4 * 2);
    const float4 pu4 = *(const float4*)(pu + h * 64 + c4);
    const float4 pv4 = *(const float4*)(pv + h * 64 + c4);
    const float* qb = g_Q + ((size_t)bh * TSEQ + t0) * DK;
#pragma unroll
    for (int it = 0; it < 4; it++) {
      const int row = frow + it * 16;
      const float4 q = *(const float4*)(qb + (size_t)row * DK + c4);
      const uint32_t sw = (uint32_t)(row * 128) + (cb ^ ((uint32_t)(row & 7) << 4));
      float ux = q.x + pu4.x, uy = q.y + pu4.y, uz = q.z + pu4.z, uw = q.w + pu4.w;
      float vx = q.x + pv4.x, vy = q.y + pv4.y, vz = q.z + pv4.z, vw = q.w + pv4.w;
      uint2 hh, ll;
      hh.x = pack_bf2(ux, uy); hh.y = pack_bf2(uz, uw);
      ll.x = pack_bf2(bf_res(ux), bf_res(uy));
      ll.y = pack_bf2(bf_res(uz), bf_res(uw));
      *(uint2*)(smem + SC_QUH + sw) = hh;
      *(uint2*)(smem + SC_QUL + sw) = ll;
      hh.x = pack_bf2(vx, vy); hh.y = pack_bf2(vz, vw);
      ll.x = pack_bf2(bf_res(vx), bf_res(vy));
      ll.y = pack_bf2(bf_res(vz), bf_res(vw));
      *(uint2*)(smem + SC_QVH + sw) = hh;
      *(uint2*)(smem + SC_QVL + sw) = ll;
    }
  }
  asm volatile("cp.async.wait_group 0;" ::: "memory");
  __syncthreads();

  // ---- mma: 8 warps = 4 (t) x 2 (s/band)
  const int wm = wid & 3;   // 16 t-rows
  const int wn = wid >> 2;  // AC: 64 s-cols, BD: 96 band-cols
  const int l7 = lane & 7;
  const uint32_t xa = (uint32_t)(l7 << 4);
  const int rowA = wm * 16 + l7 + (((lane >> 3) & 1) << 3);
  const uint32_t kadd_a = (uint32_t)(((lane >> 4) & 1) << 4);
  const int rbB = l7 + (((lane >> 4) & 1) << 3);
  const uint32_t kadd_b = (uint32_t)(((lane >> 3) & 1) << 4);

  float ac[8][4], bd[12][4];
#pragma unroll
  for (int nt = 0; nt < 8; nt++)
#pragma unroll
    for (int i = 0; i < 4; i++) ac[nt][i] = 0.f;
#pragma unroll
  for (int nt = 0; nt < 12; nt++)
#pragma unroll
    for (int i = 0; i < 4; i++) bd[nt][i] = 0.f;

#pragma unroll
  for (int ks = 0; ks < 4; ks++) {
    const uint32_t kba = (uint32_t)(ks * 32);
    const uint32_t aoff = (uint32_t)(rowA * 128) + ((kba + kadd_a) ^ xa);
    uint32_t quh[4], qul[4], qvh[4], qvl[4];
    ldm4(quh[0], quh[1], quh[2], quh[3], sb + SC_QUH + aoff);
    ldm4(qul[0], qul[1], qul[2], qul[3], sb + SC_QUL + aoff);
    ldm4(qvh[0], qvh[1], qvh[2], qvh[3], sb + SC_QVH + aoff);
    ldm4(qvl[0], qvl[1], qvl[2], qvl[3], sb + SC_QVL + aoff);
#pragma unroll
    for (int np = 0; np < 4; np++) {
      const int rowB = wn * 64 + np * 16 + rbB;
      const uint32_t boff = (uint32_t)(rowB * 128) + ((kba + kadd_b) ^ xa);
      uint32_t kh[4], kl[4];
      ldm4(kh[0], kh[1], kh[2], kh[3], sb + SC_KH + boff);
      ldm4(kl[0], kl[1], kl[2], kl[3], sb + SC_KL + boff);
      mma_bf16(ac[2 * np + 0], quh, kh[0], kh[1]);
      mma_bf16(ac[2 * np + 1], quh, kh[2], kh[3]);
      mma_bf16(ac[2 * np + 0], quh, kl[0], kl[1]);
      mma_bf16(ac[2 * np + 1], quh, kl[2], kl[3]);
      mma_bf16(ac[2 * np + 0], qul, kh[0], kh[1]);
      mma_bf16(ac[2 * np + 1], qul, kh[2], kh[3]);
    }
#pragma unroll
    for (int np = 0; np < 6; np++) {
      const int rowB = wn * 96 + np * 16 + rbB;
      const uint32_t boff = (uint32_t)(rowB * 128) + ((kba + kadd_b) ^ xa);
      uint32_t ph[4], pl[4];
      ldm4(ph[0], ph[1], ph[2], ph[3], sb + SC_PH + boff);
      ldm4(pl[0], pl[1], pl[2], pl[3], sb + SC_PL + boff);
      mma_bf16(bd[2 * np + 0], qvh, ph[0], ph[1]);
      mma_bf16(bd[2 * np + 1], qvh, ph[2], ph[3]);
      mma_bf16(bd[2 * np + 0], qvh, pl[0], pl[1]);
      mma_bf16(bd[2 * np + 1], qvh, pl[2], pl[3]);
      mma_bf16(bd[2 * np + 0], qvl, ph[0], ph[1]);
      mma_bf16(bd[2 * np + 1], qvl, ph[2], ph[3]);
    }
  }
  __syncthreads();  // operand smem dead; safe to alias with BDs

  // ---- BD -> smem (stride 196 floats)
  const int r0w = wm * 16 + (lane >> 2);
#pragma unroll
  for (int nt = 0; nt < 12; nt++) {
    const int col = wn * 96 + nt * 8 + (lane & 3) * 2;
    *(float2*)&BDs[r0w * SC_BDW + col] = make_float2(bd[nt][0], bd[nt][1]);
    *(float2*)&BDs[(r0w + 8) * SC_BDW + col] = make_float2(bd[nt][2], bd[nt][3]);
  }
  __syncthreads();

  // ---- epilogue: out = (AC + shifted BD) / 8
  float* wbase = wout + ((size_t)bh * TSEQ + t0) * TSEQ + s0;
#pragma unroll
  for (int nt = 0; nt < 8; nt++) {
    const int col = wn * 64 + nt * 8 + (lane & 3) * 2;
#pragma unroll
    for (int half = 0; half < 2; half++) {
      const int row = r0w + half * 8;
      const int bdi = row * SC_BDW + col - row + 63;
      float2 o;
      o.x = (ac[nt][half * 2 + 0] + BDs[bdi]) * 0.125f;
      o.y = (ac[nt][half * 2 + 1] + BDs[bdi + 1]) * 0.125f;
      *(float2*)(wbase + (size_t)row * TSEQ + col) = o;
    }
  }
}

// ---------------------------------------------------------------------------
// Softmax over rows of 512, in place (f32 only). One warp per row.
// ---------------------------------------------------------------------------
__global__ void __launch_bounds__(256) softmax_kernel(float* __restrict__ w) {
  const int gwarp = (blockIdx.x * 256 + threadIdx.x) >> 5;
  const int lane = threadIdx.x & 31;
  float* row = w + (size_t)gwarp * TSEQ;
  float4 v[4];
#pragma unroll
  for (int k = 0; k < 4; k++) v[k] = *(float4*)(row + k * 128 + lane * 4);
  float m = v[0].x;
#pragma unroll
  for (int k = 0; k < 4; k++)
    m = fmaxf(m, fmaxf(fmaxf(v[k].x, v[k].y), fmaxf(v[k].z, v[k].w)));
#pragma unroll
  for (int off = 16; off > 0; off >>= 1)
    m = fmaxf(m, __shfl_xor_sync(0xffffffffu, m, off));
  float s = 0.f;
#pragma unroll
  for (int k = 0; k < 4; k++) {
    v[k].x = __expf(v[k].x - m); s += v[k].x;
    v[k].y = __expf(v[k].y - m); s += v[k].y;
    v[k].z = __expf(v[k].z - m); s += v[k].z;
    v[k].w = __expf(v[k].w - m); s += v[k].w;
  }
#pragma unroll
  for (int off = 16; off > 0; off >>= 1)
    s += __shfl_xor_sync(0xffffffffu, s, off);
  const float inv = 1.0f / s;
#pragma unroll
  for (int k = 0; k < 4; k++) {
    v[k].x *= inv; v[k].y *= inv; v[k].z *= inv; v[k].w *= inv;
    *(float4*)(row + k * 128 + lane * 4) = v[k];
  }
}

// ---------------------------------------------------------------------------
// Context GEMM: ctx[b,t,h*64+d] = sum_s W[bh,t,s] * Vt[bh,d,s]
// W read as f32 and converted in-kernel to bf16 hi/lo.
// ---------------------------------------------------------------------------
#define CT_WF 0        // 128 x 64 f32 staging (linear, 256B rows), 32KB
#define CT_WH 32768    // converted W hi (swizzled), 16KB
#define CT_WL 49152    // converted W lo, 16KB
#define CT_V  65536    // V buffers: +buf*16384; hi at +0 (8KB), lo at +8192
#define CT_SMEM 98304

__global__ void __launch_bounds__(256, 2) ctx_mma(
    const float* __restrict__ wts, float* __restrict__ ctx) {
  extern __shared__ char smem[];
  const uint32_t sb = smem_u32(smem);
  const int tid = threadIdx.x;
  const int wid = tid >> 5, lane = tid & 31;
  const int t0 = blockIdx.x * 128;
  const int bh = blockIdx.y;
  const int b = bh >> 4, h = bh & 15;

  const float* Wf = wts + ((size_t)bh * TSEQ + t0) * TSEQ;
  const __nv_bfloat16* Vh = g_Vth + (size_t)bh * DK * TSEQ;
  const __nv_bfloat16* Vl = g_Vtl + (size_t)bh * DK * TSEQ;

  const int wm = wid & 3;
  const int wn = wid >> 2;
  const int l7 = lane & 7;
  const uint32_t xa = (uint32_t)(l7 << 4);
  const int rowA0 = wm * 32 + l7 + (((lane >> 3) & 1) << 3);
  const uint32_t kadd_a = (uint32_t)(((lane >> 4) & 1) << 4);
  const int rowB0 = wn * 32 + l7 + (((lane >> 4) & 1) << 3);
  const uint32_t kadd_b = (uint32_t)(((lane >> 3) & 1) << 4);

  float acc[2][4][4];
#pragma unroll
  for (int mt = 0; mt < 2; mt++)
#pragma unroll
    for (int nt = 0; nt < 4; nt++)
#pragma unroll
      for (int i = 0; i < 4; i++) acc[mt][nt][i] = 0.f;

  auto load_wf = [&](int kc) {
    const int k0 = kc * 64;
#pragma unroll
    for (int it = 0; it < 8; it++) {
      const int idx = tid + it * 256;
      const int row = idx >> 4, seg = idx & 15;
      cp16(sb + CT_WF + (uint32_t)(row * 256 + seg * 16),
           Wf + (size_t)row * TSEQ + k0 + seg * 4);
    }
  };
  auto load_v = [&](int kc, int buf) {
    const int k0 = kc * 64;
    const uint32_t vb = sb + CT_V + (uint32_t)(buf * 16384);
#pragma unroll
    for (int it = 0; it < 2; it++) {
      const int idx = tid + it * 256;
      const int row = idx >> 3, ch = idx & 7;
      const uint32_t sw = (uint32_t)(row * 128) + ((uint32_t)(ch * 16) ^ ((uint32_t)(row & 7) << 4));
      cp16(vb + sw, Vh + (size_t)row * TSEQ + k0 + ch * 8);
      cp16(vb + 8192 + sw, Vl + (size_t)row * TSEQ + k0 + ch * 8);
    }
  };

  load_wf(0);
  load_v(0, 0);
  cp_commit();

  for (int kc = 0; kc < 8; kc++) {
    asm volatile("cp.async.wait_group 0;" ::: "memory");
    __syncthreads();

#pragma unroll
    for (int it = 0; it < 8; it++) {
      const int idx = tid + it * 256;
      const int r = idx >> 4, q = idx & 15;
      const float4 wv = *(const float4*)(smem + CT_WF + r * 256 + q * 16);
      const uint32_t sw = (uint32_t)(r * 128) + ((uint32_t)(q * 8) ^ ((uint32_t)(r & 7) << 4));
      uint2 hh, ll;
      hh.x = pack_bf2(wv.x, wv.y); hh.y = pack_bf2(wv.z, wv.w);
      ll.x = pack_bf2(bf_res(wv.x), bf_res(wv.y));
      ll.y = pack_bf2(bf_res(wv.z), bf_res(wv.w));
      *(uint2*)(smem + CT_WH + sw) = hh;
      *(uint2*)(smem + CT_WL + sw) = ll;
    }
    __syncthreads();

    if (kc + 1 < 8) {
      load_wf(kc + 1);
      load_v(kc + 1, (kc + 1) & 1);
      cp_commit();
    }

    const uint32_t vb = sb + CT_V + (uint32_t)((kc & 1) * 16384);
#pragma unroll
    for (int ks = 0; ks < 4; ks++) {
      const uint32_t kba = (uint32_t)(ks * 32);
      uint32_t ah[2][4], al[2][4];
#pragma unroll
      for (int mt = 0; mt < 2; mt++) {
        const uint32_t aoff = (uint32_t)((rowA0 + mt * 16) * 128) + ((kba + kadd_a) ^ xa);
        ldm4(ah[mt][0], ah[mt][1], ah[mt][2], ah[mt][3], sb + CT_WH + aoff);
        ldm4(al[mt][0], al[mt][1], al[mt][2], al[mt][3], sb + CT_WL + aoff);
      }
#pragma unroll
      for (int np = 0; np < 2; np++) {
        const uint32_t boff = (uint32_t)((rowB0 + np * 16) * 128) + ((kba + kadd_b) ^ xa);
        uint32_t vhh[4], vll[4];
        ldm4(vhh[0], vhh[1], vhh[2], vhh[3], vb + boff);
        ldm4(vll[0], vll[1], vll[2], vll[3], vb + 8192 + boff);
#pragma unroll
        for (int mt = 0; mt < 2; mt++) {
          mma_bf16(acc[mt][2 * np + 0], ah[mt], vhh[0], vhh[1]);
          mma_bf16(acc[mt][2 * np + 1], ah[mt], vhh[2], vhh[3]);
          mma_bf16(acc[mt][2 * np + 0], ah[mt], vll[0], vll[1]);
          mma_bf16(acc[mt][2 * np + 1], ah[mt], vll[2], vll[3]);
          mma_bf16(acc[mt][2 * np + 0], al[mt], vhh[0], vhh[1]);
          mma_bf16(acc[mt][2 * np + 1], al[mt], vhh[2], vhh[3]);
        }
      }
    }
  }

  const int mrow = t0 + wm * 32 + (lane >> 2);
#pragma unroll
  for (int mt = 0; mt < 2; mt++) {
#pragma unroll
    for (int half = 0; half < 2; half++) {
      const int t = mrow + mt * 16 + half * 8;
#pragma unroll
      for (int nt = 0; nt < 4; nt++) {
        const int d = wn * 32 + nt * 8 + (lane & 3) * 2;
        float2 o;
        o.x = acc[mt][nt][half * 2 + 0];
        o.y = acc[mt][nt][half * 2 + 1];
        *(float2*)(ctx + ((size_t)b * TSEQ + t) * DM + h * DK + d) = o;
      }
    }
  }
}

// ---------------------------------------------------------------------------
// Launch
// ---------------------------------------------------------------------------
extern "C" void kernel_launch(void* const* d_in, const int* in_sizes, int n_in,
                              void* d_out, int out_size) {
  const float* x     = (const float*)d_in[0];
  const float* pos   = (const float*)d_in[2];
  const float* qvk_w = (const float*)d_in[3];
  const float* qvk_b = (const float*)d_in[4];
  const float* pos_w = (const float*)d_in[5];
  const float* posu  = (const float*)d_in[6];
  const float* posv  = (const float*)d_in[7];

  float* ctx = (float*)d_out;
  float* wts = (float*)d_out + (size_t)BATCH * TSEQ * DM;

  // 0) merged prep (all bf16 hi/lo splits)
  prep_kernel<<<6400, 256>>>(x, qvk_w, pos, pos_w);

  // 1) merged projection GEMMs, tile 128x256 (QKV 768 + pos 32 tiles)
  cudaFuncSetAttribute(mma_gemm_all, cudaFuncAttributeMaxDynamicSharedMemorySize,
                       GSMEM);
  mma_gemm_all<<<800, 512, GSMEM>>>(qvk_b);

  // 2) scores (+ merged vtsplit tail) -> weights region
  cudaFuncSetAttribute(scores_mma, cudaFuncAttributeMaxDynamicSharedMemorySize,
                       SC_SMEM);
  scores_mma<<<dim3(4, 8, 320), 256, SC_SMEM>>>(posu, posv, wts);

  // 3) softmax in place (f32 only)
  softmax_kernel<<<(BATCH * NH * TSEQ) / 8, 256>>>(wts);

  // 4) context = W @ V (W f32 converted in-kernel)
  cudaFuncSetAttribute(ctx_mma, cudaFuncAttributeMaxDynamicSharedMemorySize,
                       CT_SMEM);
  ctx_mma<<<dim3(TSEQ / 128, BATCH * NH), 256, CT_SMEM>>>(wts, ctx);
}